// round 2
// baseline (speedup 1.0000x reference)
#include <cuda_runtime.h>

#define CC 512
#define NP 4096
#define KK 64
#define BB 16
#define NSPLIT 8
#define EPSF 1e-6f

typedef unsigned long long u64;

// ---------------- scratch (static device globals; no allocation) ----------
__device__ float g_xf[(size_t)BB * CC * NP];      // conv1 output (b,c,n)
__device__ float g_rec[(size_t)BB * CC * NP];     // reconstruction
__device__ float g_z[(size_t)BB * NP * KK];       // softmax z (b,n,k)
__device__ float g_mpart[(size_t)NSPLIT * BB * CC * KK]; // split-K partials
__device__ float g_m[(size_t)BB * CC * KK];       // m (b,c,k)
__device__ float g_norm2[(size_t)8 * BB * KK];    // per-cslice partial norms

// ---------------- f32x2 helpers -------------------------------------------
__device__ __forceinline__ u64 pack2(float x) {
    u64 r;
    asm("mov.b64 %0, {%1, %2};" : "=l"(r) : "f"(x), "f"(x));
    return r;
}
__device__ __forceinline__ void fma2(u64 &d, u64 a, u64 b) {
    asm("fma.rn.f32x2 %0, %1, %2, %0;" : "+l"(d) : "l"(a), "l"(b));
}
__device__ __forceinline__ float2 unpk(u64 v) {
    float2 f;
    asm("mov.b64 {%0, %1}, %2;" : "=f"(f.x), "=f"(f.y) : "l"(v));
    return f;
}

// ---------------- conv GEMM: OUT[b,o,p] = sum_c W[o,c] * IN[b,c,p] + epi ---
// EPI=0: bias epilogue, IN = x param, OUT = g_xf
// EPI=1: BN epilogue,   IN = g_rec,  OUT = out param
template <int EPI>
__global__ __launch_bounds__(256, 2)
void gemm_conv(const float* __restrict__ W, const float* __restrict__ XIN,
               float* __restrict__ XOUT,
               const float* __restrict__ e0, const float* __restrict__ e1,
               const float* __restrict__ e2, const float* __restrict__ e3)
{
    __shared__ float As[16][132]; // [cc][o]  (W^T chunk)
    __shared__ float Bs[16][128]; // [cc][p]

    const int b  = blockIdx.z;
    const int o0 = blockIdx.y * 128;
    const int pp0 = blockIdx.x * 128;
    const float* IN  = (EPI == 0) ? XIN : g_rec;
    float*       OUT = (EPI == 0) ? g_xf : XOUT;
    const float* inb  = IN  + (size_t)b * CC * NP;
    float*       outb = OUT + (size_t)b * CC * NP;

    const int tid = threadIdx.x;
    const int tx = tid & 15, ty = tid >> 4;
    const int ro = ty * 8, rp = tx * 8;

    u64 acc[8][4];
#pragma unroll
    for (int i = 0; i < 8; i++)
#pragma unroll
        for (int j = 0; j < 4; j++) acc[i][j] = 0ULL;

    for (int c0 = 0; c0 < CC; c0 += 16) {
#pragma unroll
        for (int l = 0; l < 2; l++) {          // W tile (128 o x 16 c) -> As^T
            int f = tid + l * 256;
            int row = f >> 2, c4 = (f & 3) * 4;
            float4 v = *(const float4*)&W[(size_t)(o0 + row) * CC + c0 + c4];
            As[c4 + 0][row] = v.x; As[c4 + 1][row] = v.y;
            As[c4 + 2][row] = v.z; As[c4 + 3][row] = v.w;
        }
#pragma unroll
        for (int l = 0; l < 2; l++) {          // IN tile (16 c x 128 p) -> Bs
            int f = tid + l * 256;
            int cc = f >> 5, p4 = (f & 31) * 4;
            *(float4*)&Bs[cc][p4] =
                *(const float4*)&inb[(size_t)(c0 + cc) * NP + pp0 + p4];
        }
        __syncthreads();
#pragma unroll
        for (int cc = 0; cc < 16; cc++) {
            float4 a0 = *(const float4*)&As[cc][ro];
            float4 a1 = *(const float4*)&As[cc][ro + 4];
            u64 ap[8];
            ap[0] = pack2(a0.x); ap[1] = pack2(a0.y);
            ap[2] = pack2(a0.z); ap[3] = pack2(a0.w);
            ap[4] = pack2(a1.x); ap[5] = pack2(a1.y);
            ap[6] = pack2(a1.z); ap[7] = pack2(a1.w);
            const u64* bp = (const u64*)&Bs[cc][rp];
            u64 b0 = bp[0], b1 = bp[1], b2 = bp[2], b3 = bp[3];
#pragma unroll
            for (int i = 0; i < 8; i++) {
                fma2(acc[i][0], ap[i], b0);
                fma2(acc[i][1], ap[i], b1);
                fma2(acc[i][2], ap[i], b2);
                fma2(acc[i][3], ap[i], b3);
            }
        }
        __syncthreads();
    }

#pragma unroll
    for (int i = 0; i < 8; i++) {
        int o = o0 + ro + i;
        float4 r0, r1;
        float2 t;
        if (EPI == 0) {
            float add = e0[o];
            t = unpk(acc[i][0]); r0.x = t.x + add; r0.y = t.y + add;
            t = unpk(acc[i][1]); r0.z = t.x + add; r0.w = t.y + add;
            t = unpk(acc[i][2]); r1.x = t.x + add; r1.y = t.y + add;
            t = unpk(acc[i][3]); r1.z = t.x + add; r1.w = t.y + add;
        } else {
            float inv = e0[o] * rsqrtf(e3[o] + 1e-5f);
            float add = e1[o] - e2[o] * inv;
            t = unpk(acc[i][0]); r0.x = t.x * inv + add; r0.y = t.y * inv + add;
            t = unpk(acc[i][1]); r0.z = t.x * inv + add; r0.w = t.y * inv + add;
            t = unpk(acc[i][2]); r1.x = t.x * inv + add; r1.y = t.y * inv + add;
            t = unpk(acc[i][3]); r1.z = t.x * inv + add; r1.w = t.y * inv + add;
        }
        *(float4*)&outb[(size_t)o * NP + pp0 + rp]     = r0;
        *(float4*)&outb[(size_t)o * NP + pp0 + rp + 4] = r1;
    }
}

// ---------------- z kernel: z = softmax_k( xf^T @ m ) ---------------------
__global__ __launch_bounds__(256, 2)
void kz_kernel(const float* __restrict__ MU, int use_gm)
{
    __shared__ float Xs[16][128]; // [cc][p]
    __shared__ float Ms[16][64];  // [cc][k]

    const int b  = blockIdx.y;
    const int p0 = blockIdx.x * 128;
    const float* xf = g_xf + (size_t)b * CC * NP;
    const float* mi = use_gm ? (g_m + (size_t)b * CC * KK) : MU;

    const int tid = threadIdx.x;
    const int tx = tid & 15, ty = tid >> 4;
    const int rp = ty * 8, rk = tx * 4;

    u64 acc[8][2];
#pragma unroll
    for (int i = 0; i < 8; i++) { acc[i][0] = 0ULL; acc[i][1] = 0ULL; }

    for (int c0 = 0; c0 < CC; c0 += 16) {
#pragma unroll
        for (int l = 0; l < 2; l++) {          // xf tile (16 c x 128 p)
            int f = tid + l * 256;
            int cc = f >> 5, p4 = (f & 31) * 4;
            *(float4*)&Xs[cc][p4] =
                *(const float4*)&xf[(size_t)(c0 + cc) * NP + p0 + p4];
        }
        {                                       // m tile (16 c x 64 k)
            int cc = tid >> 4, k4 = (tid & 15) * 4;
            *(float4*)&Ms[cc][k4] =
                *(const float4*)&mi[(size_t)(c0 + cc) * KK + k4];
        }
        __syncthreads();
#pragma unroll
        for (int cc = 0; cc < 16; cc++) {
            float4 a0 = *(const float4*)&Xs[cc][rp];
            float4 a1 = *(const float4*)&Xs[cc][rp + 4];
            u64 ap[8];
            ap[0] = pack2(a0.x); ap[1] = pack2(a0.y);
            ap[2] = pack2(a0.z); ap[3] = pack2(a0.w);
            ap[4] = pack2(a1.x); ap[5] = pack2(a1.y);
            ap[6] = pack2(a1.z); ap[7] = pack2(a1.w);
            const u64* bp = (const u64*)&Ms[cc][rk];
            u64 b0 = bp[0], b1 = bp[1];
#pragma unroll
            for (int i = 0; i < 8; i++) {
                fma2(acc[i][0], ap[i], b0);
                fma2(acc[i][1], ap[i], b1);
            }
        }
        __syncthreads();
    }

    // softmax over k=64: 16 threads (same ty) each hold 4 k-values per row
    float* zb = g_z + ((size_t)b * NP + p0) * KK;
#pragma unroll
    for (int i = 0; i < 8; i++) {
        float2 v01 = unpk(acc[i][0]);
        float2 v23 = unpk(acc[i][1]);
        float mx = fmaxf(fmaxf(v01.x, v01.y), fmaxf(v23.x, v23.y));
#pragma unroll
        for (int s = 1; s < 16; s <<= 1)
            mx = fmaxf(mx, __shfl_xor_sync(0xffffffffu, mx, s));
        float e0 = expf(v01.x - mx), e1 = expf(v01.y - mx);
        float e2 = expf(v23.x - mx), e3 = expf(v23.y - mx);
        float sm = e0 + e1 + e2 + e3;
#pragma unroll
        for (int s = 1; s < 16; s <<= 1)
            sm += __shfl_xor_sync(0xffffffffu, sm, s);
        float inv = 1.f / sm;
        float4 w;
        w.x = e0 * inv; w.y = e1 * inv; w.z = e2 * inv; w.w = e3 * inv;
        *(float4*)&zb[(size_t)(rp + i) * KK + rk] = w;
    }
}

// ---------------- m update (split-K over pixels): mpart = xf @ z ----------
__global__ __launch_bounds__(256, 2)
void km_kernel()
{
    __shared__ float Xs[16][132]; // [pp][c]
    __shared__ float Zs[16][64];  // [pp][k]

    const int ct0 = blockIdx.x * 128;
    const int b   = blockIdx.y;
    const int s   = blockIdx.z;
    const int ps0 = s * (NP / NSPLIT);
    const float* xf = g_xf + (size_t)b * CC * NP;
    const float* zz = g_z + (size_t)b * NP * KK;

    const int tid = threadIdx.x;
    const int tx = tid & 15, ty = tid >> 4;
    const int rc = ty * 8, rk = tx * 4;

    u64 acc[8][2];
#pragma unroll
    for (int i = 0; i < 8; i++) { acc[i][0] = 0ULL; acc[i][1] = 0ULL; }

    for (int p0 = ps0; p0 < ps0 + (NP / NSPLIT); p0 += 16) {
#pragma unroll
        for (int l = 0; l < 2; l++) {         // xf tile (128 c x 16 p) -> Xs^T
            int f = tid + l * 256;
            int row = f >> 2, p4 = (f & 3) * 4;
            float4 v = *(const float4*)&xf[(size_t)(ct0 + row) * NP + p0 + p4];
            Xs[p4 + 0][row] = v.x; Xs[p4 + 1][row] = v.y;
            Xs[p4 + 2][row] = v.z; Xs[p4 + 3][row] = v.w;
        }
        {                                      // z tile (16 p x 64 k)
            int pp = tid >> 4, k4 = (tid & 15) * 4;
            *(float4*)&Zs[pp][k4] =
                *(const float4*)&zz[(size_t)(p0 + pp) * KK + k4];
        }
        __syncthreads();
#pragma unroll
        for (int pp = 0; pp < 16; pp++) {
            float4 a0 = *(const float4*)&Xs[pp][rc];
            float4 a1 = *(const float4*)&Xs[pp][rc + 4];
            u64 ap[8];
            ap[0] = pack2(a0.x); ap[1] = pack2(a0.y);
            ap[2] = pack2(a0.z); ap[3] = pack2(a0.w);
            ap[4] = pack2(a1.x); ap[5] = pack2(a1.y);
            ap[6] = pack2(a1.z); ap[7] = pack2(a1.w);
            const u64* bp = (const u64*)&Zs[pp][rk];
            u64 b0 = bp[0], b1 = bp[1];
#pragma unroll
            for (int i = 0; i < 8; i++) {
                fma2(acc[i][0], ap[i], b0);
                fma2(acc[i][1], ap[i], b1);
            }
        }
        __syncthreads();
    }

    float* out = g_mpart + ((size_t)(s * BB + b) * CC + ct0) * KK;
#pragma unroll
    for (int i = 0; i < 8; i++) {
        u64* op = (u64*)&out[(size_t)(rc + i) * KK + rk];
        op[0] = acc[i][0];
        op[1] = acc[i][1];
    }
}

// ---------------- norm phase 1: reduce splits, partial sum of squares -----
__global__ void knorm1()
{
    const int cs = blockIdx.x, b = blockIdx.y;
    __shared__ float red[256];
    const int tid = threadIdx.x;
    const size_t bc = ((size_t)b * CC + cs * 64) * KK;
    float ln = 0.f;
#pragma unroll
    for (int it = 0; it < 16; it++) {
        size_t off = bc + tid + it * 256;
        float v = 0.f;
#pragma unroll
        for (int s = 0; s < NSPLIT; s++)
            v += g_mpart[(size_t)s * (BB * CC * KK) + off];
        g_m[off] = v;
        ln += v * v;
    }
    red[tid] = ln;
    __syncthreads();
    if (tid < 64)
        g_norm2[(size_t)(cs * BB + b) * KK + tid] =
            red[tid] + red[tid + 64] + red[tid + 128] + red[tid + 192];
}

// ---------------- norm phase 2: scale by 1/(eps + ||.||) -------------------
__global__ void knorm2()
{
    const int cs = blockIdx.x, b = blockIdx.y;
    __shared__ float inv[64];
    const int tid = threadIdx.x;
    if (tid < 64) {
        float s = 0.f;
#pragma unroll
        for (int q = 0; q < 8; q++)
            s += g_norm2[(size_t)(q * BB + b) * KK + tid];
        inv[tid] = 1.f / (EPSF + sqrtf(s));
    }
    __syncthreads();
    const size_t bc = ((size_t)b * CC + cs * 64) * KK;
#pragma unroll
    for (int it = 0; it < 16; it++) {
        size_t off = bc + tid + it * 256;
        g_m[off] *= inv[tid & 63];
    }
}

// ---------------- rec = relu( m @ z^T ) ------------------------------------
__global__ __launch_bounds__(256, 2)
void krec_kernel()
{
    __shared__ float As[16][132]; // [kk][c]
    __shared__ float Bs[16][128]; // [kk][p]

    const int p0  = blockIdx.x * 128;
    const int ct0 = blockIdx.y * 128;
    const int b   = blockIdx.z;
    const float* mm = g_m + (size_t)b * CC * KK;
    const float* zz = g_z + (size_t)b * NP * KK;

    const int tid = threadIdx.x;
    const int tx = tid & 15, ty = tid >> 4;
    const int rc = ty * 8, rp = tx * 8;

    u64 acc[8][4];
#pragma unroll
    for (int i = 0; i < 8; i++)
#pragma unroll
        for (int j = 0; j < 4; j++) acc[i][j] = 0ULL;

    for (int k0 = 0; k0 < KK; k0 += 16) {
#pragma unroll
        for (int l = 0; l < 2; l++) {          // m tile (128 c x 16 k) -> As^T
            int f = tid + l * 256;
            int row = f >> 2, k4 = (f & 3) * 4;
            float4 v = *(const float4*)&mm[(size_t)(ct0 + row) * KK + k0 + k4];
            As[k4 + 0][row] = v.x; As[k4 + 1][row] = v.y;
            As[k4 + 2][row] = v.z; As[k4 + 3][row] = v.w;
        }
#pragma unroll
        for (int l = 0; l < 2; l++) {          // z tile (128 p x 16 k) -> Bs^T
            int f = tid + l * 256;
            int row = f >> 2, k4 = (f & 3) * 4;
            float4 v = *(const float4*)&zz[(size_t)(p0 + row) * KK + k0 + k4];
            Bs[k4 + 0][row] = v.x; Bs[k4 + 1][row] = v.y;
            Bs[k4 + 2][row] = v.z; Bs[k4 + 3][row] = v.w;
        }
        __syncthreads();
#pragma unroll
        for (int kk = 0; kk < 16; kk++) {
            float4 a0 = *(const float4*)&As[kk][rc];
            float4 a1 = *(const float4*)&As[kk][rc + 4];
            u64 ap[8];
            ap[0] = pack2(a0.x); ap[1] = pack2(a0.y);
            ap[2] = pack2(a0.z); ap[3] = pack2(a0.w);
            ap[4] = pack2(a1.x); ap[5] = pack2(a1.y);
            ap[6] = pack2(a1.z); ap[7] = pack2(a1.w);
            const u64* bp = (const u64*)&Bs[kk][rp];
            u64 b0 = bp[0], b1 = bp[1], b2 = bp[2], b3 = bp[3];
#pragma unroll
            for (int i = 0; i < 8; i++) {
                fma2(acc[i][0], ap[i], b0);
                fma2(acc[i][1], ap[i], b1);
                fma2(acc[i][2], ap[i], b2);
                fma2(acc[i][3], ap[i], b3);
            }
        }
        __syncthreads();
    }

    float* out = g_rec + ((size_t)b * CC + ct0) * NP + p0;
#pragma unroll
    for (int i = 0; i < 8; i++) {
        float2 t;
        float4 r0, r1;
        t = unpk(acc[i][0]); r0.x = fmaxf(t.x, 0.f); r0.y = fmaxf(t.y, 0.f);
        t = unpk(acc[i][1]); r0.z = fmaxf(t.x, 0.f); r0.w = fmaxf(t.y, 0.f);
        t = unpk(acc[i][2]); r1.x = fmaxf(t.x, 0.f); r1.y = fmaxf(t.y, 0.f);
        t = unpk(acc[i][3]); r1.z = fmaxf(t.x, 0.f); r1.w = fmaxf(t.y, 0.f);
        *(float4*)&out[(size_t)(rc + i) * NP + rp]     = r0;
        *(float4*)&out[(size_t)(rc + i) * NP + rp + 4] = r1;
    }
}

// ---------------- launch ----------------------------------------------------
extern "C" void kernel_launch(void* const* d_in, const int* in_sizes, int n_in,
                              void* d_out, int out_size)
{
    (void)in_sizes; (void)n_in; (void)out_size;
    const float* x     = (const float*)d_in[0];
    const float* w1    = (const float*)d_in[1];
    const float* b1    = (const float*)d_in[2];
    const float* mu    = (const float*)d_in[3];
    const float* w2    = (const float*)d_in[4];
    const float* gamma = (const float*)d_in[5];
    const float* beta  = (const float*)d_in[6];
    const float* mean  = (const float*)d_in[7];
    const float* var   = (const float*)d_in[8];
    float* out = (float*)d_out;

    dim3 gc(NP / 128, CC / 128, BB);
    gemm_conv<0><<<gc, 256>>>(w1, x, nullptr, b1, nullptr, nullptr, nullptr);

    for (int st = 0; st < 3; st++) {
        kz_kernel<<<dim3(NP / 128, BB), 256>>>(mu, st > 0 ? 1 : 0);
        km_kernel<<<dim3(CC / 128, BB, NSPLIT), 256>>>();
        knorm1<<<dim3(8, BB), 256>>>();
        knorm2<<<dim3(8, BB), 256>>>();
    }

    krec_kernel<<<dim3(NP / 128, CC / 128, BB), 256>>>();
    gemm_conv<1><<<gc, 256>>>(w2, nullptr, out, gamma, beta, mean, var);
}

// round 4
// speedup vs baseline: 1.3977x; 1.3977x over previous
#include <cuda_runtime.h>
#include <cuda_bf16.h>

#define CC 512
#define NP 4096
#define KK 64
#define BB 16
#define NSPLIT 8
#define EPSF 1e-6f
#define TK 1536          // extended K for bf16-split GEMM
#define NCHUNK 24        // 1536 / 64

typedef unsigned long long u64;
typedef unsigned int u32;
typedef unsigned short u16;

// ---------------- scratch (static device globals; no allocation) ----------
__device__ float g_xf[(size_t)BB * CC * NP];        // conv1 out fp32 (b,c,p)
__device__ float g_z[(size_t)BB * NP * KK];         // softmax z (b,n,k)
__device__ float g_mpart[(size_t)NSPLIT * BB * CC * KK];
__device__ float g_m[(size_t)BB * CC * KK];
__device__ float g_norm2[(size_t)8 * BB * KK];
__device__ u16 g_w1ext[(size_t)CC * TK];            // W1 split-ext bf16
__device__ u16 g_w2ext[(size_t)CC * TK];            // W2 split-ext bf16
__device__ u16 g_xext[(size_t)BB * NP * TK];        // x^T split-ext bf16
__device__ u16 g_recext[(size_t)BB * NP * TK];      // relu(rec)^T split-ext

// ---------------- f32x2 helpers (SIMT EM kernels) --------------------------
__device__ __forceinline__ u64 pack2(float x) {
    u64 r; asm("mov.b64 %0, {%1, %2};" : "=l"(r) : "f"(x), "f"(x)); return r;
}
__device__ __forceinline__ void fma2(u64 &d, u64 a, u64 b) {
    asm("fma.rn.f32x2 %0, %1, %2, %0;" : "+l"(d) : "l"(a), "l"(b));
}
__device__ __forceinline__ float2 unpk(u64 v) {
    float2 f; asm("mov.b64 {%0, %1}, %2;" : "=f"(f.x), "=f"(f.y) : "l"(v)); return f;
}

// ---------------- mma.sync helpers ------------------------------------------
__device__ __forceinline__ u32 smem_u32(const void* p) {
    u32 a;
    asm("{ .reg .u64 t; cvta.to.shared.u64 t, %1; cvt.u32.u64 %0, t; }"
        : "=r"(a) : "l"(p));
    return a;
}
__device__ __forceinline__ void ldsm4(u32* r, u32 addr) {
    asm volatile("ldmatrix.sync.aligned.m8n8.x4.shared.b16 {%0,%1,%2,%3}, [%4];"
                 : "=r"(r[0]), "=r"(r[1]), "=r"(r[2]), "=r"(r[3]) : "r"(addr));
}
__device__ __forceinline__ void ldsm2(u32* r, u32 addr) {
    asm volatile("ldmatrix.sync.aligned.m8n8.x2.shared.b16 {%0,%1}, [%2];"
                 : "=r"(r[0]), "=r"(r[1]) : "r"(addr));
}
__device__ __forceinline__ void mma_bf16(float* d, const u32* a, const u32* b) {
    asm volatile(
        "mma.sync.aligned.m16n8k16.row.col.f32.bf16.bf16.f32 "
        "{%0,%1,%2,%3}, {%4,%5,%6,%7}, {%8,%9}, {%0,%1,%2,%3};"
        : "+f"(d[0]), "+f"(d[1]), "+f"(d[2]), "+f"(d[3])
        : "r"(a[0]), "r"(a[1]), "r"(a[2]), "r"(a[3]), "r"(b[0]), "r"(b[1]));
}

// ---------------- weight split-ext: W[o][c] -> Wext[o][hi|hi|lo] -----------
__global__ void kwext(const float* __restrict__ w1, const float* __restrict__ w2)
{
    int idx = blockIdx.x * 256 + threadIdx.x;   // 512*512 threads
    int o = idx >> 9, c = idx & 511;
    {
        float v = w1[(size_t)o * CC + c];
        __nv_bfloat16 h = __float2bfloat16_rn(v);
        __nv_bfloat16 l = __float2bfloat16_rn(v - __bfloat162float(h));
        u16 hb = __bfloat16_as_ushort(h), lb = __bfloat16_as_ushort(l);
        size_t base = (size_t)o * TK;
        g_w1ext[base + c] = hb; g_w1ext[base + 512 + c] = hb;
        g_w1ext[base + 1024 + c] = lb;
    }
    {
        float v = w2[(size_t)o * CC + c];
        __nv_bfloat16 h = __float2bfloat16_rn(v);
        __nv_bfloat16 l = __float2bfloat16_rn(v - __bfloat162float(h));
        u16 hb = __bfloat16_as_ushort(h), lb = __bfloat16_as_ushort(l);
        size_t base = (size_t)o * TK;
        g_w2ext[base + c] = hb; g_w2ext[base + 512 + c] = hb;
        g_w2ext[base + 1024 + c] = lb;
    }
}

// ---------------- x split-ext + transpose: x[b][c][p] -> xext[b][p][hi|lo|hi]
__global__ void kxext(const float* __restrict__ x)
{
    __shared__ float s[32][33];
    const int p0 = blockIdx.x * 32, c0 = blockIdx.y * 32, b = blockIdx.z;
    const int tx = threadIdx.x, ty = threadIdx.y;
#pragma unroll
    for (int q = 0; q < 4; q++) {
        int cl = ty + q * 8;
        s[cl][tx] = x[((size_t)b * CC + c0 + cl) * NP + p0 + tx];
    }
    __syncthreads();
#pragma unroll
    for (int q = 0; q < 4; q++) {
        int pl = ty + q * 8;
        float v = s[tx][pl];
        __nv_bfloat16 h = __float2bfloat16_rn(v);
        __nv_bfloat16 l = __float2bfloat16_rn(v - __bfloat162float(h));
        u16 hb = __bfloat16_as_ushort(h), lb = __bfloat16_as_ushort(l);
        size_t base = ((size_t)b * NP + p0 + pl) * TK + c0 + tx;
        g_xext[base] = hb; g_xext[base + 512] = lb; g_xext[base + 1024] = hb;
    }
}

// ---------------- HMMA conv GEMM --------------------------------------------
// D[o, p] = sum_k Aext[o][k] * Bext[p][k]   (K = 1536, bf16, fp32 accum)
// EPI=0: +bias -> g_xf fp32 ; EPI=1: BN -> OUT param
template <int EPI>
__global__ __launch_bounds__(256, 2)
void hmma_conv(float* __restrict__ OUT,
               const float* __restrict__ e0, const float* __restrict__ e1,
               const float* __restrict__ e2, const float* __restrict__ e3)
{
    __shared__ __align__(16) u16 As[128 * 72];   // [o][k] pad 64->72
    __shared__ __align__(16) u16 Bs[128 * 72];   // [p][k]

    const int p0 = blockIdx.x * 128;
    const int o0 = blockIdx.y * 128;
    const int b  = blockIdx.z;
    const int tid = threadIdx.x;
    const int lane = tid & 31, wid = tid >> 5;
    const int wm = wid & 1, wn = wid >> 1;       // 2 (M) x 4 (N) warps
    const int ob = wm * 64, pb = wn * 32;

    const u16* Aext = (EPI == 0) ? g_w1ext : g_w2ext;
    const u16* Bext = ((EPI == 0) ? g_xext : g_recext) + (size_t)b * NP * TK;

    float acc[4][4][4];
#pragma unroll
    for (int mf = 0; mf < 4; mf++)
#pragma unroll
        for (int nf = 0; nf < 4; nf++)
#pragma unroll
            for (int q = 0; q < 4; q++) acc[mf][nf][q] = 0.f;

    const u32 sa = smem_u32(As), sbm = smem_u32(Bs);
    // ldmatrix lane base addresses
    const u32 a_base = sa  + (((ob + (lane & 15)) * 72 + (lane >> 4) * 8) << 1);
    const u32 b_base = sbm + (((pb + (lane & 7)) * 72 + ((lane >> 3) & 1) * 8) << 1);

    for (int ch = 0; ch < NCHUNK; ch++) {
        const int kc0 = ch * 64;
#pragma unroll
        for (int it = 0; it < 4; it++) {
            int lin = tid + it * 256;
            int r = lin >> 3, c8 = (lin & 7) << 3;
            *(uint4*)&As[r * 72 + c8] =
                *(const uint4*)(Aext + (size_t)(o0 + r) * TK + kc0 + c8);
            *(uint4*)&Bs[r * 72 + c8] =
                *(const uint4*)(Bext + (size_t)(p0 + r) * TK + kc0 + c8);
        }
        __syncthreads();
#pragma unroll
        for (int ks = 0; ks < 4; ks++) {
            u32 af[4][4], bf[4][2];
#pragma unroll
            for (int mf = 0; mf < 4; mf++)
                ldsm4(af[mf], a_base + mf * (16 * 72 * 2) + ks * 32);
#pragma unroll
            for (int nf = 0; nf < 4; nf++)
                ldsm2(bf[nf], b_base + nf * (8 * 72 * 2) + ks * 32);
#pragma unroll
            for (int mf = 0; mf < 4; mf++)
#pragma unroll
                for (int nf = 0; nf < 4; nf++)
                    mma_bf16(acc[mf][nf], af[mf], bf[nf]);
        }
        __syncthreads();
    }

    // epilogue
    float* outb = (EPI == 0) ? (g_xf + (size_t)b * CC * NP)
                             : (OUT + (size_t)b * CC * NP);
    const int g = lane >> 2, tg = lane & 3;
#pragma unroll
    for (int mf = 0; mf < 4; mf++) {
        int o_lo = o0 + ob + mf * 16 + g;
        int o_hi = o_lo + 8;
        float mul_lo, add_lo, mul_hi, add_hi;
        if (EPI == 0) {
            mul_lo = mul_hi = 1.f;
            add_lo = e0[o_lo]; add_hi = e0[o_hi];
        } else {
            mul_lo = e0[o_lo] * rsqrtf(e3[o_lo] + 1e-5f);
            add_lo = e1[o_lo] - e2[o_lo] * mul_lo;
            mul_hi = e0[o_hi] * rsqrtf(e3[o_hi] + 1e-5f);
            add_hi = e1[o_hi] - e2[o_hi] * mul_hi;
        }
        float* row_lo = outb + (size_t)o_lo * NP + p0 + pb;
        float* row_hi = outb + (size_t)o_hi * NP + p0 + pb;
#pragma unroll
        for (int nf = 0; nf < 4; nf++) {
            int pc = nf * 8 + tg * 2;
            float2 v0, v1;
            v0.x = acc[mf][nf][0] * mul_lo + add_lo;
            v0.y = acc[mf][nf][1] * mul_lo + add_lo;
            v1.x = acc[mf][nf][2] * mul_hi + add_hi;
            v1.y = acc[mf][nf][3] * mul_hi + add_hi;
            *(float2*)&row_lo[pc] = v0;
            *(float2*)&row_hi[pc] = v1;
        }
    }
}

// ---------------- z kernel: z = softmax_k( xf^T @ m ) ----------------------
__global__ __launch_bounds__(256, 2)
void kz_kernel(const float* __restrict__ MU, int use_gm)
{
    __shared__ float Xs[16][128];
    __shared__ float Ms[16][64];

    const int b  = blockIdx.y;
    const int p0 = blockIdx.x * 128;
    const float* xf = g_xf + (size_t)b * CC * NP;
    const float* mi = use_gm ? (g_m + (size_t)b * CC * KK) : MU;

    const int tid = threadIdx.x;
    const int tx = tid & 15, ty = tid >> 4;
    const int rp = ty * 8, rk = tx * 4;

    u64 acc[8][2];
#pragma unroll
    for (int i = 0; i < 8; i++) { acc[i][0] = 0ULL; acc[i][1] = 0ULL; }

    for (int c0 = 0; c0 < CC; c0 += 16) {
#pragma unroll
        for (int l = 0; l < 2; l++) {
            int f = tid + l * 256;
            int cc = f >> 5, p4 = (f & 31) * 4;
            *(float4*)&Xs[cc][p4] =
                *(const float4*)&xf[(size_t)(c0 + cc) * NP + p0 + p4];
        }
        {
            int cc = tid >> 4, k4 = (tid & 15) * 4;
            *(float4*)&Ms[cc][k4] =
                *(const float4*)&mi[(size_t)(c0 + cc) * KK + k4];
        }
        __syncthreads();
#pragma unroll
        for (int cc = 0; cc < 16; cc++) {
            float4 a0 = *(const float4*)&Xs[cc][rp];
            float4 a1 = *(const float4*)&Xs[cc][rp + 4];
            u64 ap[8];
            ap[0] = pack2(a0.x); ap[1] = pack2(a0.y);
            ap[2] = pack2(a0.z); ap[3] = pack2(a0.w);
            ap[4] = pack2(a1.x); ap[5] = pack2(a1.y);
            ap[6] = pack2(a1.z); ap[7] = pack2(a1.w);
            const u64* bp = (const u64*)&Ms[cc][rk];
            u64 b0 = bp[0], b1 = bp[1];
#pragma unroll
            for (int i = 0; i < 8; i++) {
                fma2(acc[i][0], ap[i], b0);
                fma2(acc[i][1], ap[i], b1);
            }
        }
        __syncthreads();
    }

    float* zb = g_z + ((size_t)b * NP + p0) * KK;
#pragma unroll
    for (int i = 0; i < 8; i++) {
        float2 v01 = unpk(acc[i][0]);
        float2 v23 = unpk(acc[i][1]);
        float mx = fmaxf(fmaxf(v01.x, v01.y), fmaxf(v23.x, v23.y));
#pragma unroll
        for (int s = 1; s < 16; s <<= 1)
            mx = fmaxf(mx, __shfl_xor_sync(0xffffffffu, mx, s));
        float e0 = expf(v01.x - mx), e1 = expf(v01.y - mx);
        float e2 = expf(v23.x - mx), e3 = expf(v23.y - mx);
        float sm = e0 + e1 + e2 + e3;
#pragma unroll
        for (int s = 1; s < 16; s <<= 1)
            sm += __shfl_xor_sync(0xffffffffu, sm, s);
        float inv = 1.f / sm;
        float4 w;
        w.x = e0 * inv; w.y = e1 * inv; w.z = e2 * inv; w.w = e3 * inv;
        *(float4*)&zb[(size_t)(rp + i) * KK + rk] = w;
    }
}

// ---------------- m update (split-K over pixels): mpart = xf @ z -----------
__global__ __launch_bounds__(256, 2)
void km_kernel()
{
    __shared__ float Xs[16][132];
    __shared__ float Zs[16][64];

    const int ct0 = blockIdx.x * 128;
    const int b   = blockIdx.y;
    const int s   = blockIdx.z;
    const int ps0 = s * (NP / NSPLIT);
    const float* xf = g_xf + (size_t)b * CC * NP;
    const float* zz = g_z + (size_t)b * NP * KK;

    const int tid = threadIdx.x;
    const int tx = tid & 15, ty = tid >> 4;
    const int rc = ty * 8, rk = tx * 4;

    u64 acc[8][2];
#pragma unroll
    for (int i = 0; i < 8; i++) { acc[i][0] = 0ULL; acc[i][1] = 0ULL; }

    for (int p0 = ps0; p0 < ps0 + (NP / NSPLIT); p0 += 16) {
#pragma unroll
        for (int l = 0; l < 2; l++) {
            int f = tid + l * 256;
            int row = f >> 2, p4 = (f & 3) * 4;
            float4 v = *(const float4*)&xf[(size_t)(ct0 + row) * NP + p0 + p4];
            Xs[p4 + 0][row] = v.x; Xs[p4 + 1][row] = v.y;
            Xs[p4 + 2][row] = v.z; Xs[p4 + 3][row] = v.w;
        }
        {
            int pp = tid >> 4, k4 = (tid & 15) * 4;
            *(float4*)&Zs[pp][k4] =
                *(const float4*)&zz[(size_t)(p0 + pp) * KK + k4];
        }
        __syncthreads();
#pragma unroll
        for (int pp = 0; pp < 16; pp++) {
            float4 a0 = *(const float4*)&Xs[pp][rc];
            float4 a1 = *(const float4*)&Xs[pp][rc + 4];
            u64 ap[8];
            ap[0] = pack2(a0.x); ap[1] = pack2(a0.y);
            ap[2] = pack2(a0.z); ap[3] = pack2(a0.w);
            ap[4] = pack2(a1.x); ap[5] = pack2(a1.y);
            ap[6] = pack2(a1.z); ap[7] = pack2(a1.w);
            const u64* bp = (const u64*)&Zs[pp][rk];
            u64 b0 = bp[0], b1 = bp[1];
#pragma unroll
            for (int i = 0; i < 8; i++) {
                fma2(acc[i][0], ap[i], b0);
                fma2(acc[i][1], ap[i], b1);
            }
        }
        __syncthreads();
    }

    float* out = g_mpart + ((size_t)(s * BB + b) * CC + ct0) * KK;
#pragma unroll
    for (int i = 0; i < 8; i++) {
        u64* op = (u64*)&out[(size_t)(rc + i) * KK + rk];
        op[0] = acc[i][0];
        op[1] = acc[i][1];
    }
}

// ---------------- norm phase 1 ----------------------------------------------
__global__ void knorm1()
{
    const int cs = blockIdx.x, b = blockIdx.y;
    __shared__ float red[256];
    const int tid = threadIdx.x;
    const size_t bc = ((size_t)b * CC + cs * 64) * KK;
    float ln = 0.f;
#pragma unroll
    for (int it = 0; it < 16; it++) {
        size_t off = bc + tid + it * 256;
        float v = 0.f;
#pragma unroll
        for (int s = 0; s < NSPLIT; s++)
            v += g_mpart[(size_t)s * (BB * CC * KK) + off];
        g_m[off] = v;
        ln += v * v;
    }
    red[tid] = ln;
    __syncthreads();
    if (tid < 64)
        g_norm2[(size_t)(cs * BB + b) * KK + tid] =
            red[tid] + red[tid + 64] + red[tid + 128] + red[tid + 192];
}

// ---------------- norm phase 2 ----------------------------------------------
__global__ void knorm2()
{
    const int cs = blockIdx.x, b = blockIdx.y;
    __shared__ float inv[64];
    const int tid = threadIdx.x;
    if (tid < 64) {
        float s = 0.f;
#pragma unroll
        for (int q = 0; q < 8; q++)
            s += g_norm2[(size_t)(q * BB + b) * KK + tid];
        inv[tid] = 1.f / (EPSF + sqrtf(s));
    }
    __syncthreads();
    const size_t bc = ((size_t)b * CC + cs * 64) * KK;
#pragma unroll
    for (int it = 0; it < 16; it++) {
        size_t off = bc + tid + it * 256;
        g_m[off] *= inv[tid & 63];
    }
}

// ---------------- rec = relu(m @ z^T) -> split-ext transposed bf16 ---------
__global__ __launch_bounds__(256, 2)
void krec_kernel()
{
    __shared__ float As[16][132];
    __shared__ float Bs[16][128];

    const int p0  = blockIdx.x * 128;
    const int ct0 = blockIdx.y * 128;
    const int b   = blockIdx.z;
    const float* mm = g_m + (size_t)b * CC * KK;
    const float* zz = g_z + (size_t)b * NP * KK;

    const int tid = threadIdx.x;
    const int tx = tid & 15, ty = tid >> 4;
    const int rc = ty * 8, rp = tx * 8;

    u64 acc[8][4];
#pragma unroll
    for (int i = 0; i < 8; i++)
#pragma unroll
        for (int j = 0; j < 4; j++) acc[i][j] = 0ULL;

    for (int k0 = 0; k0 < KK; k0 += 16) {
#pragma unroll
        for (int l = 0; l < 2; l++) {
            int f = tid + l * 256;
            int row = f >> 2, k4 = (f & 3) * 4;
            float4 v = *(const float4*)&mm[(size_t)(ct0 + row) * KK + k0 + k4];
            As[k4 + 0][row] = v.x; As[k4 + 1][row] = v.y;
            As[k4 + 2][row] = v.z; As[k4 + 3][row] = v.w;
        }
#pragma unroll
        for (int l = 0; l < 2; l++) {
            int f = tid + l * 256;
            int row = f >> 2, k4 = (f & 3) * 4;
            float4 v = *(const float4*)&zz[(size_t)(p0 + row) * KK + k0 + k4];
            Bs[k4 + 0][row] = v.x; Bs[k4 + 1][row] = v.y;
            Bs[k4 + 2][row] = v.z; Bs[k4 + 3][row] = v.w;
        }
        __syncthreads();
#pragma unroll
        for (int kk = 0; kk < 16; kk++) {
            float4 a0 = *(const float4*)&As[kk][rc];
            float4 a1 = *(const float4*)&As[kk][rc + 4];
            u64 ap[8];
            ap[0] = pack2(a0.x); ap[1] = pack2(a0.y);
            ap[2] = pack2(a0.z); ap[3] = pack2(a0.w);
            ap[4] = pack2(a1.x); ap[5] = pack2(a1.y);
            ap[6] = pack2(a1.z); ap[7] = pack2(a1.w);
            const u64* bp = (const u64*)&Bs[kk][rp];
            u64 b0 = bp[0], b1 = bp[1], b2 = bp[2], b3 = bp[3];
#pragma unroll
            for (int i = 0; i < 8; i++) {
                fma2(acc[i][0], ap[i], b0);
                fma2(acc[i][1], ap[i], b1);
                fma2(acc[i][2], ap[i], b2);
                fma2(acc[i][3], ap[i], b3);
            }
        }
        __syncthreads();
    }

    // epilogue: relu + bf16 split, write transposed [p][c-slots]
    float f[8][8];
#pragma unroll
    for (int i = 0; i < 8; i++) {
        float2 t0 = unpk(acc[i][0]), t1 = unpk(acc[i][1]);
        float2 t2 = unpk(acc[i][2]), t3 = unpk(acc[i][3]);
        f[i][0] = fmaxf(t0.x, 0.f); f[i][1] = fmaxf(t0.y, 0.f);
        f[i][2] = fmaxf(t1.x, 0.f); f[i][3] = fmaxf(t1.y, 0.f);
        f[i][4] = fmaxf(t2.x, 0.f); f[i][5] = fmaxf(t2.y, 0.f);
        f[i][6] = fmaxf(t3.x, 0.f); f[i][7] = fmaxf(t3.y, 0.f);
    }
    u16* base = g_recext + (size_t)b * NP * TK;
#pragma unroll
    for (int jp = 0; jp < 8; jp++) {
        int p = p0 + rp + jp;
        u32 hw[4], lw[4];
#pragma unroll
        for (int q = 0; q < 4; q++) {
            float v0 = f[q * 2 + 0][jp], v1 = f[q * 2 + 1][jp];
            __nv_bfloat16 h0 = __float2bfloat16_rn(v0);
            __nv_bfloat16 h1 = __float2bfloat16_rn(v1);
            __nv_bfloat16 l0 = __float2bfloat16_rn(v0 - __bfloat162float(h0));
            __nv_bfloat16 l1 = __float2bfloat16_rn(v1 - __bfloat162float(h1));
            hw[q] = (u32)__bfloat16_as_ushort(h0) |
                    ((u32)__bfloat16_as_ushort(h1) << 16);
            lw[q] = (u32)__bfloat16_as_ushort(l0) |
                    ((u32)__bfloat16_as_ushort(l1) << 16);
        }
        uint4 hv = make_uint4(hw[0], hw[1], hw[2], hw[3]);
        uint4 lv = make_uint4(lw[0], lw[1], lw[2], lw[3]);
        u16* row = base + (size_t)p * TK + ct0 + rc;
        *(uint4*)(row)        = hv;   // slot 0: hi
        *(uint4*)(row + 512)  = lv;   // slot 1: lo
        *(uint4*)(row + 1024) = hv;   // slot 2: hi
    }
}

// ---------------- launch ----------------------------------------------------
extern "C" void kernel_launch(void* const* d_in, const int* in_sizes, int n_in,
                              void* d_out, int out_size)
{
    (void)in_sizes; (void)n_in; (void)out_size;
    const float* x     = (const float*)d_in[0];
    const float* w1    = (const float*)d_in[1];
    const float* b1    = (const float*)d_in[2];
    const float* mu    = (const float*)d_in[3];
    const float* w2    = (const float*)d_in[4];
    const float* gamma = (const float*)d_in[5];
    const float* beta  = (const float*)d_in[6];
    const float* mean  = (const float*)d_in[7];
    const float* var   = (const float*)d_in[8];
    float* out = (float*)d_out;

    kwext<<<1024, 256>>>(w1, w2);
    kxext<<<dim3(NP / 32, CC / 32, BB), dim3(32, 8)>>>(x);

    hmma_conv<0><<<dim3(NP / 128, CC / 128, BB), 256>>>(
        nullptr, b1, nullptr, nullptr, nullptr);

    for (int st = 0; st < 3; st++) {
        kz_kernel<<<dim3(NP / 128, BB), 256>>>(mu, st > 0 ? 1 : 0);
        km_kernel<<<dim3(CC / 128, BB, NSPLIT), 256>>>();
        knorm1<<<dim3(8, BB), 256>>>();
        knorm2<<<dim3(8, BB), 256>>>();
    }

    krec_kernel<<<dim3(NP / 128, CC / 128, BB), 256>>>();

    hmma_conv<1><<<dim3(NP / 128, CC / 128, BB), 256>>>(
        out, gamma, beta, mean, var);
}

// round 5
// speedup vs baseline: 2.0565x; 1.4713x over previous
#include <cuda_runtime.h>
#include <cuda_bf16.h>

#define CC 512
#define NP 4096
#define KK 64
#define BB 16
#define NSPLIT 4
#define EPSF 1e-6f

typedef unsigned long long u64;
typedef unsigned int u32;
typedef unsigned short u16;

// ---------------- scratch (static device globals) ---------------------------
__device__ u16 g_xh[(size_t)BB * CC * NP];   // x hi   (b,c,p)
__device__ u16 g_xl[(size_t)BB * CC * NP];   // x lo
__device__ u16 g_wh1[(size_t)CC * CC], g_wl1[(size_t)CC * CC];
__device__ u16 g_wh2[(size_t)CC * CC], g_wl2[(size_t)CC * CC];
__device__ u16 g_muh[(size_t)CC * KK], g_mul[(size_t)CC * KK];
__device__ u16 g_xfh[(size_t)BB * CC * NP];  // conv1 out hi (b,c,p)
__device__ u16 g_xfl[(size_t)BB * CC * NP];
__device__ u16 g_zh[(size_t)BB * NP * KK];   // z hi (b,p,k)
__device__ u16 g_zl[(size_t)BB * NP * KK];
__device__ u16 g_mh[(size_t)BB * CC * KK];   // m hi (b,c,k)
__device__ u16 g_ml[(size_t)BB * CC * KK];
__device__ u16 g_rech[(size_t)BB * CC * NP]; // relu(rec) hi (b,c,p)
__device__ u16 g_recl[(size_t)BB * CC * NP];
__device__ float g_mpart[(size_t)NSPLIT * BB * CC * KK];
__device__ float g_m[(size_t)BB * CC * KK];
__device__ float g_norm2[(size_t)8 * BB * KK];

// ---------------- helpers ----------------------------------------------------
__device__ __forceinline__ u32 smem_u32(const void* p) {
    u32 a;
    asm("{ .reg .u64 t; cvta.to.shared.u64 t, %1; cvt.u32.u64 %0, t; }"
        : "=r"(a) : "l"(p));
    return a;
}
__device__ __forceinline__ void ldsm4(u32* r, u32 addr) {
    asm volatile("ldmatrix.sync.aligned.m8n8.x4.shared.b16 {%0,%1,%2,%3}, [%4];"
                 : "=r"(r[0]), "=r"(r[1]), "=r"(r[2]), "=r"(r[3]) : "r"(addr));
}
__device__ __forceinline__ void ldsm4t(u32* r, u32 addr) {
    asm volatile("ldmatrix.sync.aligned.m8n8.x4.trans.shared.b16 {%0,%1,%2,%3}, [%4];"
                 : "=r"(r[0]), "=r"(r[1]), "=r"(r[2]), "=r"(r[3]) : "r"(addr));
}
__device__ __forceinline__ void mma_bf16(float* d, const u32* a, const u32* b) {
    asm volatile(
        "mma.sync.aligned.m16n8k16.row.col.f32.bf16.bf16.f32 "
        "{%0,%1,%2,%3}, {%4,%5,%6,%7}, {%8,%9}, {%0,%1,%2,%3};"
        : "+f"(d[0]), "+f"(d[1]), "+f"(d[2]), "+f"(d[3])
        : "r"(a[0]), "r"(a[1]), "r"(a[2]), "r"(a[3]), "r"(b[0]), "r"(b[1]));
}
__device__ __forceinline__ void split2(float v0, float v1, u32& hi, u32& lo) {
    __nv_bfloat16 h0 = __float2bfloat16_rn(v0);
    __nv_bfloat16 h1 = __float2bfloat16_rn(v1);
    __nv_bfloat16 l0 = __float2bfloat16_rn(v0 - __bfloat162float(h0));
    __nv_bfloat16 l1 = __float2bfloat16_rn(v1 - __bfloat162float(h1));
    hi = (u32)__bfloat16_as_ushort(h0) | ((u32)__bfloat16_as_ushort(h1) << 16);
    lo = (u32)__bfloat16_as_ushort(l0) | ((u32)__bfloat16_as_ushort(l1) << 16);
}

// ---------------- convert kernels -------------------------------------------
__global__ void kcvt_x(const float* __restrict__ x)
{
    size_t i4 = ((size_t)blockIdx.x * 256 + threadIdx.x) * 4;
    float4 v = *(const float4*)&x[i4];
    u32 h0, l0, h1, l1;
    split2(v.x, v.y, h0, l0);
    split2(v.z, v.w, h1, l1);
    *(uint2*)&g_xh[i4] = make_uint2(h0, h1);
    *(uint2*)&g_xl[i4] = make_uint2(l0, l1);
}
__global__ void kcvt_w(const float* __restrict__ w1, const float* __restrict__ w2)
{
    size_t i2 = ((size_t)blockIdx.x * 256 + threadIdx.x) * 2;
    {
        u32 h, l;
        split2(w1[i2], w1[i2 + 1], h, l);
        *(u32*)&g_wh1[i2] = h; *(u32*)&g_wl1[i2] = l;
    }
    {
        u32 h, l;
        split2(w2[i2], w2[i2 + 1], h, l);
        *(u32*)&g_wh2[i2] = h; *(u32*)&g_wl2[i2] = l;
    }
}
__global__ void kcvt_mu(const float* __restrict__ mu)
{
    size_t i2 = ((size_t)blockIdx.x * 256 + threadIdx.x) * 2;
    u32 h, l;
    split2(mu[i2], mu[i2 + 1], h, l);
    *(u32*)&g_muh[i2] = h; *(u32*)&g_mul[i2] = l;
}

// ---------------- conv GEMM: D[o,p] = sum_c W[o,c]*IN[c,p] + epi -------------
// EPI=0: bias -> g_xfh/g_xfl (bf16 split) ; EPI=1: BN -> OUT fp32
template <int EPI>
__global__ __launch_bounds__(256, 2)
void hconv(float* __restrict__ OUT,
           const float* __restrict__ e0, const float* __restrict__ e1,
           const float* __restrict__ e2, const float* __restrict__ e3)
{
    __shared__ __align__(16) u16 Ah[128 * 40], Al[128 * 40]; // (o, c32) pitch 40
    __shared__ __align__(16) u16 Bh[32 * 136], Bl[32 * 136]; // (c32, p128) pitch 136

    const int p0 = blockIdx.x * 128;
    const int o0 = blockIdx.y * 128;
    const int b  = blockIdx.z;
    const int tid = threadIdx.x;
    const int lane = tid & 31, wid = tid >> 5;
    const int wm = wid & 1, wn = wid >> 1;
    const int ob = wm * 64, pb = wn * 32;

    const u16* WH = (EPI == 0) ? g_wh1 : g_wh2;
    const u16* WL = (EPI == 0) ? g_wl1 : g_wl2;
    const u16* IH = ((EPI == 0) ? g_xh : g_rech) + (size_t)b * CC * NP;
    const u16* IL = ((EPI == 0) ? g_xl : g_recl) + (size_t)b * CC * NP;

    float acc[4][4][4];
#pragma unroll
    for (int mf = 0; mf < 4; mf++)
#pragma unroll
        for (int nf = 0; nf < 4; nf++)
#pragma unroll
            for (int q = 0; q < 4; q++) acc[mf][nf][q] = 0.f;

    const u32 sah = smem_u32(Ah), sal = smem_u32(Al);
    const u32 sbh = smem_u32(Bh), sbl = smem_u32(Bl);

    for (int c0 = 0; c0 < CC; c0 += 32) {
#pragma unroll
        for (int it = 0; it < 2; it++) {        // A: 128 x 32
            int lin = tid + it * 256;
            int r = lin >> 2, g = lin & 3;
            *(uint4*)&Ah[r * 40 + g * 8] =
                *(const uint4*)(WH + (size_t)(o0 + r) * CC + c0 + g * 8);
            *(uint4*)&Al[r * 40 + g * 8] =
                *(const uint4*)(WL + (size_t)(o0 + r) * CC + c0 + g * 8);
        }
#pragma unroll
        for (int it = 0; it < 2; it++) {        // B: 32 x 128 (c-major source)
            int lin = tid + it * 256;
            int r = lin >> 4, g = lin & 15;
            *(uint4*)&Bh[r * 136 + g * 8] =
                *(const uint4*)(IH + (size_t)(c0 + r) * NP + p0 + g * 8);
            *(uint4*)&Bl[r * 136 + g * 8] =
                *(const uint4*)(IL + (size_t)(c0 + r) * NP + p0 + g * 8);
        }
        __syncthreads();
#pragma unroll
        for (int ks = 0; ks < 2; ks++) {
            u32 ah[4][4], al[4][4];
            u32 a_off = (((ob + (lane & 15)) * 40 + ks * 16 + (lane >> 4) * 8)) << 1;
#pragma unroll
            for (int mf = 0; mf < 4; mf++) {
                ldsm4(ah[mf], sah + a_off + mf * (16 * 40 * 2));
                ldsm4(al[mf], sal + a_off + mf * (16 * 40 * 2));
            }
            // B via trans: row = c (K dim), col = p
            u32 bh[2][4], bl[2][4];
            u32 brow = ks * 16 + (lane & 7) + ((lane >> 3) & 1) * 8;
            u32 bcol = pb + ((lane >> 4) & 1) * 8;
#pragma unroll
            for (int pr = 0; pr < 2; pr++) {
                u32 boff = (brow * 136 + bcol + pr * 16) << 1;
                ldsm4t(bh[pr], sbh + boff);
                ldsm4t(bl[pr], sbl + boff);
            }
#pragma unroll
            for (int mf = 0; mf < 4; mf++)
#pragma unroll
                for (int nf = 0; nf < 4; nf++) {
                    const u32* bhp = &bh[nf >> 1][(nf & 1) * 2];
                    const u32* blp = &bl[nf >> 1][(nf & 1) * 2];
                    mma_bf16(acc[mf][nf], ah[mf], bhp);
                    mma_bf16(acc[mf][nf], ah[mf], blp);
                    mma_bf16(acc[mf][nf], al[mf], bhp);
                }
        }
        __syncthreads();
    }

    const int g = lane >> 2, tg = lane & 3;
#pragma unroll
    for (int mf = 0; mf < 4; mf++) {
        int o_lo = o0 + ob + mf * 16 + g;
        int o_hi = o_lo + 8;
        if (EPI == 0) {
            float add_lo = e0[o_lo], add_hi = e0[o_hi];
            u16* xfh = g_xfh + (size_t)b * CC * NP;
            u16* xfl = g_xfl + (size_t)b * CC * NP;
#pragma unroll
            for (int nf = 0; nf < 4; nf++) {
                int pc = p0 + pb + nf * 8 + tg * 2;
                u32 h, l;
                split2(acc[mf][nf][0] + add_lo, acc[mf][nf][1] + add_lo, h, l);
                *(u32*)&xfh[(size_t)o_lo * NP + pc] = h;
                *(u32*)&xfl[(size_t)o_lo * NP + pc] = l;
                split2(acc[mf][nf][2] + add_hi, acc[mf][nf][3] + add_hi, h, l);
                *(u32*)&xfh[(size_t)o_hi * NP + pc] = h;
                *(u32*)&xfl[(size_t)o_hi * NP + pc] = l;
            }
        } else {
            float mul_lo = e0[o_lo] * rsqrtf(e3[o_lo] + 1e-5f);
            float add_lo = e1[o_lo] - e2[o_lo] * mul_lo;
            float mul_hi = e0[o_hi] * rsqrtf(e3[o_hi] + 1e-5f);
            float add_hi = e1[o_hi] - e2[o_hi] * mul_hi;
            float* outb = OUT + (size_t)b * CC * NP;
#pragma unroll
            for (int nf = 0; nf < 4; nf++) {
                int pc = p0 + pb + nf * 8 + tg * 2;
                float2 v0, v1;
                v0.x = acc[mf][nf][0] * mul_lo + add_lo;
                v0.y = acc[mf][nf][1] * mul_lo + add_lo;
                v1.x = acc[mf][nf][2] * mul_hi + add_hi;
                v1.y = acc[mf][nf][3] * mul_hi + add_hi;
                *(float2*)&outb[(size_t)o_lo * NP + pc] = v0;
                *(float2*)&outb[(size_t)o_hi * NP + pc] = v1;
            }
        }
    }
}

// ---------------- kz: z = softmax_k( xf^T @ m ), HMMA ------------------------
// M = p (128/CTA, 16/warp), N = k = 64, K = c = 512
__global__ __launch_bounds__(256, 2)
void kz_kernel(int use_gm)
{
    __shared__ __align__(16) u16 Xh[32 * 136], Xl[32 * 136]; // (c32, p128)
    __shared__ __align__(16) u16 Mh[32 * 72],  Ml[32 * 72];  // (c32, k64)

    const int p0 = blockIdx.x * 128;
    const int b  = blockIdx.y;
    const int tid = threadIdx.x;
    const int lane = tid & 31, wid = tid >> 5;
    const int pw = wid * 16;                       // warp p-base (CTA-rel)

    const u16* XH = g_xfh + (size_t)b * CC * NP;
    const u16* XL = g_xfl + (size_t)b * CC * NP;
    const u16* MH = use_gm ? (g_mh + (size_t)b * CC * KK) : g_muh;
    const u16* ML = use_gm ? (g_ml + (size_t)b * CC * KK) : g_mul;

    float acc[8][4];
#pragma unroll
    for (int nf = 0; nf < 8; nf++)
#pragma unroll
        for (int q = 0; q < 4; q++) acc[nf][q] = 0.f;

    const u32 sxh = smem_u32(Xh), sxl = smem_u32(Xl);
    const u32 smh = smem_u32(Mh), sml = smem_u32(Ml);

    for (int c0 = 0; c0 < CC; c0 += 32) {
#pragma unroll
        for (int it = 0; it < 2; it++) {        // X: 32 x 128
            int lin = tid + it * 256;
            int r = lin >> 4, g = lin & 15;
            *(uint4*)&Xh[r * 136 + g * 8] =
                *(const uint4*)(XH + (size_t)(c0 + r) * NP + p0 + g * 8);
            *(uint4*)&Xl[r * 136 + g * 8] =
                *(const uint4*)(XL + (size_t)(c0 + r) * NP + p0 + g * 8);
        }
        {                                        // M: 32 x 64
            int r = tid >> 3, g = tid & 7;
            *(uint4*)&Mh[r * 72 + g * 8] =
                *(const uint4*)(MH + (size_t)(c0 + r) * KK + g * 8);
            *(uint4*)&Ml[r * 72 + g * 8] =
                *(const uint4*)(ML + (size_t)(c0 + r) * KK + g * 8);
        }
        __syncthreads();
#pragma unroll
        for (int ks = 0; ks < 2; ks++) {
            // A via trans: a0=(m0-7,k0-7) a1=(m8-15,k0-7) a2=(m0-7,k8-15) a3=(m8-15,k8-15)
            u32 ah[4], al[4];
            {
                u32 row = ks * 16 + (lane & 7) + ((lane >> 4) & 1) * 8;
                u32 col = pw + ((lane >> 3) & 1) * 8;
                u32 off = (row * 136 + col) << 1;
                ldsm4t(ah, sxh + off);
                ldsm4t(al, sxl + off);
            }
            u32 bh[4][4], bl[4][4];
            {
                u32 row = ks * 16 + (lane & 7) + ((lane >> 3) & 1) * 8;
                u32 col = ((lane >> 4) & 1) * 8;
#pragma unroll
                for (int pr = 0; pr < 4; pr++) {
                    u32 off = (row * 72 + col + pr * 16) << 1;
                    ldsm4t(bh[pr], smh + off);
                    ldsm4t(bl[pr], sml + off);
                }
            }
#pragma unroll
            for (int nf = 0; nf < 8; nf++) {
                const u32* bhp = &bh[nf >> 1][(nf & 1) * 2];
                const u32* blp = &bl[nf >> 1][(nf & 1) * 2];
                mma_bf16(acc[nf], ah, bhp);
                mma_bf16(acc[nf], ah, blp);
                mma_bf16(acc[nf], al, bhp);
            }
        }
        __syncthreads();
    }

    // softmax over k=64 (4 lanes per row x 16 vals each), then split-write z
    const int gr = lane >> 2;
    float mx0 = -1e30f, mx1 = -1e30f;
#pragma unroll
    for (int nf = 0; nf < 8; nf++) {
        mx0 = fmaxf(mx0, fmaxf(acc[nf][0], acc[nf][1]));
        mx1 = fmaxf(mx1, fmaxf(acc[nf][2], acc[nf][3]));
    }
#pragma unroll
    for (int s = 1; s < 4; s <<= 1) {
        mx0 = fmaxf(mx0, __shfl_xor_sync(0xffffffffu, mx0, s));
        mx1 = fmaxf(mx1, __shfl_xor_sync(0xffffffffu, mx1, s));
    }
    float sm0 = 0.f, sm1 = 0.f;
#pragma unroll
    for (int nf = 0; nf < 8; nf++) {
        acc[nf][0] = expf(acc[nf][0] - mx0); sm0 += acc[nf][0];
        acc[nf][1] = expf(acc[nf][1] - mx0); sm0 += acc[nf][1];
        acc[nf][2] = expf(acc[nf][2] - mx1); sm1 += acc[nf][2];
        acc[nf][3] = expf(acc[nf][3] - mx1); sm1 += acc[nf][3];
    }
#pragma unroll
    for (int s = 1; s < 4; s <<= 1) {
        sm0 += __shfl_xor_sync(0xffffffffu, sm0, s);
        sm1 += __shfl_xor_sync(0xffffffffu, sm1, s);
    }
    float inv0 = 1.f / sm0, inv1 = 1.f / sm1;
    const int tg = lane & 3;
    size_t prow_lo = (size_t)(b * NP + p0 + pw + gr) * KK;
    size_t prow_hi = prow_lo + (size_t)8 * KK;
#pragma unroll
    for (int nf = 0; nf < 8; nf++) {
        int kc = nf * 8 + tg * 2;
        u32 h, l;
        split2(acc[nf][0] * inv0, acc[nf][1] * inv0, h, l);
        *(u32*)&g_zh[prow_lo + kc] = h;
        *(u32*)&g_zl[prow_lo + kc] = l;
        split2(acc[nf][2] * inv1, acc[nf][3] * inv1, h, l);
        *(u32*)&g_zh[prow_hi + kc] = h;
        *(u32*)&g_zl[prow_hi + kc] = l;
    }
}

// ---------------- km: mpart = xf @ z (split-K over p), HMMA ------------------
// M = c (128/CTA, 16/warp), N = k = 64, K = p (1024/split)
__global__ __launch_bounds__(256, 2)
void km_kernel()
{
    __shared__ __align__(16) u16 Ah[128 * 40], Al[128 * 40]; // (c128, p32)
    __shared__ __align__(16) u16 Zh[32 * 72],  Zl[32 * 72];  // (p32, k64)

    const int ct0 = blockIdx.x * 128;
    const int b   = blockIdx.y;
    const int s   = blockIdx.z;
    const int ps0 = s * (NP / NSPLIT);
    const int tid = threadIdx.x;
    const int lane = tid & 31, wid = tid >> 5;

    const u16* XH = g_xfh + (size_t)b * CC * NP;
    const u16* XL = g_xfl + (size_t)b * CC * NP;
    const u16* ZH = g_zh + (size_t)b * NP * KK;
    const u16* ZL = g_zl + (size_t)b * NP * KK;

    float acc[8][4];
#pragma unroll
    for (int nf = 0; nf < 8; nf++)
#pragma unroll
        for (int q = 0; q < 4; q++) acc[nf][q] = 0.f;

    const u32 sah = smem_u32(Ah), sal = smem_u32(Al);
    const u32 szh = smem_u32(Zh), szl = smem_u32(Zl);

    for (int pc0 = ps0; pc0 < ps0 + NP / NSPLIT; pc0 += 32) {
#pragma unroll
        for (int it = 0; it < 2; it++) {        // A: 128 c x 32 p
            int lin = tid + it * 256;
            int r = lin >> 2, g = lin & 3;
            *(uint4*)&Ah[r * 40 + g * 8] =
                *(const uint4*)(XH + (size_t)(ct0 + r) * NP + pc0 + g * 8);
            *(uint4*)&Al[r * 40 + g * 8] =
                *(const uint4*)(XL + (size_t)(ct0 + r) * NP + pc0 + g * 8);
        }
        {                                        // Z: 32 p x 64 k
            int r = tid >> 3, g = tid & 7;
            *(uint4*)&Zh[r * 72 + g * 8] =
                *(const uint4*)(ZH + (size_t)(pc0 + r) * KK + g * 8);
            *(uint4*)&Zl[r * 72 + g * 8] =
                *(const uint4*)(ZL + (size_t)(pc0 + r) * KK + g * 8);
        }
        __syncthreads();
#pragma unroll
        for (int ks = 0; ks < 2; ks++) {
            u32 ah[4], al[4];
            {
                u32 off = (((wid * 16 + (lane & 15)) * 40 +
                            ks * 16 + (lane >> 4) * 8)) << 1;
                ldsm4(ah, sah + off);
                ldsm4(al, sal + off);
            }
            u32 bh[4][4], bl[4][4];
            {
                u32 row = ks * 16 + (lane & 7) + ((lane >> 3) & 1) * 8;
                u32 col = ((lane >> 4) & 1) * 8;
#pragma unroll
                for (int pr = 0; pr < 4; pr++) {
                    u32 off = (row * 72 + col + pr * 16) << 1;
                    ldsm4t(bh[pr], szh + off);
                    ldsm4t(bl[pr], szl + off);
                }
            }
#pragma unroll
            for (int nf = 0; nf < 8; nf++) {
                const u32* bhp = &bh[nf >> 1][(nf & 1) * 2];
                const u32* blp = &bl[nf >> 1][(nf & 1) * 2];
                mma_bf16(acc[nf], ah, bhp);
                mma_bf16(acc[nf], ah, blp);
                mma_bf16(acc[nf], al, bhp);
            }
        }
        __syncthreads();
    }

    const int gr = lane >> 2, tg = lane & 3;
    float* out = g_mpart + ((size_t)(s * BB + b) * CC + ct0 + wid * 16) * KK;
#pragma unroll
    for (int nf = 0; nf < 8; nf++) {
        int kc = nf * 8 + tg * 2;
        *(float2*)&out[(size_t)gr * KK + kc] =
            make_float2(acc[nf][0], acc[nf][1]);
        *(float2*)&out[(size_t)(gr + 8) * KK + kc] =
            make_float2(acc[nf][2], acc[nf][3]);
    }
}

// ---------------- norm phase 1: reduce splits + partial norms ---------------
__global__ void knorm1()
{
    const int cs = blockIdx.x, b = blockIdx.y;
    __shared__ float red[256];
    const int tid = threadIdx.x;
    const size_t bc = ((size_t)b * CC + cs * 64) * KK;
    float ln = 0.f;
#pragma unroll
    for (int it = 0; it < 16; it++) {
        size_t off = bc + tid + it * 256;
        float v = 0.f;
#pragma unroll
        for (int s = 0; s < NSPLIT; s++)
            v += g_mpart[(size_t)s * (BB * CC * KK) + off];
        g_m[off] = v;
        ln += v * v;
    }
    red[tid] = ln;
    __syncthreads();
    if (tid < 64)
        g_norm2[(size_t)(cs * BB + b) * KK + tid] =
            red[tid] + red[tid + 64] + red[tid + 128] + red[tid + 192];
}

// ---------------- norm phase 2: scale + split to bf16 ------------------------
__global__ void knorm2()
{
    const int cs = blockIdx.x, b = blockIdx.y;
    __shared__ float inv[64];
    const int tid = threadIdx.x;
    if (tid < 64) {
        float s = 0.f;
#pragma unroll
        for (int q = 0; q < 8; q++)
            s += g_norm2[(size_t)(q * BB + b) * KK + tid];
        inv[tid] = 1.f / (EPSF + sqrtf(s));
    }
    __syncthreads();
    const size_t bc = ((size_t)b * CC + cs * 64) * KK;
#pragma unroll
    for (int it = 0; it < 8; it++) {
        size_t off = bc + (tid + it * 256) * 2;
        float v0 = g_m[off] * inv[(2 * tid) & 63];
        float v1 = g_m[off + 1] * inv[(2 * tid + 1) & 63];
        u32 h, l;
        split2(v0, v1, h, l);
        *(u32*)&g_mh[off] = h;
        *(u32*)&g_ml[off] = l;
    }
}

// ---------------- krec: rec = relu(m @ z^T) -> hi/lo bf16 (c,p) --------------
// M = c 128, N = p 128, K = k 64
__global__ __launch_bounds__(256, 2)
void krec_kernel()
{
    __shared__ __align__(16) u16 Ah[128 * 40], Al[128 * 40]; // (c128, k32)
    __shared__ __align__(16) u16 Bh[128 * 40], Bl[128 * 40]; // (p128, k32)

    const int p0  = blockIdx.x * 128;
    const int ct0 = blockIdx.y * 128;
    const int b   = blockIdx.z;
    const int tid = threadIdx.x;
    const int lane = tid & 31, wid = tid >> 5;
    const int wm = wid & 1, wn = wid >> 1;
    const int cb = wm * 64, pb = wn * 32;

    const u16* MH = g_mh + (size_t)b * CC * KK;
    const u16* ML = g_ml + (size_t)b * CC * KK;
    const u16* ZH = g_zh + (size_t)b * NP * KK;
    const u16* ZL = g_zl + (size_t)b * NP * KK;

    float acc[4][4][4];
#pragma unroll
    for (int mf = 0; mf < 4; mf++)
#pragma unroll
        for (int nf = 0; nf < 4; nf++)
#pragma unroll
            for (int q = 0; q < 4; q++) acc[mf][nf][q] = 0.f;

    const u32 sah = smem_u32(Ah), sal = smem_u32(Al);
    const u32 sbh = smem_u32(Bh), sbl = smem_u32(Bl);

    for (int kc0 = 0; kc0 < KK; kc0 += 32) {
#pragma unroll
        for (int it = 0; it < 2; it++) {
            int lin = tid + it * 256;
            int r = lin >> 2, g = lin & 3;
            *(uint4*)&Ah[r * 40 + g * 8] =
                *(const uint4*)(MH + (size_t)(ct0 + r) * KK + kc0 + g * 8);
            *(uint4*)&Al[r * 40 + g * 8] =
                *(const uint4*)(ML + (size_t)(ct0 + r) * KK + kc0 + g * 8);
        }
#pragma unroll
        for (int it = 0; it < 2; it++) {
            int lin = tid + it * 256;
            int r = lin >> 2, g = lin & 3;
            *(uint4*)&Bh[r * 40 + g * 8] =
                *(const uint4*)(ZH + (size_t)(p0 + r) * KK + kc0 + g * 8);
            *(uint4*)&Bl[r * 40 + g * 8] =
                *(const uint4*)(ZL + (size_t)(p0 + r) * KK + kc0 + g * 8);
        }
        __syncthreads();
#pragma unroll
        for (int ks = 0; ks < 2; ks++) {
            u32 ah[4][4], al[4][4];
            u32 a_off = (((cb + (lane & 15)) * 40 + ks * 16 + (lane >> 4) * 8)) << 1;
#pragma unroll
            for (int mf = 0; mf < 4; mf++) {
                ldsm4(ah[mf], sah + a_off + mf * (16 * 40 * 2));
                ldsm4(al[mf], sal + a_off + mf * (16 * 40 * 2));
            }
            // B non-trans pairs: rows p, cols k
            u32 bh[2][4], bl[2][4];
            u32 brow = pb + ((lane >> 4) & 1) * 8 + (lane & 7);
            u32 bcol = ks * 16 + ((lane >> 3) & 1) * 8;
#pragma unroll
            for (int pr = 0; pr < 2; pr++) {
                u32 boff = ((brow + pr * 16) * 40 + bcol) << 1;
                ldsm4(bh[pr], sbh + boff);
                ldsm4(bl[pr], sbl + boff);
            }
#pragma unroll
            for (int mf = 0; mf < 4; mf++)
#pragma unroll
                for (int nf = 0; nf < 4; nf++) {
                    const u32* bhp = &bh[nf >> 1][(nf & 1) * 2];
                    const u32* blp = &bl[nf >> 1][(nf & 1) * 2];
                    mma_bf16(acc[mf][nf], ah[mf], bhp);
                    mma_bf16(acc[mf][nf], ah[mf], blp);
                    mma_bf16(acc[mf][nf], al[mf], bhp);
                }
        }
        __syncthreads();
    }

    const int g = lane >> 2, tg = lane & 3;
    u16* rh = g_rech + (size_t)b * CC * NP;
    u16* rl = g_recl + (size_t)b * CC * NP;
#pragma unroll
    for (int mf = 0; mf < 4; mf++) {
        int c_lo = ct0 + cb + mf * 16 + g;
        int c_hi = c_lo + 8;
#pragma unroll
        for (int nf = 0; nf < 4; nf++) {
            int pc = p0 + pb + nf * 8 + tg * 2;
            u32 h, l;
            split2(fmaxf(acc[mf][nf][0], 0.f), fmaxf(acc[mf][nf][1], 0.f), h, l);
            *(u32*)&rh[(size_t)c_lo * NP + pc] = h;
            *(u32*)&rl[(size_t)c_lo * NP + pc] = l;
            split2(fmaxf(acc[mf][nf][2], 0.f), fmaxf(acc[mf][nf][3], 0.f), h, l);
            *(u32*)&rh[(size_t)c_hi * NP + pc] = h;
            *(u32*)&rl[(size_t)c_hi * NP + pc] = l;
        }
    }
}

// ---------------- launch ----------------------------------------------------
extern "C" void kernel_launch(void* const* d_in, const int* in_sizes, int n_in,
                              void* d_out, int out_size)
{
    (void)in_sizes; (void)n_in; (void)out_size;
    const float* x     = (const float*)d_in[0];
    const float* w1    = (const float*)d_in[1];
    const float* b1    = (const float*)d_in[2];
    const float* mu    = (const float*)d_in[3];
    const float* w2    = (const float*)d_in[4];
    const float* gamma = (const float*)d_in[5];
    const float* beta  = (const float*)d_in[6];
    const float* mean  = (const float*)d_in[7];
    const float* var   = (const float*)d_in[8];
    float* out = (float*)d_out;

    kcvt_x<<<(int)(((size_t)BB * CC * NP) / 1024), 256>>>(x);
    kcvt_w<<<(CC * CC) / 512, 256>>>(w1, w2);
    kcvt_mu<<<(CC * KK) / 512, 256>>>(mu);

    hconv<0><<<dim3(NP / 128, CC / 128, BB), 256>>>(
        nullptr, b1, nullptr, nullptr, nullptr);

    for (int st = 0; st < 3; st++) {
        kz_kernel<<<dim3(NP / 128, BB), 256>>>(st > 0 ? 1 : 0);
        km_kernel<<<dim3(CC / 128, BB, NSPLIT), 256>>>();
        knorm1<<<dim3(8, BB), 256>>>();
        knorm2<<<dim3(8, BB), 256>>>();
    }

    krec_kernel<<<dim3(NP / 128, CC / 128, BB), 256>>>();

    hconv<1><<<dim3(NP / 128, CC / 128, BB), 256>>>(
        out, gamma, beta, mean, var);
}

// round 6
// speedup vs baseline: 2.0990x; 1.0207x over previous
#include <cuda_runtime.h>
#include <cuda_bf16.h>

#define CC 512
#define NP 4096
#define KK 64
#define BB 16
#define NSPLIT 4
#define EPSF 1e-6f

typedef unsigned long long u64;
typedef unsigned int u32;
typedef unsigned short u16;

// ---------------- scratch (static device globals) ---------------------------
__device__ u16 g_xh[(size_t)BB * CC * NP];   // x hi   (b,c,p)
__device__ u16 g_xl[(size_t)BB * CC * NP];   // x lo
__device__ u16 g_wh1[(size_t)CC * CC], g_wl1[(size_t)CC * CC];
__device__ u16 g_wh2[(size_t)CC * CC], g_wl2[(size_t)CC * CC];
__device__ u16 g_muh[(size_t)CC * KK], g_mul[(size_t)CC * KK];
__device__ u16 g_xfh[(size_t)BB * CC * NP];  // conv1 out hi (b,c,p)
__device__ u16 g_xfl[(size_t)BB * CC * NP];
__device__ u16 g_zh[(size_t)BB * NP * KK];   // z hi (b,p,k)
__device__ u16 g_zl[(size_t)BB * NP * KK];
__device__ u16 g_mh[(size_t)BB * CC * KK];   // m hi (b,c,k)
__device__ u16 g_ml[(size_t)BB * CC * KK];
__device__ u16 g_rech[(size_t)BB * CC * NP]; // relu(rec) hi (b,c,p)
__device__ u16 g_recl[(size_t)BB * CC * NP];
__device__ float g_mpart[(size_t)NSPLIT * BB * CC * KK];
__device__ float g_m[(size_t)BB * CC * KK];
__device__ float g_norm2[(size_t)8 * BB * KK];

// ---------------- helpers ----------------------------------------------------
__device__ __forceinline__ u32 smem_u32(const void* p) {
    u32 a;
    asm("{ .reg .u64 t; cvta.to.shared.u64 t, %1; cvt.u32.u64 %0, t; }"
        : "=r"(a) : "l"(p));
    return a;
}
__device__ __forceinline__ void ldsm4(u32* r, u32 addr) {
    asm volatile("ldmatrix.sync.aligned.m8n8.x4.shared.b16 {%0,%1,%2,%3}, [%4];"
                 : "=r"(r[0]), "=r"(r[1]), "=r"(r[2]), "=r"(r[3]) : "r"(addr));
}
__device__ __forceinline__ void ldsm4t(u32* r, u32 addr) {
    asm volatile("ldmatrix.sync.aligned.m8n8.x4.trans.shared.b16 {%0,%1,%2,%3}, [%4];"
                 : "=r"(r[0]), "=r"(r[1]), "=r"(r[2]), "=r"(r[3]) : "r"(addr));
}
__device__ __forceinline__ void mma_bf16(float* d, const u32* a, const u32* b) {
    asm volatile(
        "mma.sync.aligned.m16n8k16.row.col.f32.bf16.bf16.f32 "
        "{%0,%1,%2,%3}, {%4,%5,%6,%7}, {%8,%9}, {%0,%1,%2,%3};"
        : "+f"(d[0]), "+f"(d[1]), "+f"(d[2]), "+f"(d[3])
        : "r"(a[0]), "r"(a[1]), "r"(a[2]), "r"(a[3]), "r"(b[0]), "r"(b[1]));
}
__device__ __forceinline__ void split2(float v0, float v1, u32& hi, u32& lo) {
    __nv_bfloat16 h0 = __float2bfloat16_rn(v0);
    __nv_bfloat16 h1 = __float2bfloat16_rn(v1);
    __nv_bfloat16 l0 = __float2bfloat16_rn(v0 - __bfloat162float(h0));
    __nv_bfloat16 l1 = __float2bfloat16_rn(v1 - __bfloat162float(h1));
    hi = (u32)__bfloat16_as_ushort(h0) | ((u32)__bfloat16_as_ushort(h1) << 16);
    lo = (u32)__bfloat16_as_ushort(l0) | ((u32)__bfloat16_as_ushort(l1) << 16);
}
__device__ __forceinline__ void cpa16(u32 dst, const void* src) {
    asm volatile("cp.async.cg.shared.global [%0], [%1], 16;"
                 :: "r"(dst), "l"(src));
}
#define CPA_COMMIT() asm volatile("cp.async.commit_group;")
#define CPA_WAIT(n)  asm volatile("cp.async.wait_group %0;" :: "n"(n))

// ---------------- convert kernels -------------------------------------------
__global__ void kcvt_x(const float* __restrict__ x)
{
    size_t i4 = ((size_t)blockIdx.x * 256 + threadIdx.x) * 4;
    float4 v = *(const float4*)&x[i4];
    u32 h0, l0, h1, l1;
    split2(v.x, v.y, h0, l0);
    split2(v.z, v.w, h1, l1);
    *(uint2*)&g_xh[i4] = make_uint2(h0, h1);
    *(uint2*)&g_xl[i4] = make_uint2(l0, l1);
}
__global__ void kcvt_w(const float* __restrict__ w1, const float* __restrict__ w2)
{
    size_t i2 = ((size_t)blockIdx.x * 256 + threadIdx.x) * 2;
    {
        u32 h, l;
        split2(w1[i2], w1[i2 + 1], h, l);
        *(u32*)&g_wh1[i2] = h; *(u32*)&g_wl1[i2] = l;
    }
    {
        u32 h, l;
        split2(w2[i2], w2[i2 + 1], h, l);
        *(u32*)&g_wh2[i2] = h; *(u32*)&g_wl2[i2] = l;
    }
}
__global__ void kcvt_mu(const float* __restrict__ mu)
{
    size_t i2 = ((size_t)blockIdx.x * 256 + threadIdx.x) * 2;
    u32 h, l;
    split2(mu[i2], mu[i2 + 1], h, l);
    *(u32*)&g_muh[i2] = h; *(u32*)&g_mul[i2] = l;
}

// ---------------- conv GEMM v2: 64x64 warp tile + cp.async 2-stage ----------
// D[o,p] = sum_c W[o,c]*IN[c,p] + epi
// EPI=0: bias -> g_xfh/g_xfl (bf16 split) ; EPI=1: BN -> OUT fp32
#define APITCH 24
#define BPITCH 136
template <int EPI>
__global__ __launch_bounds__(128, 2)
void hconv(float* __restrict__ OUT,
           const float* __restrict__ e0, const float* __restrict__ e1,
           const float* __restrict__ e2, const float* __restrict__ e3)
{
    __shared__ __align__(16) u16 Ah[2][128 * APITCH], Al[2][128 * APITCH];
    __shared__ __align__(16) u16 Bh[2][16 * BPITCH],  Bl[2][16 * BPITCH];

    const int p0 = blockIdx.x * 128;
    const int o0 = blockIdx.y * 128;
    const int b  = blockIdx.z;
    const int tid = threadIdx.x;
    const int lane = tid & 31, wid = tid >> 5;
    const int ob = (wid & 1) * 64, pb = (wid >> 1) * 64;

    const u16* WH = (EPI == 0) ? g_wh1 : g_wh2;
    const u16* WL = (EPI == 0) ? g_wl1 : g_wl2;
    const u16* IH = ((EPI == 0) ? g_xh : g_rech) + (size_t)b * CC * NP;
    const u16* IL = ((EPI == 0) ? g_xl : g_recl) + (size_t)b * CC * NP;

    float acc[4][8][4];
#pragma unroll
    for (int mf = 0; mf < 4; mf++)
#pragma unroll
        for (int nf = 0; nf < 8; nf++)
#pragma unroll
            for (int q = 0; q < 4; q++) acc[mf][nf][q] = 0.f;

    const u32 sah = smem_u32(Ah), sal = smem_u32(Al);
    const u32 sbh = smem_u32(Bh), sbl = smem_u32(Bl);

    // per-thread load coords (chunk = 16 K-cols)
    const int ar0 = tid >> 1, ag0 = (tid & 1) * 8;          // A: 128 x 16
    const int ar1 = (tid + 128) >> 1, ag1 = ((tid + 128) & 1) * 8;
    const int br0 = tid >> 4, bg0 = (tid & 15) * 8;          // B: 16 x 128
    const int br1 = (tid + 128) >> 4, bg1 = ((tid + 128) & 15) * 8;

#define LOAD_CHUNK(st, c0)                                                     \
    do {                                                                       \
        cpa16(sah + (st) * (128 * APITCH * 2) + (ar0 * APITCH + ag0) * 2,      \
              WH + (size_t)(o0 + ar0) * CC + (c0) + ag0);                      \
        cpa16(sah + (st) * (128 * APITCH * 2) + (ar1 * APITCH + ag1) * 2,      \
              WH + (size_t)(o0 + ar1) * CC + (c0) + ag1);                      \
        cpa16(sal + (st) * (128 * APITCH * 2) + (ar0 * APITCH + ag0) * 2,      \
              WL + (size_t)(o0 + ar0) * CC + (c0) + ag0);                      \
        cpa16(sal + (st) * (128 * APITCH * 2) + (ar1 * APITCH + ag1) * 2,      \
              WL + (size_t)(o0 + ar1) * CC + (c0) + ag1);                      \
        cpa16(sbh + (st) * (16 * BPITCH * 2) + (br0 * BPITCH + bg0) * 2,       \
              IH + (size_t)((c0) + br0) * NP + p0 + bg0);                      \
        cpa16(sbh + (st) * (16 * BPITCH * 2) + (br1 * BPITCH + bg1) * 2,       \
              IH + (size_t)((c0) + br1) * NP + p0 + bg1);                      \
        cpa16(sbl + (st) * (16 * BPITCH * 2) + (br0 * BPITCH + bg0) * 2,       \
              IL + (size_t)((c0) + br0) * NP + p0 + bg0);                      \
        cpa16(sbl + (st) * (16 * BPITCH * 2) + (br1 * BPITCH + bg1) * 2,       \
              IL + (size_t)((c0) + br1) * NP + p0 + bg1);                      \
        CPA_COMMIT();                                                          \
    } while (0)

    LOAD_CHUNK(0, 0);

    const u32 a_lane = ((ob + (lane & 15)) * APITCH + (lane >> 4) * 8) * 2;
    const u32 b_row  = (lane & 7) + ((lane >> 3) & 1) * 8;
    const u32 b_coll = pb + ((lane >> 4) & 1) * 8;

    for (int ch = 0; ch < 32; ch++) {
        const int st = ch & 1;
        if (ch < 31) LOAD_CHUNK(st ^ 1, (ch + 1) * 16);
        if (ch < 31) { CPA_WAIT(1); } else { CPA_WAIT(0); }
        __syncthreads();

        u32 ah[4][4], al[4][4];
        const u32 abase = st * (128 * APITCH * 2) + a_lane;
#pragma unroll
        for (int mf = 0; mf < 4; mf++) {
            ldsm4(ah[mf], sah + abase + mf * (16 * APITCH * 2));
            ldsm4(al[mf], sal + abase + mf * (16 * APITCH * 2));
        }
        const u32 bbase = st * (16 * BPITCH * 2) + (b_row * BPITCH + b_coll) * 2;
#pragma unroll
        for (int pr = 0; pr < 4; pr++) {
            u32 bh[4], bl[4];
            ldsm4t(bh, sbh + bbase + pr * 32);
            ldsm4t(bl, sbl + bbase + pr * 32);
#pragma unroll
            for (int mf = 0; mf < 4; mf++) {
#pragma unroll
                for (int hn = 0; hn < 2; hn++) {
                    float* a = acc[mf][pr * 2 + hn];
                    mma_bf16(a, ah[mf], &bh[hn * 2]);
                    mma_bf16(a, ah[mf], &bl[hn * 2]);
                    mma_bf16(a, al[mf], &bh[hn * 2]);
                }
            }
        }
        __syncthreads();
    }

    const int g = lane >> 2, tg = lane & 3;
#pragma unroll
    for (int mf = 0; mf < 4; mf++) {
        int o_lo = o0 + ob + mf * 16 + g;
        int o_hi = o_lo + 8;
        if (EPI == 0) {
            float add_lo = e0[o_lo], add_hi = e0[o_hi];
            u16* xfh = g_xfh + (size_t)b * CC * NP;
            u16* xfl = g_xfl + (size_t)b * CC * NP;
#pragma unroll
            for (int nf = 0; nf < 8; nf++) {
                int pc = p0 + pb + nf * 8 + tg * 2;
                u32 h, l;
                split2(acc[mf][nf][0] + add_lo, acc[mf][nf][1] + add_lo, h, l);
                *(u32*)&xfh[(size_t)o_lo * NP + pc] = h;
                *(u32*)&xfl[(size_t)o_lo * NP + pc] = l;
                split2(acc[mf][nf][2] + add_hi, acc[mf][nf][3] + add_hi, h, l);
                *(u32*)&xfh[(size_t)o_hi * NP + pc] = h;
                *(u32*)&xfl[(size_t)o_hi * NP + pc] = l;
            }
        } else {
            float mul_lo = e0[o_lo] * rsqrtf(e3[o_lo] + 1e-5f);
            float add_lo = e1[o_lo] - e2[o_lo] * mul_lo;
            float mul_hi = e0[o_hi] * rsqrtf(e3[o_hi] + 1e-5f);
            float add_hi = e1[o_hi] - e2[o_hi] * mul_hi;
            float* outb = OUT + (size_t)b * CC * NP;
#pragma unroll
            for (int nf = 0; nf < 8; nf++) {
                int pc = p0 + pb + nf * 8 + tg * 2;
                float2 v0, v1;
                v0.x = acc[mf][nf][0] * mul_lo + add_lo;
                v0.y = acc[mf][nf][1] * mul_lo + add_lo;
                v1.x = acc[mf][nf][2] * mul_hi + add_hi;
                v1.y = acc[mf][nf][3] * mul_hi + add_hi;
                *(float2*)&outb[(size_t)o_lo * NP + pc] = v0;
                *(float2*)&outb[(size_t)o_hi * NP + pc] = v1;
            }
        }
    }
#undef LOAD_CHUNK
}

// ---------------- kz: z = softmax_k( xf^T @ m ), HMMA ------------------------
// M = p (128/CTA, 16/warp), N = k = 64, K = c = 512
__global__ __launch_bounds__(256, 2)
void kz_kernel(int use_gm)
{
    __shared__ __align__(16) u16 Xh[32 * 136], Xl[32 * 136]; // (c32, p128)
    __shared__ __align__(16) u16 Mh[32 * 72],  Ml[32 * 72];  // (c32, k64)

    const int p0 = blockIdx.x * 128;
    const int b  = blockIdx.y;
    const int tid = threadIdx.x;
    const int lane = tid & 31, wid = tid >> 5;
    const int pw = wid * 16;

    const u16* XH = g_xfh + (size_t)b * CC * NP;
    const u16* XL = g_xfl + (size_t)b * CC * NP;
    const u16* MH = use_gm ? (g_mh + (size_t)b * CC * KK) : g_muh;
    const u16* ML = use_gm ? (g_ml + (size_t)b * CC * KK) : g_mul;

    float acc[8][4];
#pragma unroll
    for (int nf = 0; nf < 8; nf++)
#pragma unroll
        for (int q = 0; q < 4; q++) acc[nf][q] = 0.f;

    const u32 sxh = smem_u32(Xh), sxl = smem_u32(Xl);
    const u32 smh = smem_u32(Mh), sml = smem_u32(Ml);

    for (int c0 = 0; c0 < CC; c0 += 32) {
#pragma unroll
        for (int it = 0; it < 2; it++) {
            int lin = tid + it * 256;
            int r = lin >> 4, g = lin & 15;
            *(uint4*)&Xh[r * 136 + g * 8] =
                *(const uint4*)(XH + (size_t)(c0 + r) * NP + p0 + g * 8);
            *(uint4*)&Xl[r * 136 + g * 8] =
                *(const uint4*)(XL + (size_t)(c0 + r) * NP + p0 + g * 8);
        }
        {
            int r = tid >> 3, g = tid & 7;
            *(uint4*)&Mh[r * 72 + g * 8] =
                *(const uint4*)(MH + (size_t)(c0 + r) * KK + g * 8);
            *(uint4*)&Ml[r * 72 + g * 8] =
                *(const uint4*)(ML + (size_t)(c0 + r) * KK + g * 8);
        }
        __syncthreads();
#pragma unroll
        for (int ks = 0; ks < 2; ks++) {
            u32 ah[4], al[4];
            {
                u32 row = ks * 16 + (lane & 7) + ((lane >> 4) & 1) * 8;
                u32 col = pw + ((lane >> 3) & 1) * 8;
                u32 off = (row * 136 + col) << 1;
                ldsm4t(ah, sxh + off);
                ldsm4t(al, sxl + off);
            }
            u32 bh[4][4], bl[4][4];
            {
                u32 row = ks * 16 + (lane & 7) + ((lane >> 3) & 1) * 8;
                u32 col = ((lane >> 4) & 1) * 8;
#pragma unroll
                for (int pr = 0; pr < 4; pr++) {
                    u32 off = (row * 72 + col + pr * 16) << 1;
                    ldsm4t(bh[pr], smh + off);
                    ldsm4t(bl[pr], sml + off);
                }
            }
#pragma unroll
            for (int nf = 0; nf < 8; nf++) {
                const u32* bhp = &bh[nf >> 1][(nf & 1) * 2];
                const u32* blp = &bl[nf >> 1][(nf & 1) * 2];
                mma_bf16(acc[nf], ah, bhp);
                mma_bf16(acc[nf], ah, blp);
                mma_bf16(acc[nf], al, bhp);
            }
        }
        __syncthreads();
    }

    const int gr = lane >> 2;
    float mx0 = -1e30f, mx1 = -1e30f;
#pragma unroll
    for (int nf = 0; nf < 8; nf++) {
        mx0 = fmaxf(mx0, fmaxf(acc[nf][0], acc[nf][1]));
        mx1 = fmaxf(mx1, fmaxf(acc[nf][2], acc[nf][3]));
    }
#pragma unroll
    for (int s = 1; s < 4; s <<= 1) {
        mx0 = fmaxf(mx0, __shfl_xor_sync(0xffffffffu, mx0, s));
        mx1 = fmaxf(mx1, __shfl_xor_sync(0xffffffffu, mx1, s));
    }
    float sm0 = 0.f, sm1 = 0.f;
#pragma unroll
    for (int nf = 0; nf < 8; nf++) {
        acc[nf][0] = expf(acc[nf][0] - mx0); sm0 += acc[nf][0];
        acc[nf][1] = expf(acc[nf][1] - mx0); sm0 += acc[nf][1];
        acc[nf][2] = expf(acc[nf][2] - mx1); sm1 += acc[nf][2];
        acc[nf][3] = expf(acc[nf][3] - mx1); sm1 += acc[nf][3];
    }
#pragma unroll
    for (int s = 1; s < 4; s <<= 1) {
        sm0 += __shfl_xor_sync(0xffffffffu, sm0, s);
        sm1 += __shfl_xor_sync(0xffffffffu, sm1, s);
    }
    float inv0 = 1.f / sm0, inv1 = 1.f / sm1;
    const int tg = lane & 3;
    size_t prow_lo = (size_t)(b * NP + p0 + pw + gr) * KK;
    size_t prow_hi = prow_lo + (size_t)8 * KK;
#pragma unroll
    for (int nf = 0; nf < 8; nf++) {
        int kc = nf * 8 + tg * 2;
        u32 h, l;
        split2(acc[nf][0] * inv0, acc[nf][1] * inv0, h, l);
        *(u32*)&g_zh[prow_lo + kc] = h;
        *(u32*)&g_zl[prow_lo + kc] = l;
        split2(acc[nf][2] * inv1, acc[nf][3] * inv1, h, l);
        *(u32*)&g_zh[prow_hi + kc] = h;
        *(u32*)&g_zl[prow_hi + kc] = l;
    }
}

// ---------------- km: mpart = xf @ z (split-K over p), HMMA ------------------
__global__ __launch_bounds__(256, 2)
void km_kernel()
{
    __shared__ __align__(16) u16 Ah[128 * 40], Al[128 * 40]; // (c128, p32)
    __shared__ __align__(16) u16 Zh[32 * 72],  Zl[32 * 72];  // (p32, k64)

    const int ct0 = blockIdx.x * 128;
    const int b   = blockIdx.y;
    const int s   = blockIdx.z;
    const int ps0 = s * (NP / NSPLIT);
    const int tid = threadIdx.x;
    const int lane = tid & 31, wid = tid >> 5;

    const u16* XH = g_xfh + (size_t)b * CC * NP;
    const u16* XL = g_xfl + (size_t)b * CC * NP;
    const u16* ZH = g_zh + (size_t)b * NP * KK;
    const u16* ZL = g_zl + (size_t)b * NP * KK;

    float acc[8][4];
#pragma unroll
    for (int nf = 0; nf < 8; nf++)
#pragma unroll
        for (int q = 0; q < 4; q++) acc[nf][q] = 0.f;

    const u32 sah = smem_u32(Ah), sal = smem_u32(Al);
    const u32 szh = smem_u32(Zh), szl = smem_u32(Zl);

    for (int pc0 = ps0; pc0 < ps0 + NP / NSPLIT; pc0 += 32) {
#pragma unroll
        for (int it = 0; it < 2; it++) {
            int lin = tid + it * 256;
            int r = lin >> 2, g = lin & 3;
            *(uint4*)&Ah[r * 40 + g * 8] =
                *(const uint4*)(XH + (size_t)(ct0 + r) * NP + pc0 + g * 8);
            *(uint4*)&Al[r * 40 + g * 8] =
                *(const uint4*)(XL + (size_t)(ct0 + r) * NP + pc0 + g * 8);
        }
        {
            int r = tid >> 3, g = tid & 7;
            *(uint4*)&Zh[r * 72 + g * 8] =
                *(const uint4*)(ZH + (size_t)(pc0 + r) * KK + g * 8);
            *(uint4*)&Zl[r * 72 + g * 8] =
                *(const uint4*)(ZL + (size_t)(pc0 + r) * KK + g * 8);
        }
        __syncthreads();
#pragma unroll
        for (int ks = 0; ks < 2; ks++) {
            u32 ah[4], al[4];
            {
                u32 off = (((wid * 16 + (lane & 15)) * 40 +
                            ks * 16 + (lane >> 4) * 8)) << 1;
                ldsm4(ah, sah + off);
                ldsm4(al, sal + off);
            }
            u32 bh[4][4], bl[4][4];
            {
                u32 row = ks * 16 + (lane & 7) + ((lane >> 3) & 1) * 8;
                u32 col = ((lane >> 4) & 1) * 8;
#pragma unroll
                for (int pr = 0; pr < 4; pr++) {
                    u32 off = (row * 72 + col + pr * 16) << 1;
                    ldsm4t(bh[pr], szh + off);
                    ldsm4t(bl[pr], szl + off);
                }
            }
#pragma unroll
            for (int nf = 0; nf < 8; nf++) {
                const u32* bhp = &bh[nf >> 1][(nf & 1) * 2];
                const u32* blp = &bl[nf >> 1][(nf & 1) * 2];
                mma_bf16(acc[nf], ah, bhp);
                mma_bf16(acc[nf], ah, blp);
                mma_bf16(acc[nf], al, bhp);
            }
        }
        __syncthreads();
    }

    const int gr = lane >> 2, tg = lane & 3;
    float* out = g_mpart + ((size_t)(s * BB + b) * CC + ct0 + wid * 16) * KK;
#pragma unroll
    for (int nf = 0; nf < 8; nf++) {
        int kc = nf * 8 + tg * 2;
        *(float2*)&out[(size_t)gr * KK + kc] =
            make_float2(acc[nf][0], acc[nf][1]);
        *(float2*)&out[(size_t)(gr + 8) * KK + kc] =
            make_float2(acc[nf][2], acc[nf][3]);
    }
}

// ---------------- norm phase 1 ------------------------------------------------
__global__ void knorm1()
{
    const int cs = blockIdx.x, b = blockIdx.y;
    __shared__ float red[256];
    const int tid = threadIdx.x;
    const size_t bc = ((size_t)b * CC + cs * 64) * KK;
    float ln = 0.f;
#pragma unroll
    for (int it = 0; it < 16; it++) {
        size_t off = bc + tid + it * 256;
        float v = 0.f;
#pragma unroll
        for (int s = 0; s < NSPLIT; s++)
            v += g_mpart[(size_t)s * (BB * CC * KK) + off];
        g_m[off] = v;
        ln += v * v;
    }
    red[tid] = ln;
    __syncthreads();
    if (tid < 64)
        g_norm2[(size_t)(cs * BB + b) * KK + tid] =
            red[tid] + red[tid + 64] + red[tid + 128] + red[tid + 192];
}

// ---------------- norm phase 2 ------------------------------------------------
__global__ void knorm2()
{
    const int cs = blockIdx.x, b = blockIdx.y;
    __shared__ float inv[64];
    const int tid = threadIdx.x;
    if (tid < 64) {
        float s = 0.f;
#pragma unroll
        for (int q = 0; q < 8; q++)
            s += g_norm2[(size_t)(q * BB + b) * KK + tid];
        inv[tid] = 1.f / (EPSF + sqrtf(s));
    }
    __syncthreads();
    const size_t bc = ((size_t)b * CC + cs * 64) * KK;
#pragma unroll
    for (int it = 0; it < 8; it++) {
        size_t off = bc + (tid + it * 256) * 2;
        float v0 = g_m[off] * inv[(2 * tid) & 63];
        float v1 = g_m[off + 1] * inv[(2 * tid + 1) & 63];
        u32 h, l;
        split2(v0, v1, h, l);
        *(u32*)&g_mh[off] = h;
        *(u32*)&g_ml[off] = l;
    }
}

// ---------------- krec: rec = relu(m @ z^T) -> hi/lo bf16 (c,p) --------------
__global__ __launch_bounds__(256, 2)
void krec_kernel()
{
    __shared__ __align__(16) u16 Ah[128 * 40], Al[128 * 40]; // (c128, k32)
    __shared__ __align__(16) u16 Bh[128 * 40], Bl[128 * 40]; // (p128, k32)

    const int p0  = blockIdx.x * 128;
    const int ct0 = blockIdx.y * 128;
    const int b   = blockIdx.z;
    const int tid = threadIdx.x;
    const int lane = tid & 31, wid = tid >> 5;
    const int wm = wid & 1, wn = wid >> 1;
    const int cb = wm * 64, pb = wn * 32;

    const u16* MH = g_mh + (size_t)b * CC * KK;
    const u16* ML = g_ml + (size_t)b * CC * KK;
    const u16* ZH = g_zh + (size_t)b * NP * KK;
    const u16* ZL = g_zl + (size_t)b * NP * KK;

    float acc[4][4][4];
#pragma unroll
    for (int mf = 0; mf < 4; mf++)
#pragma unroll
        for (int nf = 0; nf < 4; nf++)
#pragma unroll
            for (int q = 0; q < 4; q++) acc[mf][nf][q] = 0.f;

    const u32 sah = smem_u32(Ah), sal = smem_u32(Al);
    const u32 sbh = smem_u32(Bh), sbl = smem_u32(Bl);

    for (int kc0 = 0; kc0 < KK; kc0 += 32) {
#pragma unroll
        for (int it = 0; it < 2; it++) {
            int lin = tid + it * 256;
            int r = lin >> 2, g = lin & 3;
            *(uint4*)&Ah[r * 40 + g * 8] =
                *(const uint4*)(MH + (size_t)(ct0 + r) * KK + kc0 + g * 8);
            *(uint4*)&Al[r * 40 + g * 8] =
                *(const uint4*)(ML + (size_t)(ct0 + r) * KK + kc0 + g * 8);
        }
#pragma unroll
        for (int it = 0; it < 2; it++) {
            int lin = tid + it * 256;
            int r = lin >> 2, g = lin & 3;
            *(uint4*)&Bh[r * 40 + g * 8] =
                *(const uint4*)(ZH + (size_t)(p0 + r) * KK + kc0 + g * 8);
            *(uint4*)&Bl[r * 40 + g * 8] =
                *(const uint4*)(ZL + (size_t)(p0 + r) * KK + kc0 + g * 8);
        }
        __syncthreads();
#pragma unroll
        for (int ks = 0; ks < 2; ks++) {
            u32 ah[4][4], al[4][4];
            u32 a_off = (((cb + (lane & 15)) * 40 + ks * 16 + (lane >> 4) * 8)) << 1;
#pragma unroll
            for (int mf = 0; mf < 4; mf++) {
                ldsm4(ah[mf], sah + a_off + mf * (16 * 40 * 2));
                ldsm4(al[mf], sal + a_off + mf * (16 * 40 * 2));
            }
            u32 bh[2][4], bl[2][4];
            u32 brow = pb + ((lane >> 4) & 1) * 8 + (lane & 7);
            u32 bcol = ks * 16 + ((lane >> 3) & 1) * 8;
#pragma unroll
            for (int pr = 0; pr < 2; pr++) {
                u32 boff = ((brow + pr * 16) * 40 + bcol) << 1;
                ldsm4(bh[pr], sbh + boff);
                ldsm4(bl[pr], sbl + boff);
            }
#pragma unroll
            for (int mf = 0; mf < 4; mf++)
#pragma unroll
                for (int nf = 0; nf < 4; nf++) {
                    const u32* bhp = &bh[nf >> 1][(nf & 1) * 2];
                    const u32* blp = &bl[nf >> 1][(nf & 1) * 2];
                    mma_bf16(acc[mf][nf], ah[mf], bhp);
                    mma_bf16(acc[mf][nf], ah[mf], blp);
                    mma_bf16(acc[mf][nf], al[mf], bhp);
                }
        }
        __syncthreads();
    }

    const int g = lane >> 2, tg = lane & 3;
    u16* rh = g_rech + (size_t)b * CC * NP;
    u16* rl = g_recl + (size_t)b * CC * NP;
#pragma unroll
    for (int mf = 0; mf < 4; mf++) {
        int c_lo = ct0 + cb + mf * 16 + g;
        int c_hi = c_lo + 8;
#pragma unroll
        for (int nf = 0; nf < 4; nf++) {
            int pc = p0 + pb + nf * 8 + tg * 2;
            u32 h, l;
            split2(fmaxf(acc[mf][nf][0], 0.f), fmaxf(acc[mf][nf][1], 0.f), h, l);
            *(u32*)&rh[(size_t)c_lo * NP + pc] = h;
            *(u32*)&rl[(size_t)c_lo * NP + pc] = l;
            split2(fmaxf(acc[mf][nf][2], 0.f), fmaxf(acc[mf][nf][3], 0.f), h, l);
            *(u32*)&rh[(size_t)c_hi * NP + pc] = h;
            *(u32*)&rl[(size_t)c_hi * NP + pc] = l;
        }
    }
}

// ---------------- launch ----------------------------------------------------
extern "C" void kernel_launch(void* const* d_in, const int* in_sizes, int n_in,
                              void* d_out, int out_size)
{
    (void)in_sizes; (void)n_in; (void)out_size;
    const float* x     = (const float*)d_in[0];
    const float* w1    = (const float*)d_in[1];
    const float* b1    = (const float*)d_in[2];
    const float* mu    = (const float*)d_in[3];
    const float* w2    = (const float*)d_in[4];
    const float* gamma = (const float*)d_in[5];
    const float* beta  = (const float*)d_in[6];
    const float* mean  = (const float*)d_in[7];
    const float* var   = (const float*)d_in[8];
    float* out = (float*)d_out;

    kcvt_x<<<(int)(((size_t)BB * CC * NP) / 1024), 256>>>(x);
    kcvt_w<<<(CC * CC) / 512, 256>>>(w1, w2);
    kcvt_mu<<<(CC * KK) / 512, 256>>>(mu);

    hconv<0><<<dim3(NP / 128, CC / 128, BB), 128>>>(
        nullptr, b1, nullptr, nullptr, nullptr);

    for (int st = 0; st < 3; st++) {
        kz_kernel<<<dim3(NP / 128, BB), 256>>>(st > 0 ? 1 : 0);
        km_kernel<<<dim3(CC / 128, BB, NSPLIT), 256>>>();
        knorm1<<<dim3(8, BB), 256>>>();
        knorm2<<<dim3(8, BB), 256>>>();
    }

    krec_kernel<<<dim3(NP / 128, CC / 128, BB), 256>>>();

    hconv<1><<<dim3(NP / 128, CC / 128, BB), 128>>>(
        out, gamma, beta, mean, var);
}

// round 7
// speedup vs baseline: 2.1848x; 1.0409x over previous
#include <cuda_runtime.h>
#include <cuda_bf16.h>

#define CC 512
#define NP 4096
#define KK 64
#define BB 16
#define NSPLIT 4
#define EPSF 1e-6f

typedef unsigned long long u64;
typedef unsigned int u32;
typedef unsigned short u16;

// ---------------- scratch (static device globals) ---------------------------
__device__ u16 g_xh[(size_t)BB * CC * NP];   // x hi   (b,c,p)
__device__ u16 g_xl[(size_t)BB * CC * NP];   // x lo
__device__ u16 g_wh1[(size_t)CC * CC], g_wl1[(size_t)CC * CC];
__device__ u16 g_wh2[(size_t)CC * CC], g_wl2[(size_t)CC * CC];
__device__ u16 g_muh[(size_t)CC * KK], g_mul[(size_t)CC * KK];
__device__ u16 g_xfh[(size_t)BB * CC * NP];  // conv1 out hi (b,c,p)
__device__ u16 g_xfl[(size_t)BB * CC * NP];
__device__ u16 g_zh[(size_t)BB * NP * KK];   // z hi (b,p,k)
__device__ u16 g_zl[(size_t)BB * NP * KK];
__device__ u16 g_mh[(size_t)BB * CC * KK];   // m hi (b,c,k)
__device__ u16 g_ml[(size_t)BB * CC * KK];
__device__ u16 g_rech[(size_t)BB * CC * NP]; // relu(rec) hi (b,c,p)
__device__ u16 g_recl[(size_t)BB * CC * NP];
__device__ float g_mpart[(size_t)NSPLIT * BB * CC * KK];
__device__ float g_m[(size_t)BB * CC * KK];
__device__ float g_norm2[(size_t)8 * BB * KK];

// ---------------- helpers ----------------------------------------------------
__device__ __forceinline__ u32 smem_u32(const void* p) {
    u32 a;
    asm("{ .reg .u64 t; cvta.to.shared.u64 t, %1; cvt.u32.u64 %0, t; }"
        : "=r"(a) : "l"(p));
    return a;
}
__device__ __forceinline__ void ldsm4(u32* r, u32 addr) {
    asm volatile("ldmatrix.sync.aligned.m8n8.x4.shared.b16 {%0,%1,%2,%3}, [%4];"
                 : "=r"(r[0]), "=r"(r[1]), "=r"(r[2]), "=r"(r[3]) : "r"(addr));
}
__device__ __forceinline__ void ldsm4t(u32* r, u32 addr) {
    asm volatile("ldmatrix.sync.aligned.m8n8.x4.trans.shared.b16 {%0,%1,%2,%3}, [%4];"
                 : "=r"(r[0]), "=r"(r[1]), "=r"(r[2]), "=r"(r[3]) : "r"(addr));
}
__device__ __forceinline__ void mma_bf16(float* d, const u32* a, const u32* b) {
    asm volatile(
        "mma.sync.aligned.m16n8k16.row.col.f32.bf16.bf16.f32 "
        "{%0,%1,%2,%3}, {%4,%5,%6,%7}, {%8,%9}, {%0,%1,%2,%3};"
        : "+f"(d[0]), "+f"(d[1]), "+f"(d[2]), "+f"(d[3])
        : "r"(a[0]), "r"(a[1]), "r"(a[2]), "r"(a[3]), "r"(b[0]), "r"(b[1]));
}
__device__ __forceinline__ void split2(float v0, float v1, u32& hi, u32& lo) {
    __nv_bfloat16 h0 = __float2bfloat16_rn(v0);
    __nv_bfloat16 h1 = __float2bfloat16_rn(v1);
    __nv_bfloat16 l0 = __float2bfloat16_rn(v0 - __bfloat162float(h0));
    __nv_bfloat16 l1 = __float2bfloat16_rn(v1 - __bfloat162float(h1));
    hi = (u32)__bfloat16_as_ushort(h0) | ((u32)__bfloat16_as_ushort(h1) << 16);
    lo = (u32)__bfloat16_as_ushort(l0) | ((u32)__bfloat16_as_ushort(l1) << 16);
}
__device__ __forceinline__ void cpa16(u32 dst, const void* src) {
    asm volatile("cp.async.cg.shared.global [%0], [%1], 16;"
                 :: "r"(dst), "l"(src));
}
#define CPA_COMMIT() asm volatile("cp.async.commit_group;")
#define CPA_WAIT(n)  asm volatile("cp.async.wait_group %0;" :: "n"(n))

// ---------------- convert kernels -------------------------------------------
__global__ void kcvt_x(const float* __restrict__ x)
{
    size_t i4 = ((size_t)blockIdx.x * 256 + threadIdx.x) * 4;
    float4 v = *(const float4*)&x[i4];
    u32 h0, l0, h1, l1;
    split2(v.x, v.y, h0, l0);
    split2(v.z, v.w, h1, l1);
    *(uint2*)&g_xh[i4] = make_uint2(h0, h1);
    *(uint2*)&g_xl[i4] = make_uint2(l0, l1);
}
__global__ void kcvt_w(const float* __restrict__ w1, const float* __restrict__ w2)
{
    size_t i2 = ((size_t)blockIdx.x * 256 + threadIdx.x) * 2;
    {
        u32 h, l;
        split2(w1[i2], w1[i2 + 1], h, l);
        *(u32*)&g_wh1[i2] = h; *(u32*)&g_wl1[i2] = l;
    }
    {
        u32 h, l;
        split2(w2[i2], w2[i2 + 1], h, l);
        *(u32*)&g_wh2[i2] = h; *(u32*)&g_wl2[i2] = l;
    }
}
__global__ void kcvt_mu(const float* __restrict__ mu)
{
    size_t i2 = ((size_t)blockIdx.x * 256 + threadIdx.x) * 2;
    u32 h, l;
    split2(mu[i2], mu[i2 + 1], h, l);
    *(u32*)&g_muh[i2] = h; *(u32*)&g_mul[i2] = l;
}

// ---------------- conv GEMM v3: 3-stage cp.async, K-chunk 32, 1 sync/chunk --
// D[o,p] = sum_c W[o,c]*IN[c,p] + epi
#define APITCH 40
#define BPITCH 136
#define AH_OFF 0
#define AL_OFF 10240
#define BH_OFF 20480
#define BL_OFF 29184
#define STAGE_B 37888
#define NSTAGE 3
#define NCH 16
#define HCONV_SMEM (STAGE_B * NSTAGE)

template <int EPI>
__global__ __launch_bounds__(128, 2)
void hconv(float* __restrict__ OUT,
           const float* __restrict__ e0, const float* __restrict__ e1,
           const float* __restrict__ e2, const float* __restrict__ e3)
{
    extern __shared__ __align__(16) char dsm[];
    const u32 sb = smem_u32(dsm);

    const int p0 = blockIdx.x * 128;
    const int o0 = blockIdx.y * 128;
    const int b  = blockIdx.z;
    const int tid = threadIdx.x;
    const int lane = tid & 31, wid = tid >> 5;
    const int ob = (wid & 1) * 64, pb = (wid >> 1) * 64;

    const u16* WH = (EPI == 0) ? g_wh1 : g_wh2;
    const u16* WL = (EPI == 0) ? g_wl1 : g_wl2;
    const u16* IH = ((EPI == 0) ? g_xh : g_rech) + (size_t)b * CC * NP;
    const u16* IL = ((EPI == 0) ? g_xl : g_recl) + (size_t)b * CC * NP;

    float acc[4][8][4];
#pragma unroll
    for (int mf = 0; mf < 4; mf++)
#pragma unroll
        for (int nf = 0; nf < 8; nf++)
#pragma unroll
            for (int q = 0; q < 4; q++) acc[mf][nf][q] = 0.f;

    // per-thread load coords: A 128x32 (4 u16x8 per row), B 32x128
    const int arow = tid >> 2, au = (tid & 3) * 8;          // A: lin=tid (+128*i)
    const int brow = tid >> 4, bu = (tid & 15) * 8;

#define LOAD_CHUNK(st, c0)                                                      \
    do {                                                                        \
        u32 base = sb + (st) * STAGE_B;                                         \
        _Pragma("unroll")                                                       \
        for (int i = 0; i < 4; i++) {                                           \
            int r = arow + i * 32;                                              \
            cpa16(base + AH_OFF + (r * APITCH + au) * 2,                        \
                  WH + (size_t)(o0 + r) * CC + (c0) + au);                      \
            cpa16(base + AL_OFF + (r * APITCH + au) * 2,                        \
                  WL + (size_t)(o0 + r) * CC + (c0) + au);                      \
        }                                                                       \
        _Pragma("unroll")                                                       \
        for (int i = 0; i < 4; i++) {                                           \
            int r = brow + i * 8;                                               \
            cpa16(base + BH_OFF + (r * BPITCH + bu) * 2,                        \
                  IH + (size_t)((c0) + r) * NP + p0 + bu);                      \
            cpa16(base + BL_OFF + (r * BPITCH + bu) * 2,                        \
                  IL + (size_t)((c0) + r) * NP + p0 + bu);                      \
        }                                                                       \
        CPA_COMMIT();                                                           \
    } while (0)

    LOAD_CHUNK(0, 0);
    LOAD_CHUNK(1, 32);

    const u32 a_lane = ((ob + (lane & 15)) * APITCH + (lane >> 4) * 8) * 2;
    const u32 b_rbase = (lane & 7) + ((lane >> 3) & 1) * 8;
    const u32 b_col   = pb + ((lane >> 4) & 1) * 8;

    for (int ch = 0; ch < NCH; ch++) {
        if (ch < NCH - 1) { CPA_WAIT(1); } else { CPA_WAIT(0); }
        __syncthreads();
        if (ch < NCH - 2) LOAD_CHUNK((ch + 2) % NSTAGE, (ch + 2) * 32);

        const u32 stb = sb + (ch % NSTAGE) * STAGE_B;
#pragma unroll
        for (int ks = 0; ks < 2; ks++) {
            u32 ah[4][4], al[4][4];
            const u32 abase = stb + a_lane + ks * 32;
#pragma unroll
            for (int mf = 0; mf < 4; mf++) {
                ldsm4(ah[mf], abase + AH_OFF + mf * (16 * APITCH * 2));
                ldsm4(al[mf], abase + AL_OFF + mf * (16 * APITCH * 2));
            }
            const u32 brow = ks * 16 + b_rbase;
            const u32 bbase = stb + (brow * BPITCH + b_col) * 2;
#pragma unroll
            for (int pr = 0; pr < 4; pr++) {
                u32 bh[4], bl[4];
                ldsm4t(bh, bbase + BH_OFF + pr * 32);
                ldsm4t(bl, bbase + BL_OFF + pr * 32);
#pragma unroll
                for (int mf = 0; mf < 4; mf++) {
#pragma unroll
                    for (int hn = 0; hn < 2; hn++) {
                        float* a = acc[mf][pr * 2 + hn];
                        mma_bf16(a, ah[mf], &bh[hn * 2]);
                        mma_bf16(a, ah[mf], &bl[hn * 2]);
                        mma_bf16(a, al[mf], &bh[hn * 2]);
                    }
                }
            }
        }
    }

    const int g = lane >> 2, tg = lane & 3;
#pragma unroll
    for (int mf = 0; mf < 4; mf++) {
        int o_lo = o0 + ob + mf * 16 + g;
        int o_hi = o_lo + 8;
        if (EPI == 0) {
            float add_lo = e0[o_lo], add_hi = e0[o_hi];
            u16* xfh = g_xfh + (size_t)b * CC * NP;
            u16* xfl = g_xfl + (size_t)b * CC * NP;
#pragma unroll
            for (int nf = 0; nf < 8; nf++) {
                int pc = p0 + pb + nf * 8 + tg * 2;
                u32 h, l;
                split2(acc[mf][nf][0] + add_lo, acc[mf][nf][1] + add_lo, h, l);
                *(u32*)&xfh[(size_t)o_lo * NP + pc] = h;
                *(u32*)&xfl[(size_t)o_lo * NP + pc] = l;
                split2(acc[mf][nf][2] + add_hi, acc[mf][nf][3] + add_hi, h, l);
                *(u32*)&xfh[(size_t)o_hi * NP + pc] = h;
                *(u32*)&xfl[(size_t)o_hi * NP + pc] = l;
            }
        } else {
            float mul_lo = e0[o_lo] * rsqrtf(e3[o_lo] + 1e-5f);
            float add_lo = e1[o_lo] - e2[o_lo] * mul_lo;
            float mul_hi = e0[o_hi] * rsqrtf(e3[o_hi] + 1e-5f);
            float add_hi = e1[o_hi] - e2[o_hi] * mul_hi;
            float* outb = OUT + (size_t)b * CC * NP;
#pragma unroll
            for (int nf = 0; nf < 8; nf++) {
                int pc = p0 + pb + nf * 8 + tg * 2;
                float2 v0, v1;
                v0.x = acc[mf][nf][0] * mul_lo + add_lo;
                v0.y = acc[mf][nf][1] * mul_lo + add_lo;
                v1.x = acc[mf][nf][2] * mul_hi + add_hi;
                v1.y = acc[mf][nf][3] * mul_hi + add_hi;
                *(float2*)&outb[(size_t)o_lo * NP + pc] = v0;
                *(float2*)&outb[(size_t)o_hi * NP + pc] = v1;
            }
        }
    }
#undef LOAD_CHUNK
}

// ---------------- kz: z = softmax_k( xf^T @ m ), HMMA ------------------------
__global__ __launch_bounds__(256, 2)
void kz_kernel(int use_gm)
{
    __shared__ __align__(16) u16 Xh[32 * 136], Xl[32 * 136]; // (c32, p128)
    __shared__ __align__(16) u16 Mh[32 * 72],  Ml[32 * 72];  // (c32, k64)

    const int p0 = blockIdx.x * 128;
    const int b  = blockIdx.y;
    const int tid = threadIdx.x;
    const int lane = tid & 31, wid = tid >> 5;
    const int pw = wid * 16;

    const u16* XH = g_xfh + (size_t)b * CC * NP;
    const u16* XL = g_xfl + (size_t)b * CC * NP;
    const u16* MH = use_gm ? (g_mh + (size_t)b * CC * KK) : g_muh;
    const u16* ML = use_gm ? (g_ml + (size_t)b * CC * KK) : g_mul;

    float acc[8][4];
#pragma unroll
    for (int nf = 0; nf < 8; nf++)
#pragma unroll
        for (int q = 0; q < 4; q++) acc[nf][q] = 0.f;

    const u32 sxh = smem_u32(Xh), sxl = smem_u32(Xl);
    const u32 smh = smem_u32(Mh), sml = smem_u32(Ml);

    for (int c0 = 0; c0 < CC; c0 += 32) {
#pragma unroll
        for (int it = 0; it < 2; it++) {
            int lin = tid + it * 256;
            int r = lin >> 4, g = lin & 15;
            *(uint4*)&Xh[r * 136 + g * 8] =
                *(const uint4*)(XH + (size_t)(c0 + r) * NP + p0 + g * 8);
            *(uint4*)&Xl[r * 136 + g * 8] =
                *(const uint4*)(XL + (size_t)(c0 + r) * NP + p0 + g * 8);
        }
        {
            int r = tid >> 3, g = tid & 7;
            *(uint4*)&Mh[r * 72 + g * 8] =
                *(const uint4*)(MH + (size_t)(c0 + r) * KK + g * 8);
            *(uint4*)&Ml[r * 72 + g * 8] =
                *(const uint4*)(ML + (size_t)(c0 + r) * KK + g * 8);
        }
        __syncthreads();
#pragma unroll
        for (int ks = 0; ks < 2; ks++) {
            u32 ah[4], al[4];
            {
                u32 row = ks * 16 + (lane & 7) + ((lane >> 4) & 1) * 8;
                u32 col = pw + ((lane >> 3) & 1) * 8;
                u32 off = (row * 136 + col) << 1;
                ldsm4t(ah, sxh + off);
                ldsm4t(al, sxl + off);
            }
            u32 bh[4][4], bl[4][4];
            {
                u32 row = ks * 16 + (lane & 7) + ((lane >> 3) & 1) * 8;
                u32 col = ((lane >> 4) & 1) * 8;
#pragma unroll
                for (int pr = 0; pr < 4; pr++) {
                    u32 off = (row * 72 + col + pr * 16) << 1;
                    ldsm4t(bh[pr], smh + off);
                    ldsm4t(bl[pr], sml + off);
                }
            }
#pragma unroll
            for (int nf = 0; nf < 8; nf++) {
                const u32* bhp = &bh[nf >> 1][(nf & 1) * 2];
                const u32* blp = &bl[nf >> 1][(nf & 1) * 2];
                mma_bf16(acc[nf], ah, bhp);
                mma_bf16(acc[nf], ah, blp);
                mma_bf16(acc[nf], al, bhp);
            }
        }
        __syncthreads();
    }

    const int gr = lane >> 2;
    float mx0 = -1e30f, mx1 = -1e30f;
#pragma unroll
    for (int nf = 0; nf < 8; nf++) {
        mx0 = fmaxf(mx0, fmaxf(acc[nf][0], acc[nf][1]));
        mx1 = fmaxf(mx1, fmaxf(acc[nf][2], acc[nf][3]));
    }
#pragma unroll
    for (int s = 1; s < 4; s <<= 1) {
        mx0 = fmaxf(mx0, __shfl_xor_sync(0xffffffffu, mx0, s));
        mx1 = fmaxf(mx1, __shfl_xor_sync(0xffffffffu, mx1, s));
    }
    float sm0 = 0.f, sm1 = 0.f;
#pragma unroll
    for (int nf = 0; nf < 8; nf++) {
        acc[nf][0] = expf(acc[nf][0] - mx0); sm0 += acc[nf][0];
        acc[nf][1] = expf(acc[nf][1] - mx0); sm0 += acc[nf][1];
        acc[nf][2] = expf(acc[nf][2] - mx1); sm1 += acc[nf][2];
        acc[nf][3] = expf(acc[nf][3] - mx1); sm1 += acc[nf][3];
    }
#pragma unroll
    for (int s = 1; s < 4; s <<= 1) {
        sm0 += __shfl_xor_sync(0xffffffffu, sm0, s);
        sm1 += __shfl_xor_sync(0xffffffffu, sm1, s);
    }
    float inv0 = 1.f / sm0, inv1 = 1.f / sm1;
    const int tg = lane & 3;
    size_t prow_lo = (size_t)(b * NP + p0 + pw + gr) * KK;
    size_t prow_hi = prow_lo + (size_t)8 * KK;
#pragma unroll
    for (int nf = 0; nf < 8; nf++) {
        int kc = nf * 8 + tg * 2;
        u32 h, l;
        split2(acc[nf][0] * inv0, acc[nf][1] * inv0, h, l);
        *(u32*)&g_zh[prow_lo + kc] = h;
        *(u32*)&g_zl[prow_lo + kc] = l;
        split2(acc[nf][2] * inv1, acc[nf][3] * inv1, h, l);
        *(u32*)&g_zh[prow_hi + kc] = h;
        *(u32*)&g_zl[prow_hi + kc] = l;
    }
}

// ---------------- km: mpart = xf @ z (split-K over p), HMMA ------------------
__global__ __launch_bounds__(256, 2)
void km_kernel()
{
    __shared__ __align__(16) u16 Ah[128 * 40], Al[128 * 40]; // (c128, p32)
    __shared__ __align__(16) u16 Zh[32 * 72],  Zl[32 * 72];  // (p32, k64)

    const int ct0 = blockIdx.x * 128;
    const int b   = blockIdx.y;
    const int s   = blockIdx.z;
    const int ps0 = s * (NP / NSPLIT);
    const int tid = threadIdx.x;
    const int lane = tid & 31, wid = tid >> 5;

    const u16* XH = g_xfh + (size_t)b * CC * NP;
    const u16* XL = g_xfl + (size_t)b * CC * NP;
    const u16* ZH = g_zh + (size_t)b * NP * KK;
    const u16* ZL = g_zl + (size_t)b * NP * KK;

    float acc[8][4];
#pragma unroll
    for (int nf = 0; nf < 8; nf++)
#pragma unroll
        for (int q = 0; q < 4; q++) acc[nf][q] = 0.f;

    const u32 sah = smem_u32(Ah), sal = smem_u32(Al);
    const u32 szh = smem_u32(Zh), szl = smem_u32(Zl);

    for (int pc0 = ps0; pc0 < ps0 + NP / NSPLIT; pc0 += 32) {
#pragma unroll
        for (int it = 0; it < 2; it++) {
            int lin = tid + it * 256;
            int r = lin >> 2, g = lin & 3;
            *(uint4*)&Ah[r * 40 + g * 8] =
                *(const uint4*)(XH + (size_t)(ct0 + r) * NP + pc0 + g * 8);
            *(uint4*)&Al[r * 40 + g * 8] =
                *(const uint4*)(XL + (size_t)(ct0 + r) * NP + pc0 + g * 8);
        }
        {
            int r = tid >> 3, g = tid & 7;
            *(uint4*)&Zh[r * 72 + g * 8] =
                *(const uint4*)(ZH + (size_t)(pc0 + r) * KK + g * 8);
            *(uint4*)&Zl[r * 72 + g * 8] =
                *(const uint4*)(ZL + (size_t)(pc0 + r) * KK + g * 8);
        }
        __syncthreads();
#pragma unroll
        for (int ks = 0; ks < 2; ks++) {
            u32 ah[4], al[4];
            {
                u32 off = (((wid * 16 + (lane & 15)) * 40 +
                            ks * 16 + (lane >> 4) * 8)) << 1;
                ldsm4(ah, sah + off);
                ldsm4(al, sal + off);
            }
            u32 bh[4][4], bl[4][4];
            {
                u32 row = ks * 16 + (lane & 7) + ((lane >> 3) & 1) * 8;
                u32 col = ((lane >> 4) & 1) * 8;
#pragma unroll
                for (int pr = 0; pr < 4; pr++) {
                    u32 off = (row * 72 + col + pr * 16) << 1;
                    ldsm4t(bh[pr], szh + off);
                    ldsm4t(bl[pr], szl + off);
                }
            }
#pragma unroll
            for (int nf = 0; nf < 8; nf++) {
                const u32* bhp = &bh[nf >> 1][(nf & 1) * 2];
                const u32* blp = &bl[nf >> 1][(nf & 1) * 2];
                mma_bf16(acc[nf], ah, bhp);
                mma_bf16(acc[nf], ah, blp);
                mma_bf16(acc[nf], al, bhp);
            }
        }
        __syncthreads();
    }

    const int gr = lane >> 2, tg = lane & 3;
    float* out = g_mpart + ((size_t)(s * BB + b) * CC + ct0 + wid * 16) * KK;
#pragma unroll
    for (int nf = 0; nf < 8; nf++) {
        int kc = nf * 8 + tg * 2;
        *(float2*)&out[(size_t)gr * KK + kc] =
            make_float2(acc[nf][0], acc[nf][1]);
        *(float2*)&out[(size_t)(gr + 8) * KK + kc] =
            make_float2(acc[nf][2], acc[nf][3]);
    }
}

// ---------------- norm phase 1 ------------------------------------------------
__global__ void knorm1()
{
    const int cs = blockIdx.x, b = blockIdx.y;
    __shared__ float red[256];
    const int tid = threadIdx.x;
    const size_t bc = ((size_t)b * CC + cs * 64) * KK;
    float ln = 0.f;
#pragma unroll
    for (int it = 0; it < 16; it++) {
        size_t off = bc + tid + it * 256;
        float v = 0.f;
#pragma unroll
        for (int s = 0; s < NSPLIT; s++)
            v += g_mpart[(size_t)s * (BB * CC * KK) + off];
        g_m[off] = v;
        ln += v * v;
    }
    red[tid] = ln;
    __syncthreads();
    if (tid < 64)
        g_norm2[(size_t)(cs * BB + b) * KK + tid] =
            red[tid] + red[tid + 64] + red[tid + 128] + red[tid + 192];
}

// ---------------- norm phase 2 ------------------------------------------------
__global__ void knorm2()
{
    const int cs = blockIdx.x, b = blockIdx.y;
    __shared__ float inv[64];
    const int tid = threadIdx.x;
    if (tid < 64) {
        float s = 0.f;
#pragma unroll
        for (int q = 0; q < 8; q++)
            s += g_norm2[(size_t)(q * BB + b) * KK + tid];
        inv[tid] = 1.f / (EPSF + sqrtf(s));
    }
    __syncthreads();
    const size_t bc = ((size_t)b * CC + cs * 64) * KK;
#pragma unroll
    for (int it = 0; it < 8; it++) {
        size_t off = bc + (tid + it * 256) * 2;
        float v0 = g_m[off] * inv[(2 * tid) & 63];
        float v1 = g_m[off + 1] * inv[(2 * tid + 1) & 63];
        u32 h, l;
        split2(v0, v1, h, l);
        *(u32*)&g_mh[off] = h;
        *(u32*)&g_ml[off] = l;
    }
}

// ---------------- krec: rec = relu(m @ z^T) -> hi/lo bf16 (c,p) --------------
__global__ __launch_bounds__(256, 2)
void krec_kernel()
{
    __shared__ __align__(16) u16 Ah[128 * 40], Al[128 * 40]; // (c128, k32)
    __shared__ __align__(16) u16 Bh[128 * 40], Bl[128 * 40]; // (p128, k32)

    const int p0  = blockIdx.x * 128;
    const int ct0 = blockIdx.y * 128;
    const int b   = blockIdx.z;
    const int tid = threadIdx.x;
    const int lane = tid & 31, wid = tid >> 5;
    const int wm = wid & 1, wn = wid >> 1;
    const int cb = wm * 64, pb = wn * 32;

    const u16* MH = g_mh + (size_t)b * CC * KK;
    const u16* ML = g_ml + (size_t)b * CC * KK;
    const u16* ZH = g_zh + (size_t)b * NP * KK;
    const u16* ZL = g_zl + (size_t)b * NP * KK;

    float acc[4][4][4];
#pragma unroll
    for (int mf = 0; mf < 4; mf++)
#pragma unroll
        for (int nf = 0; nf < 4; nf++)
#pragma unroll
            for (int q = 0; q < 4; q++) acc[mf][nf][q] = 0.f;

    const u32 sah = smem_u32(Ah), sal = smem_u32(Al);
    const u32 sbh = smem_u32(Bh), sbl = smem_u32(Bl);

    for (int kc0 = 0; kc0 < KK; kc0 += 32) {
#pragma unroll
        for (int it = 0; it < 2; it++) {
            int lin = tid + it * 256;
            int r = lin >> 2, g = lin & 3;
            *(uint4*)&Ah[r * 40 + g * 8] =
                *(const uint4*)(MH + (size_t)(ct0 + r) * KK + kc0 + g * 8);
            *(uint4*)&Al[r * 40 + g * 8] =
                *(const uint4*)(ML + (size_t)(ct0 + r) * KK + kc0 + g * 8);
        }
#pragma unroll
        for (int it = 0; it < 2; it++) {
            int lin = tid + it * 256;
            int r = lin >> 2, g = lin & 3;
            *(uint4*)&Bh[r * 40 + g * 8] =
                *(const uint4*)(ZH + (size_t)(p0 + r) * KK + kc0 + g * 8);
            *(uint4*)&Bl[r * 40 + g * 8] =
                *(const uint4*)(ZL + (size_t)(p0 + r) * KK + kc0 + g * 8);
        }
        __syncthreads();
#pragma unroll
        for (int ks = 0; ks < 2; ks++) {
            u32 ah[4][4], al[4][4];
            u32 a_off = (((cb + (lane & 15)) * 40 + ks * 16 + (lane >> 4) * 8)) << 1;
#pragma unroll
            for (int mf = 0; mf < 4; mf++) {
                ldsm4(ah[mf], sah + a_off + mf * (16 * 40 * 2));
                ldsm4(al[mf], sal + a_off + mf * (16 * 40 * 2));
            }
            u32 bh[2][4], bl[2][4];
            u32 brow = pb + ((lane >> 4) & 1) * 8 + (lane & 7);
            u32 bcol = ks * 16 + ((lane >> 3) & 1) * 8;
#pragma unroll
            for (int pr = 0; pr < 2; pr++) {
                u32 boff = ((brow + pr * 16) * 40 + bcol) << 1;
                ldsm4(bh[pr], sbh + boff);
                ldsm4(bl[pr], sbl + boff);
            }
#pragma unroll
            for (int mf = 0; mf < 4; mf++)
#pragma unroll
                for (int nf = 0; nf < 4; nf++) {
                    const u32* bhp = &bh[nf >> 1][(nf & 1) * 2];
                    const u32* blp = &bl[nf >> 1][(nf & 1) * 2];
                    mma_bf16(acc[mf][nf], ah[mf], bhp);
                    mma_bf16(acc[mf][nf], ah[mf], blp);
                    mma_bf16(acc[mf][nf], al[mf], bhp);
                }
        }
        __syncthreads();
    }

    const int g = lane >> 2, tg = lane & 3;
    u16* rh = g_rech + (size_t)b * CC * NP;
    u16* rl = g_recl + (size_t)b * CC * NP;
#pragma unroll
    for (int mf = 0; mf < 4; mf++) {
        int c_lo = ct0 + cb + mf * 16 + g;
        int c_hi = c_lo + 8;
#pragma unroll
        for (int nf = 0; nf < 4; nf++) {
            int pc = p0 + pb + nf * 8 + tg * 2;
            u32 h, l;
            split2(fmaxf(acc[mf][nf][0], 0.f), fmaxf(acc[mf][nf][1], 0.f), h, l);
            *(u32*)&rh[(size_t)c_lo * NP + pc] = h;
            *(u32*)&rl[(size_t)c_lo * NP + pc] = l;
            split2(fmaxf(acc[mf][nf][2], 0.f), fmaxf(acc[mf][nf][3], 0.f), h, l);
            *(u32*)&rh[(size_t)c_hi * NP + pc] = h;
            *(u32*)&rl[(size_t)c_hi * NP + pc] = l;
        }
    }
}

// ---------------- launch ----------------------------------------------------
extern "C" void kernel_launch(void* const* d_in, const int* in_sizes, int n_in,
                              void* d_out, int out_size)
{
    (void)in_sizes; (void)n_in; (void)out_size;
    const float* x     = (const float*)d_in[0];
    const float* w1    = (const float*)d_in[1];
    const float* b1    = (const float*)d_in[2];
    const float* mu    = (const float*)d_in[3];
    const float* w2    = (const float*)d_in[4];
    const float* gamma = (const float*)d_in[5];
    const float* beta  = (const float*)d_in[6];
    const float* mean  = (const float*)d_in[7];
    const float* var   = (const float*)d_in[8];
    float* out = (float*)d_out;

    cudaFuncSetAttribute(hconv<0>, cudaFuncAttributeMaxDynamicSharedMemorySize,
                         HCONV_SMEM);
    cudaFuncSetAttribute(hconv<1>, cudaFuncAttributeMaxDynamicSharedMemorySize,
                         HCONV_SMEM);

    kcvt_x<<<(int)(((size_t)BB * CC * NP) / 1024), 256>>>(x);
    kcvt_w<<<(CC * CC) / 512, 256>>>(w1, w2);
    kcvt_mu<<<(CC * KK) / 512, 256>>>(mu);

    hconv<0><<<dim3(NP / 128, CC / 128, BB), 128, HCONV_SMEM>>>(
        nullptr, b1, nullptr, nullptr, nullptr);

    for (int st = 0; st < 3; st++) {
        kz_kernel<<<dim3(NP / 128, BB), 256>>>(st > 0 ? 1 : 0);
        km_kernel<<<dim3(CC / 128, BB, NSPLIT), 256>>>();
        knorm1<<<dim3(8, BB), 256>>>();
        knorm2<<<dim3(8, BB), 256>>>();
    }

    krec_kernel<<<dim3(NP / 128, CC / 128, BB), 256>>>();

    hconv<1><<<dim3(NP / 128, CC / 128, BB), 128, HCONV_SMEM>>>(
        out, gamma, beta, mean, var);
}

// round 8
// speedup vs baseline: 2.5996x; 1.1898x over previous
#include <cuda_runtime.h>
#include <cuda_bf16.h>
#include <cuda_fp16.h>

#define CC 512
#define NP 4096
#define KK 64
#define BB 16
#define NSPLIT 4
#define EPSF 1e-6f

typedef unsigned long long u64;
typedef unsigned int u32;
typedef unsigned short u16;

// ---------------- scratch (static device globals) ---------------------------
__device__ u16 g_xh[(size_t)BB * CC * NP];   // x hi fp16 (b,c,p)
__device__ u16 g_xl[(size_t)BB * CC * NP];   // x lo fp16
__device__ u16 g_wf1[(size_t)CC * CC];       // w1 fp16 single
__device__ u16 g_wf2[(size_t)CC * CC];       // w2 fp16 single
__device__ u16 g_muh[(size_t)CC * KK], g_mul[(size_t)CC * KK];   // bf16
__device__ u16 g_xfh[(size_t)BB * CC * NP];  // conv1 out hi bf16 (b,c,p)
__device__ u16 g_xfl[(size_t)BB * CC * NP];
__device__ u16 g_zh[(size_t)BB * NP * KK];   // z hi bf16 (b,p,k)
__device__ u16 g_zl[(size_t)BB * NP * KK];
__device__ u16 g_mh[(size_t)BB * CC * KK];   // m hi bf16 (b,c,k)
__device__ u16 g_ml[(size_t)BB * CC * KK];
__device__ u16 g_rech[(size_t)BB * CC * NP]; // relu(rec) hi fp16 (b,c,p)
__device__ u16 g_recl[(size_t)BB * CC * NP]; // relu(rec) lo fp16
__device__ float g_mpart[(size_t)NSPLIT * BB * CC * KK];
__device__ float g_m[(size_t)BB * CC * KK];
__device__ float g_norm2[(size_t)8 * BB * KK];

// ---------------- helpers ----------------------------------------------------
__device__ __forceinline__ u32 smem_u32(const void* p) {
    u32 a;
    asm("{ .reg .u64 t; cvta.to.shared.u64 t, %1; cvt.u32.u64 %0, t; }"
        : "=r"(a) : "l"(p));
    return a;
}
__device__ __forceinline__ void ldsm4(u32* r, u32 addr) {
    asm volatile("ldmatrix.sync.aligned.m8n8.x4.shared.b16 {%0,%1,%2,%3}, [%4];"
                 : "=r"(r[0]), "=r"(r[1]), "=r"(r[2]), "=r"(r[3]) : "r"(addr));
}
__device__ __forceinline__ void ldsm4t(u32* r, u32 addr) {
    asm volatile("ldmatrix.sync.aligned.m8n8.x4.trans.shared.b16 {%0,%1,%2,%3}, [%4];"
                 : "=r"(r[0]), "=r"(r[1]), "=r"(r[2]), "=r"(r[3]) : "r"(addr));
}
__device__ __forceinline__ void mma_bf16(float* d, const u32* a, const u32* b) {
    asm volatile(
        "mma.sync.aligned.m16n8k16.row.col.f32.bf16.bf16.f32 "
        "{%0,%1,%2,%3}, {%4,%5,%6,%7}, {%8,%9}, {%0,%1,%2,%3};"
        : "+f"(d[0]), "+f"(d[1]), "+f"(d[2]), "+f"(d[3])
        : "r"(a[0]), "r"(a[1]), "r"(a[2]), "r"(a[3]), "r"(b[0]), "r"(b[1]));
}
__device__ __forceinline__ void mma_fp16(float* d, const u32* a, const u32* b) {
    asm volatile(
        "mma.sync.aligned.m16n8k16.row.col.f32.f16.f16.f32 "
        "{%0,%1,%2,%3}, {%4,%5,%6,%7}, {%8,%9}, {%0,%1,%2,%3};"
        : "+f"(d[0]), "+f"(d[1]), "+f"(d[2]), "+f"(d[3])
        : "r"(a[0]), "r"(a[1]), "r"(a[2]), "r"(a[3]), "r"(b[0]), "r"(b[1]));
}
__device__ __forceinline__ void split2(float v0, float v1, u32& hi, u32& lo) {
    __nv_bfloat16 h0 = __float2bfloat16_rn(v0);
    __nv_bfloat16 h1 = __float2bfloat16_rn(v1);
    __nv_bfloat16 l0 = __float2bfloat16_rn(v0 - __bfloat162float(h0));
    __nv_bfloat16 l1 = __float2bfloat16_rn(v1 - __bfloat162float(h1));
    hi = (u32)__bfloat16_as_ushort(h0) | ((u32)__bfloat16_as_ushort(h1) << 16);
    lo = (u32)__bfloat16_as_ushort(l0) | ((u32)__bfloat16_as_ushort(l1) << 16);
}
__device__ __forceinline__ void split2h(float v0, float v1, u32& hi, u32& lo) {
    __half h0 = __float2half_rn(v0);
    __half h1 = __float2half_rn(v1);
    __half l0 = __float2half_rn(v0 - __half2float(h0));
    __half l1 = __float2half_rn(v1 - __half2float(h1));
    hi = (u32)__half_as_ushort(h0) | ((u32)__half_as_ushort(h1) << 16);
    lo = (u32)__half_as_ushort(l0) | ((u32)__half_as_ushort(l1) << 16);
}
__device__ __forceinline__ void cpa16(u32 dst, const void* src) {
    asm volatile("cp.async.cg.shared.global [%0], [%1], 16;"
                 :: "r"(dst), "l"(src));
}
#define CPA_COMMIT() asm volatile("cp.async.commit_group;")
#define CPA_WAIT(n)  asm volatile("cp.async.wait_group %0;" :: "n"(n))

// ---------------- convert kernels -------------------------------------------
__global__ void kcvt_x(const float* __restrict__ x)
{
    size_t i4 = ((size_t)blockIdx.x * 256 + threadIdx.x) * 4;
    float4 v = *(const float4*)&x[i4];
    u32 h0, l0, h1, l1;
    split2h(v.x, v.y, h0, l0);
    split2h(v.z, v.w, h1, l1);
    *(uint2*)&g_xh[i4] = make_uint2(h0, h1);
    *(uint2*)&g_xl[i4] = make_uint2(l0, l1);
}
__global__ void kcvt_w(const float* __restrict__ w1, const float* __restrict__ w2)
{
    size_t i2 = ((size_t)blockIdx.x * 256 + threadIdx.x) * 2;
    {
        __half a = __float2half_rn(w1[i2]), b = __float2half_rn(w1[i2 + 1]);
        *(u32*)&g_wf1[i2] = (u32)__half_as_ushort(a) |
                            ((u32)__half_as_ushort(b) << 16);
    }
    {
        __half a = __float2half_rn(w2[i2]), b = __float2half_rn(w2[i2 + 1]);
        *(u32*)&g_wf2[i2] = (u32)__half_as_ushort(a) |
                            ((u32)__half_as_ushort(b) << 16);
    }
}
__global__ void kcvt_mu(const float* __restrict__ mu)
{
    size_t i2 = ((size_t)blockIdx.x * 256 + threadIdx.x) * 2;
    u32 h, l;
    split2(mu[i2], mu[i2 + 1], h, l);
    *(u32*)&g_muh[i2] = h; *(u32*)&g_mul[i2] = l;
}

// ---------------- conv GEMM v4: fp16 2-term, 3-stage cp.async ---------------
// D[o,p] = sum_c W[o,c]*(INh+INl)[c,p] + epi   (W fp16 single)
#define APITCH 40
#define BPITCH 136
#define AH_OFF 0
#define BH_OFF 10240
#define BL_OFF 18944
#define STAGE_B 27648
#define NSTAGE 3
#define NCH 16
#define HCONV_SMEM (STAGE_B * NSTAGE)

template <int EPI>
__global__ __launch_bounds__(128, 2)
void hconv(float* __restrict__ OUT,
           const float* __restrict__ e0, const float* __restrict__ e1,
           const float* __restrict__ e2, const float* __restrict__ e3)
{
    extern __shared__ __align__(16) char dsm[];
    const u32 sb = smem_u32(dsm);

    const int p0 = blockIdx.x * 128;
    const int o0 = blockIdx.y * 128;
    const int b  = blockIdx.z;
    const int tid = threadIdx.x;
    const int lane = tid & 31, wid = tid >> 5;
    const int ob = (wid & 1) * 64, pb = (wid >> 1) * 64;

    const u16* WH = (EPI == 0) ? g_wf1 : g_wf2;
    const u16* IH = ((EPI == 0) ? g_xh : g_rech) + (size_t)b * CC * NP;
    const u16* IL = ((EPI == 0) ? g_xl : g_recl) + (size_t)b * CC * NP;

    float acc[4][8][4];
#pragma unroll
    for (int mf = 0; mf < 4; mf++)
#pragma unroll
        for (int nf = 0; nf < 8; nf++)
#pragma unroll
            for (int q = 0; q < 4; q++) acc[mf][nf][q] = 0.f;

    const int arow = tid >> 2, au = (tid & 3) * 8;   // A: 128 x 32, 4/thread
    const int brow = tid >> 4, bu = (tid & 15) * 8;  // B: 32 x 128, 4/thread ea

#define LOAD_CHUNK(st, c0)                                                      \
    do {                                                                        \
        u32 base = sb + (st) * STAGE_B;                                         \
        _Pragma("unroll")                                                       \
        for (int i = 0; i < 4; i++) {                                           \
            int r = arow + i * 32;                                              \
            cpa16(base + AH_OFF + (r * APITCH + au) * 2,                        \
                  WH + (size_t)(o0 + r) * CC + (c0) + au);                      \
        }                                                                       \
        _Pragma("unroll")                                                       \
        for (int i = 0; i < 4; i++) {                                           \
            int r = brow + i * 8;                                               \
            cpa16(base + BH_OFF + (r * BPITCH + bu) * 2,                        \
                  IH + (size_t)((c0) + r) * NP + p0 + bu);                      \
            cpa16(base + BL_OFF + (r * BPITCH + bu) * 2,                        \
                  IL + (size_t)((c0) + r) * NP + p0 + bu);                      \
        }                                                                       \
        CPA_COMMIT();                                                           \
    } while (0)

    LOAD_CHUNK(0, 0);
    LOAD_CHUNK(1, 32);

    const u32 a_lane = ((ob + (lane & 15)) * APITCH + (lane >> 4) * 8) * 2;
    const u32 b_rbase = (lane & 7) + ((lane >> 3) & 1) * 8;
    const u32 b_col   = pb + ((lane >> 4) & 1) * 8;

    for (int ch = 0; ch < NCH; ch++) {
        if (ch < NCH - 1) { CPA_WAIT(1); } else { CPA_WAIT(0); }
        __syncthreads();
        if (ch < NCH - 2) LOAD_CHUNK((ch + 2) % NSTAGE, (ch + 2) * 32);

        const u32 stb = sb + (ch % NSTAGE) * STAGE_B;
#pragma unroll
        for (int ks = 0; ks < 2; ks++) {
            u32 ah[4][4];
            const u32 abase = stb + a_lane + ks * 32;
#pragma unroll
            for (int mf = 0; mf < 4; mf++)
                ldsm4(ah[mf], abase + AH_OFF + mf * (16 * APITCH * 2));
            const u32 brow = ks * 16 + b_rbase;
            const u32 bbase = stb + (brow * BPITCH + b_col) * 2;
#pragma unroll
            for (int pr = 0; pr < 4; pr++) {
                u32 bh[4], bl[4];
                ldsm4t(bh, bbase + BH_OFF + pr * 32);
                ldsm4t(bl, bbase + BL_OFF + pr * 32);
#pragma unroll
                for (int mf = 0; mf < 4; mf++) {
#pragma unroll
                    for (int hn = 0; hn < 2; hn++) {
                        float* a = acc[mf][pr * 2 + hn];
                        mma_fp16(a, ah[mf], &bh[hn * 2]);
                        mma_fp16(a, ah[mf], &bl[hn * 2]);
                    }
                }
            }
        }
    }

    const int g = lane >> 2, tg = lane & 3;
#pragma unroll
    for (int mf = 0; mf < 4; mf++) {
        int o_lo = o0 + ob + mf * 16 + g;
        int o_hi = o_lo + 8;
        if (EPI == 0) {
            float add_lo = e0[o_lo], add_hi = e0[o_hi];
            u16* xfh = g_xfh + (size_t)b * CC * NP;
            u16* xfl = g_xfl + (size_t)b * CC * NP;
#pragma unroll
            for (int nf = 0; nf < 8; nf++) {
                int pc = p0 + pb + nf * 8 + tg * 2;
                u32 h, l;
                split2(acc[mf][nf][0] + add_lo, acc[mf][nf][1] + add_lo, h, l);
                *(u32*)&xfh[(size_t)o_lo * NP + pc] = h;
                *(u32*)&xfl[(size_t)o_lo * NP + pc] = l;
                split2(acc[mf][nf][2] + add_hi, acc[mf][nf][3] + add_hi, h, l);
                *(u32*)&xfh[(size_t)o_hi * NP + pc] = h;
                *(u32*)&xfl[(size_t)o_hi * NP + pc] = l;
            }
        } else {
            float mul_lo = e0[o_lo] * rsqrtf(e3[o_lo] + 1e-5f);
            float add_lo = e1[o_lo] - e2[o_lo] * mul_lo;
            float mul_hi = e0[o_hi] * rsqrtf(e3[o_hi] + 1e-5f);
            float add_hi = e1[o_hi] - e2[o_hi] * mul_hi;
            float* outb = OUT + (size_t)b * CC * NP;
#pragma unroll
            for (int nf = 0; nf < 8; nf++) {
                int pc = p0 + pb + nf * 8 + tg * 2;
                float2 v0, v1;
                v0.x = acc[mf][nf][0] * mul_lo + add_lo;
                v0.y = acc[mf][nf][1] * mul_lo + add_lo;
                v1.x = acc[mf][nf][2] * mul_hi + add_hi;
                v1.y = acc[mf][nf][3] * mul_hi + add_hi;
                *(float2*)&outb[(size_t)o_lo * NP + pc] = v0;
                *(float2*)&outb[(size_t)o_hi * NP + pc] = v1;
            }
        }
    }
#undef LOAD_CHUNK
}

// ---------------- kz: z = softmax_k( xf^T @ m ), bf16 3-term HMMA -----------
__global__ __launch_bounds__(256, 2)
void kz_kernel(int use_gm)
{
    __shared__ __align__(16) u16 Xh[32 * 136], Xl[32 * 136]; // (c32, p128)
    __shared__ __align__(16) u16 Mh[32 * 72],  Ml[32 * 72];  // (c32, k64)

    const int p0 = blockIdx.x * 128;
    const int b  = blockIdx.y;
    const int tid = threadIdx.x;
    const int lane = tid & 31, wid = tid >> 5;
    const int pw = wid * 16;

    const u16* XH = g_xfh + (size_t)b * CC * NP;
    const u16* XL = g_xfl + (size_t)b * CC * NP;
    const u16* MH = use_gm ? (g_mh + (size_t)b * CC * KK) : g_muh;
    const u16* ML = use_gm ? (g_ml + (size_t)b * CC * KK) : g_mul;

    float acc[8][4];
#pragma unroll
    for (int nf = 0; nf < 8; nf++)
#pragma unroll
        for (int q = 0; q < 4; q++) acc[nf][q] = 0.f;

    const u32 sxh = smem_u32(Xh), sxl = smem_u32(Xl);
    const u32 smh = smem_u32(Mh), sml = smem_u32(Ml);

    for (int c0 = 0; c0 < CC; c0 += 32) {
#pragma unroll
        for (int it = 0; it < 2; it++) {
            int lin = tid + it * 256;
            int r = lin >> 4, g = lin & 15;
            *(uint4*)&Xh[r * 136 + g * 8] =
                *(const uint4*)(XH + (size_t)(c0 + r) * NP + p0 + g * 8);
            *(uint4*)&Xl[r * 136 + g * 8] =
                *(const uint4*)(XL + (size_t)(c0 + r) * NP + p0 + g * 8);
        }
        {
            int r = tid >> 3, g = tid & 7;
            *(uint4*)&Mh[r * 72 + g * 8] =
                *(const uint4*)(MH + (size_t)(c0 + r) * KK + g * 8);
            *(uint4*)&Ml[r * 72 + g * 8] =
                *(const uint4*)(ML + (size_t)(c0 + r) * KK + g * 8);
        }
        __syncthreads();
#pragma unroll
        for (int ks = 0; ks < 2; ks++) {
            u32 ah[4], al[4];
            {
                u32 row = ks * 16 + (lane & 7) + ((lane >> 4) & 1) * 8;
                u32 col = pw + ((lane >> 3) & 1) * 8;
                u32 off = (row * 136 + col) << 1;
                ldsm4t(ah, sxh + off);
                ldsm4t(al, sxl + off);
            }
            u32 bh[4][4], bl[4][4];
            {
                u32 row = ks * 16 + (lane & 7) + ((lane >> 3) & 1) * 8;
                u32 col = ((lane >> 4) & 1) * 8;
#pragma unroll
                for (int pr = 0; pr < 4; pr++) {
                    u32 off = (row * 72 + col + pr * 16) << 1;
                    ldsm4t(bh[pr], smh + off);
                    ldsm4t(bl[pr], sml + off);
                }
            }
#pragma unroll
            for (int nf = 0; nf < 8; nf++) {
                const u32* bhp = &bh[nf >> 1][(nf & 1) * 2];
                const u32* blp = &bl[nf >> 1][(nf & 1) * 2];
                mma_bf16(acc[nf], ah, bhp);
                mma_bf16(acc[nf], ah, blp);
                mma_bf16(acc[nf], al, bhp);
            }
        }
        __syncthreads();
    }

    const int gr = lane >> 2;
    float mx0 = -1e30f, mx1 = -1e30f;
#pragma unroll
    for (int nf = 0; nf < 8; nf++) {
        mx0 = fmaxf(mx0, fmaxf(acc[nf][0], acc[nf][1]));
        mx1 = fmaxf(mx1, fmaxf(acc[nf][2], acc[nf][3]));
    }
#pragma unroll
    for (int s = 1; s < 4; s <<= 1) {
        mx0 = fmaxf(mx0, __shfl_xor_sync(0xffffffffu, mx0, s));
        mx1 = fmaxf(mx1, __shfl_xor_sync(0xffffffffu, mx1, s));
    }
    float sm0 = 0.f, sm1 = 0.f;
#pragma unroll
    for (int nf = 0; nf < 8; nf++) {
        acc[nf][0] = expf(acc[nf][0] - mx0); sm0 += acc[nf][0];
        acc[nf][1] = expf(acc[nf][1] - mx0); sm0 += acc[nf][1];
        acc[nf][2] = expf(acc[nf][2] - mx1); sm1 += acc[nf][2];
        acc[nf][3] = expf(acc[nf][3] - mx1); sm1 += acc[nf][3];
    }
#pragma unroll
    for (int s = 1; s < 4; s <<= 1) {
        sm0 += __shfl_xor_sync(0xffffffffu, sm0, s);
        sm1 += __shfl_xor_sync(0xffffffffu, sm1, s);
    }
    float inv0 = 1.f / sm0, inv1 = 1.f / sm1;
    const int tg = lane & 3;
    size_t prow_lo = (size_t)(b * NP + p0 + pw + gr) * KK;
    size_t prow_hi = prow_lo + (size_t)8 * KK;
#pragma unroll
    for (int nf = 0; nf < 8; nf++) {
        int kc = nf * 8 + tg * 2;
        u32 h, l;
        split2(acc[nf][0] * inv0, acc[nf][1] * inv0, h, l);
        *(u32*)&g_zh[prow_lo + kc] = h;
        *(u32*)&g_zl[prow_lo + kc] = l;
        split2(acc[nf][2] * inv1, acc[nf][3] * inv1, h, l);
        *(u32*)&g_zh[prow_hi + kc] = h;
        *(u32*)&g_zl[prow_hi + kc] = l;
    }
}

// ---------------- km: mpart = xf @ z (split-K over p), HMMA ------------------
__global__ __launch_bounds__(256, 2)
void km_kernel()
{
    __shared__ __align__(16) u16 Ah[128 * 40], Al[128 * 40]; // (c128, p32)
    __shared__ __align__(16) u16 Zh[32 * 72],  Zl[32 * 72];  // (p32, k64)

    const int ct0 = blockIdx.x * 128;
    const int b   = blockIdx.y;
    const int s   = blockIdx.z;
    const int ps0 = s * (NP / NSPLIT);
    const int tid = threadIdx.x;
    const int lane = tid & 31, wid = tid >> 5;

    const u16* XH = g_xfh + (size_t)b * CC * NP;
    const u16* XL = g_xfl + (size_t)b * CC * NP;
    const u16* ZH = g_zh + (size_t)b * NP * KK;
    const u16* ZL = g_zl + (size_t)b * NP * KK;

    float acc[8][4];
#pragma unroll
    for (int nf = 0; nf < 8; nf++)
#pragma unroll
        for (int q = 0; q < 4; q++) acc[nf][q] = 0.f;

    const u32 sah = smem_u32(Ah), sal = smem_u32(Al);
    const u32 szh = smem_u32(Zh), szl = smem_u32(Zl);

    for (int pc0 = ps0; pc0 < ps0 + NP / NSPLIT; pc0 += 32) {
#pragma unroll
        for (int it = 0; it < 2; it++) {
            int lin = tid + it * 256;
            int r = lin >> 2, g = lin & 3;
            *(uint4*)&Ah[r * 40 + g * 8] =
                *(const uint4*)(XH + (size_t)(ct0 + r) * NP + pc0 + g * 8);
            *(uint4*)&Al[r * 40 + g * 8] =
                *(const uint4*)(XL + (size_t)(ct0 + r) * NP + pc0 + g * 8);
        }
        {
            int r = tid >> 3, g = tid & 7;
            *(uint4*)&Zh[r * 72 + g * 8] =
                *(const uint4*)(ZH + (size_t)(pc0 + r) * KK + g * 8);
            *(uint4*)&Zl[r * 72 + g * 8] =
                *(const uint4*)(ZL + (size_t)(pc0 + r) * KK + g * 8);
        }
        __syncthreads();
#pragma unroll
        for (int ks = 0; ks < 2; ks++) {
            u32 ah[4], al[4];
            {
                u32 off = (((wid * 16 + (lane & 15)) * 40 +
                            ks * 16 + (lane >> 4) * 8)) << 1;
                ldsm4(ah, sah + off);
                ldsm4(al, sal + off);
            }
            u32 bh[4][4], bl[4][4];
            {
                u32 row = ks * 16 + (lane & 7) + ((lane >> 3) & 1) * 8;
                u32 col = ((lane >> 4) & 1) * 8;
#pragma unroll
                for (int pr = 0; pr < 4; pr++) {
                    u32 off = (row * 72 + col + pr * 16) << 1;
                    ldsm4t(bh[pr], szh + off);
                    ldsm4t(bl[pr], szl + off);
                }
            }
#pragma unroll
            for (int nf = 0; nf < 8; nf++) {
                const u32* bhp = &bh[nf >> 1][(nf & 1) * 2];
                const u32* blp = &bl[nf >> 1][(nf & 1) * 2];
                mma_bf16(acc[nf], ah, bhp);
                mma_bf16(acc[nf], ah, blp);
                mma_bf16(acc[nf], al, bhp);
            }
        }
        __syncthreads();
    }

    const int gr = lane >> 2, tg = lane & 3;
    float* out = g_mpart + ((size_t)(s * BB + b) * CC + ct0 + wid * 16) * KK;
#pragma unroll
    for (int nf = 0; nf < 8; nf++) {
        int kc = nf * 8 + tg * 2;
        *(float2*)&out[(size_t)gr * KK + kc] =
            make_float2(acc[nf][0], acc[nf][1]);
        *(float2*)&out[(size_t)(gr + 8) * KK + kc] =
            make_float2(acc[nf][2], acc[nf][3]);
    }
}

// ---------------- norm phase 1 ------------------------------------------------
__global__ void knorm1()
{
    const int cs = blockIdx.x, b = blockIdx.y;
    __shared__ float red[256];
    const int tid = threadIdx.x;
    const size_t bc = ((size_t)b * CC + cs * 64) * KK;
    float ln = 0.f;
#pragma unroll
    for (int it = 0; it < 16; it++) {
        size_t off = bc + tid + it * 256;
        float v = 0.f;
#pragma unroll
        for (int s = 0; s < NSPLIT; s++)
            v += g_mpart[(size_t)s * (BB * CC * KK) + off];
        g_m[off] = v;
        ln += v * v;
    }
    red[tid] = ln;
    __syncthreads();
    if (tid < 64)
        g_norm2[(size_t)(cs * BB + b) * KK + tid] =
            red[tid] + red[tid + 64] + red[tid + 128] + red[tid + 192];
}

// ---------------- norm phase 2 ------------------------------------------------
__global__ void knorm2()
{
    const int cs = blockIdx.x, b = blockIdx.y;
    __shared__ float inv[64];
    const int tid = threadIdx.x;
    if (tid < 64) {
        float s = 0.f;
#pragma unroll
        for (int q = 0; q < 8; q++)
            s += g_norm2[(size_t)(q * BB + b) * KK + tid];
        inv[tid] = 1.f / (EPSF + sqrtf(s));
    }
    __syncthreads();
    const size_t bc = ((size_t)b * CC + cs * 64) * KK;
#pragma unroll
    for (int it = 0; it < 8; it++) {
        size_t off = bc + (tid + it * 256) * 2;
        float v0 = g_m[off] * inv[(2 * tid) & 63];
        float v1 = g_m[off + 1] * inv[(2 * tid + 1) & 63];
        u32 h, l;
        split2(v0, v1, h, l);
        *(u32*)&g_mh[off] = h;
        *(u32*)&g_ml[off] = l;
    }
}

// ---------------- krec: rec = relu(m @ z^T) -> fp16 hi/lo (c,p) --------------
__global__ __launch_bounds__(256, 2)
void krec_kernel()
{
    __shared__ __align__(16) u16 Ah[128 * 40], Al[128 * 40]; // (c128, k32)
    __shared__ __align__(16) u16 Bh[128 * 40], Bl[128 * 40]; // (p128, k32)

    const int p0  = blockIdx.x * 128;
    const int ct0 = blockIdx.y * 128;
    const int b   = blockIdx.z;
    const int tid = threadIdx.x;
    const int lane = tid & 31, wid = tid >> 5;
    const int wm = wid & 1, wn = wid >> 1;
    const int cb = wm * 64, pb = wn * 32;

    const u16* MH = g_mh + (size_t)b * CC * KK;
    const u16* ML = g_ml + (size_t)b * CC * KK;
    const u16* ZH = g_zh + (size_t)b * NP * KK;
    const u16* ZL = g_zl + (size_t)b * NP * KK;

    float acc[4][4][4];
#pragma unroll
    for (int mf = 0; mf < 4; mf++)
#pragma unroll
        for (int nf = 0; nf < 4; nf++)
#pragma unroll
            for (int q = 0; q < 4; q++) acc[mf][nf][q] = 0.f;

    const u32 sah = smem_u32(Ah), sal = smem_u32(Al);
    const u32 sbh = smem_u32(Bh), sbl = smem_u32(Bl);

    for (int kc0 = 0; kc0 < KK; kc0 += 32) {
#pragma unroll
        for (int it = 0; it < 2; it++) {
            int lin = tid + it * 256;
            int r = lin >> 2, g = lin & 3;
            *(uint4*)&Ah[r * 40 + g * 8] =
                *(const uint4*)(MH + (size_t)(ct0 + r) * KK + kc0 + g * 8);
            *(uint4*)&Al[r * 40 + g * 8] =
                *(const uint4*)(ML + (size_t)(ct0 + r) * KK + kc0 + g * 8);
        }
#pragma unroll
        for (int it = 0; it < 2; it++) {
            int lin = tid + it * 256;
            int r = lin >> 2, g = lin & 3;
            *(uint4*)&Bh[r * 40 + g * 8] =
                *(const uint4*)(ZH + (size_t)(p0 + r) * KK + kc0 + g * 8);
            *(uint4*)&Bl[r * 40 + g * 8] =
                *(const uint4*)(ZL + (size_t)(p0 + r) * KK + kc0 + g * 8);
        }
        __syncthreads();
#pragma unroll
        for (int ks = 0; ks < 2; ks++) {
            u32 ah[4][4], al[4][4];
            u32 a_off = (((cb + (lane & 15)) * 40 + ks * 16 + (lane >> 4) * 8)) << 1;
#pragma unroll
            for (int mf = 0; mf < 4; mf++) {
                ldsm4(ah[mf], sah + a_off + mf * (16 * 40 * 2));
                ldsm4(al[mf], sal + a_off + mf * (16 * 40 * 2));
            }
            u32 bh[2][4], bl[2][4];
            u32 brow = pb + ((lane >> 4) & 1) * 8 + (lane & 7);
            u32 bcol = ks * 16 + ((lane >> 3) & 1) * 8;
#pragma unroll
            for (int pr = 0; pr < 2; pr++) {
                u32 boff = ((brow + pr * 16) * 40 + bcol) << 1;
                ldsm4(bh[pr], sbh + boff);
                ldsm4(bl[pr], sbl + boff);
            }
#pragma unroll
            for (int mf = 0; mf < 4; mf++)
#pragma unroll
                for (int nf = 0; nf < 4; nf++) {
                    const u32* bhp = &bh[nf >> 1][(nf & 1) * 2];
                    const u32* blp = &bl[nf >> 1][(nf & 1) * 2];
                    mma_bf16(acc[mf][nf], ah[mf], bhp);
                    mma_bf16(acc[mf][nf], ah[mf], blp);
                    mma_bf16(acc[mf][nf], al[mf], bhp);
                }
        }
        __syncthreads();
    }

    const int g = lane >> 2, tg = lane & 3;
    u16* rh = g_rech + (size_t)b * CC * NP;
    u16* rl = g_recl + (size_t)b * CC * NP;
#pragma unroll
    for (int mf = 0; mf < 4; mf++) {
        int c_lo = ct0 + cb + mf * 16 + g;
        int c_hi = c_lo + 8;
#pragma unroll
        for (int nf = 0; nf < 4; nf++) {
            int pc = p0 + pb + nf * 8 + tg * 2;
            u32 h, l;
            split2h(fmaxf(acc[mf][nf][0], 0.f), fmaxf(acc[mf][nf][1], 0.f), h, l);
            *(u32*)&rh[(size_t)c_lo * NP + pc] = h;
            *(u32*)&rl[(size_t)c_lo * NP + pc] = l;
            split2h(fmaxf(acc[mf][nf][2], 0.f), fmaxf(acc[mf][nf][3], 0.f), h, l);
            *(u32*)&rh[(size_t)c_hi * NP + pc] = h;
            *(u32*)&rl[(size_t)c_hi * NP + pc] = l;
        }
    }
}

// ---------------- launch ----------------------------------------------------
extern "C" void kernel_launch(void* const* d_in, const int* in_sizes, int n_in,
                              void* d_out, int out_size)
{
    (void)in_sizes; (void)n_in; (void)out_size;
    const float* x     = (const float*)d_in[0];
    const float* w1    = (const float*)d_in[1];
    const float* b1    = (const float*)d_in[2];
    const float* mu    = (const float*)d_in[3];
    const float* w2    = (const float*)d_in[4];
    const float* gamma = (const float*)d_in[5];
    const float* beta  = (const float*)d_in[6];
    const float* mean  = (const float*)d_in[7];
    const float* var   = (const float*)d_in[8];
    float* out = (float*)d_out;

    cudaFuncSetAttribute(hconv<0>, cudaFuncAttributeMaxDynamicSharedMemorySize,
                         HCONV_SMEM);
    cudaFuncSetAttribute(hconv<1>, cudaFuncAttributeMaxDynamicSharedMemorySize,
                         HCONV_SMEM);

    kcvt_x<<<(int)(((size_t)BB * CC * NP) / 1024), 256>>>(x);
    kcvt_w<<<(CC * CC) / 512, 256>>>(w1, w2);
    kcvt_mu<<<(CC * KK) / 512, 256>>>(mu);

    hconv<0><<<dim3(NP / 128, CC / 128, BB), 128, HCONV_SMEM>>>(
        nullptr, b1, nullptr, nullptr, nullptr);

    for (int st = 0; st < 3; st++) {
        kz_kernel<<<dim3(NP / 128, BB), 256>>>(st > 0 ? 1 : 0);
        km_kernel<<<dim3(CC / 128, BB, NSPLIT), 256>>>();
        knorm1<<<dim3(8, BB), 256>>>();
        knorm2<<<dim3(8, BB), 256>>>();
    }

    krec_kernel<<<dim3(NP / 128, CC / 128, BB), 256>>>();

    hconv<1><<<dim3(NP / 128, CC / 128, BB), 128, HCONV_SMEM>>>(
        out, gamma, beta, mean, var);
}

// round 9
// speedup vs baseline: 2.7374x; 1.0530x over previous
#include <cuda_runtime.h>
#include <cuda_bf16.h>
#include <cuda_fp16.h>

#define CC 512
#define NP 4096
#define KK 64
#define BB 16
#define NSPLIT 4
#define EPSF 1e-6f

typedef unsigned long long u64;
typedef unsigned int u32;
typedef unsigned short u16;

// ---------------- scratch (static device globals) ---------------------------
__device__ u16 g_xh[(size_t)BB * CC * NP];   // x hi fp16 (b,c,p)
__device__ u16 g_xl[(size_t)BB * CC * NP];   // x lo fp16
__device__ u16 g_wf1[(size_t)CC * CC];       // w1 fp16 single
__device__ u16 g_wf2[(size_t)CC * CC];       // w2 fp16 single
__device__ u16 g_muh[(size_t)CC * KK], g_mul[(size_t)CC * KK];   // bf16
__device__ u16 g_xfh[(size_t)BB * CC * NP];  // conv1 out hi bf16 (b,c,p)
__device__ u16 g_xfl[(size_t)BB * CC * NP];
__device__ u16 g_zh[(size_t)BB * NP * KK];   // z hi bf16 (b,p,k)
__device__ u16 g_zl[(size_t)BB * NP * KK];
__device__ u16 g_mh[(size_t)BB * CC * KK];   // m hi bf16 (b,c,k)
__device__ u16 g_ml[(size_t)BB * CC * KK];
__device__ u16 g_rech[(size_t)BB * CC * NP]; // relu(rec) hi fp16 (b,c,p)
__device__ u16 g_recl[(size_t)BB * CC * NP]; // relu(rec) lo fp16
__device__ float g_mpart[(size_t)NSPLIT * BB * CC * KK];
__device__ float g_m[(size_t)BB * CC * KK];
__device__ float g_norm2[(size_t)8 * BB * KK];

// ---------------- helpers ----------------------------------------------------
__device__ __forceinline__ u32 smem_u32(const void* p) {
    u32 a;
    asm("{ .reg .u64 t; cvta.to.shared.u64 t, %1; cvt.u32.u64 %0, t; }"
        : "=r"(a) : "l"(p));
    return a;
}
__device__ __forceinline__ void ldsm4(u32* r, u32 addr) {
    asm volatile("ldmatrix.sync.aligned.m8n8.x4.shared.b16 {%0,%1,%2,%3}, [%4];"
                 : "=r"(r[0]), "=r"(r[1]), "=r"(r[2]), "=r"(r[3]) : "r"(addr));
}
__device__ __forceinline__ void ldsm4t(u32* r, u32 addr) {
    asm volatile("ldmatrix.sync.aligned.m8n8.x4.trans.shared.b16 {%0,%1,%2,%3}, [%4];"
                 : "=r"(r[0]), "=r"(r[1]), "=r"(r[2]), "=r"(r[3]) : "r"(addr));
}
__device__ __forceinline__ void mma_bf16(float* d, const u32* a, const u32* b) {
    asm volatile(
        "mma.sync.aligned.m16n8k16.row.col.f32.bf16.bf16.f32 "
        "{%0,%1,%2,%3}, {%4,%5,%6,%7}, {%8,%9}, {%0,%1,%2,%3};"
        : "+f"(d[0]), "+f"(d[1]), "+f"(d[2]), "+f"(d[3])
        : "r"(a[0]), "r"(a[1]), "r"(a[2]), "r"(a[3]), "r"(b[0]), "r"(b[1]));
}
__device__ __forceinline__ void mma_fp16(float* d, const u32* a, const u32* b) {
    asm volatile(
        "mma.sync.aligned.m16n8k16.row.col.f32.f16.f16.f32 "
        "{%0,%1,%2,%3}, {%4,%5,%6,%7}, {%8,%9}, {%0,%1,%2,%3};"
        : "+f"(d[0]), "+f"(d[1]), "+f"(d[2]), "+f"(d[3])
        : "r"(a[0]), "r"(a[1]), "r"(a[2]), "r"(a[3]), "r"(b[0]), "r"(b[1]));
}
__device__ __forceinline__ void split2(float v0, float v1, u32& hi, u32& lo) {
    __nv_bfloat16 h0 = __float2bfloat16_rn(v0);
    __nv_bfloat16 h1 = __float2bfloat16_rn(v1);
    __nv_bfloat16 l0 = __float2bfloat16_rn(v0 - __bfloat162float(h0));
    __nv_bfloat16 l1 = __float2bfloat16_rn(v1 - __bfloat162float(h1));
    hi = (u32)__bfloat16_as_ushort(h0) | ((u32)__bfloat16_as_ushort(h1) << 16);
    lo = (u32)__bfloat16_as_ushort(l0) | ((u32)__bfloat16_as_ushort(l1) << 16);
}
__device__ __forceinline__ void split2h(float v0, float v1, u32& hi, u32& lo) {
    __half h0 = __float2half_rn(v0);
    __half h1 = __float2half_rn(v1);
    __half l0 = __float2half_rn(v0 - __half2float(h0));
    __half l1 = __float2half_rn(v1 - __half2float(h1));
    hi = (u32)__half_as_ushort(h0) | ((u32)__half_as_ushort(h1) << 16);
    lo = (u32)__half_as_ushort(l0) | ((u32)__half_as_ushort(l1) << 16);
}
__device__ __forceinline__ void cpa16(u32 dst, const void* src) {
    asm volatile("cp.async.cg.shared.global [%0], [%1], 16;"
                 :: "r"(dst), "l"(src));
}
#define CPA_COMMIT() asm volatile("cp.async.commit_group;")
#define CPA_WAIT(n)  asm volatile("cp.async.wait_group %0;" :: "n"(n))

// ---------------- convert kernels -------------------------------------------
__global__ void kcvt_x(const float* __restrict__ x)
{
    size_t i4 = ((size_t)blockIdx.x * 256 + threadIdx.x) * 4;
    float4 v = *(const float4*)&x[i4];
    u32 h0, l0, h1, l1;
    split2h(v.x, v.y, h0, l0);
    split2h(v.z, v.w, h1, l1);
    *(uint2*)&g_xh[i4] = make_uint2(h0, h1);
    *(uint2*)&g_xl[i4] = make_uint2(l0, l1);
}
__global__ void kcvt_w(const float* __restrict__ w1, const float* __restrict__ w2)
{
    size_t i2 = ((size_t)blockIdx.x * 256 + threadIdx.x) * 2;
    {
        __half a = __float2half_rn(w1[i2]), b = __float2half_rn(w1[i2 + 1]);
        *(u32*)&g_wf1[i2] = (u32)__half_as_ushort(a) |
                            ((u32)__half_as_ushort(b) << 16);
    }
    {
        __half a = __float2half_rn(w2[i2]), b = __float2half_rn(w2[i2 + 1]);
        *(u32*)&g_wf2[i2] = (u32)__half_as_ushort(a) |
                            ((u32)__half_as_ushort(b) << 16);
    }
}
__global__ void kcvt_mu(const float* __restrict__ mu)
{
    size_t i2 = ((size_t)blockIdx.x * 256 + threadIdx.x) * 2;
    u32 h, l;
    split2(mu[i2], mu[i2 + 1], h, l);
    *(u32*)&g_muh[i2] = h; *(u32*)&g_mul[i2] = l;
}

// ---------------- conv GEMM v4: fp16 2-term, 3-stage cp.async ---------------
#define APITCH 40
#define BPITCH 136
#define AH_OFF 0
#define BH_OFF 10240
#define BL_OFF 18944
#define STAGE_B 27648
#define NSTAGE 3
#define NCH 16
#define HCONV_SMEM (STAGE_B * NSTAGE)

template <int EPI>
__global__ __launch_bounds__(128, 2)
void hconv(float* __restrict__ OUT,
           const float* __restrict__ e0, const float* __restrict__ e1,
           const float* __restrict__ e2, const float* __restrict__ e3)
{
    extern __shared__ __align__(16) char dsm[];
    const u32 sb = smem_u32(dsm);

    const int p0 = blockIdx.x * 128;
    const int o0 = blockIdx.y * 128;
    const int b  = blockIdx.z;
    const int tid = threadIdx.x;
    const int lane = tid & 31, wid = tid >> 5;
    const int ob = (wid & 1) * 64, pb = (wid >> 1) * 64;

    const u16* WH = (EPI == 0) ? g_wf1 : g_wf2;
    const u16* IH = ((EPI == 0) ? g_xh : g_rech) + (size_t)b * CC * NP;
    const u16* IL = ((EPI == 0) ? g_xl : g_recl) + (size_t)b * CC * NP;

    float acc[4][8][4];
#pragma unroll
    for (int mf = 0; mf < 4; mf++)
#pragma unroll
        for (int nf = 0; nf < 8; nf++)
#pragma unroll
            for (int q = 0; q < 4; q++) acc[mf][nf][q] = 0.f;

    const int arow = tid >> 2, au = (tid & 3) * 8;
    const int brow = tid >> 4, bu = (tid & 15) * 8;

#define LOAD_CHUNK(st, c0)                                                      \
    do {                                                                        \
        u32 base = sb + (st) * STAGE_B;                                         \
        _Pragma("unroll")                                                       \
        for (int i = 0; i < 4; i++) {                                           \
            int r = arow + i * 32;                                              \
            cpa16(base + AH_OFF + (r * APITCH + au) * 2,                        \
                  WH + (size_t)(o0 + r) * CC + (c0) + au);                      \
        }                                                                       \
        _Pragma("unroll")                                                       \
        for (int i = 0; i < 4; i++) {                                           \
            int r = brow + i * 8;                                               \
            cpa16(base + BH_OFF + (r * BPITCH + bu) * 2,                        \
                  IH + (size_t)((c0) + r) * NP + p0 + bu);                      \
            cpa16(base + BL_OFF + (r * BPITCH + bu) * 2,                        \
                  IL + (size_t)((c0) + r) * NP + p0 + bu);                      \
        }                                                                       \
        CPA_COMMIT();                                                           \
    } while (0)

    LOAD_CHUNK(0, 0);
    LOAD_CHUNK(1, 32);

    const u32 a_lane = ((ob + (lane & 15)) * APITCH + (lane >> 4) * 8) * 2;
    const u32 b_rbase = (lane & 7) + ((lane >> 3) & 1) * 8;
    const u32 b_col   = pb + ((lane >> 4) & 1) * 8;

    for (int ch = 0; ch < NCH; ch++) {
        if (ch < NCH - 1) { CPA_WAIT(1); } else { CPA_WAIT(0); }
        __syncthreads();
        if (ch < NCH - 2) LOAD_CHUNK((ch + 2) % NSTAGE, (ch + 2) * 32);

        const u32 stb = sb + (ch % NSTAGE) * STAGE_B;
#pragma unroll
        for (int ks = 0; ks < 2; ks++) {
            u32 ah[4][4];
            const u32 abase = stb + a_lane + ks * 32;
#pragma unroll
            for (int mf = 0; mf < 4; mf++)
                ldsm4(ah[mf], abase + AH_OFF + mf * (16 * APITCH * 2));
            const u32 brow = ks * 16 + b_rbase;
            const u32 bbase = stb + (brow * BPITCH + b_col) * 2;
#pragma unroll
            for (int pr = 0; pr < 4; pr++) {
                u32 bh[4], bl[4];
                ldsm4t(bh, bbase + BH_OFF + pr * 32);
                ldsm4t(bl, bbase + BL_OFF + pr * 32);
#pragma unroll
                for (int mf = 0; mf < 4; mf++) {
#pragma unroll
                    for (int hn = 0; hn < 2; hn++) {
                        float* a = acc[mf][pr * 2 + hn];
                        mma_fp16(a, ah[mf], &bh[hn * 2]);
                        mma_fp16(a, ah[mf], &bl[hn * 2]);
                    }
                }
            }
        }
    }

    const int g = lane >> 2, tg = lane & 3;
#pragma unroll
    for (int mf = 0; mf < 4; mf++) {
        int o_lo = o0 + ob + mf * 16 + g;
        int o_hi = o_lo + 8;
        if (EPI == 0) {
            float add_lo = e0[o_lo], add_hi = e0[o_hi];
            u16* xfh = g_xfh + (size_t)b * CC * NP;
            u16* xfl = g_xfl + (size_t)b * CC * NP;
#pragma unroll
            for (int nf = 0; nf < 8; nf++) {
                int pc = p0 + pb + nf * 8 + tg * 2;
                u32 h, l;
                split2(acc[mf][nf][0] + add_lo, acc[mf][nf][1] + add_lo, h, l);
                *(u32*)&xfh[(size_t)o_lo * NP + pc] = h;
                *(u32*)&xfl[(size_t)o_lo * NP + pc] = l;
                split2(acc[mf][nf][2] + add_hi, acc[mf][nf][3] + add_hi, h, l);
                *(u32*)&xfh[(size_t)o_hi * NP + pc] = h;
                *(u32*)&xfl[(size_t)o_hi * NP + pc] = l;
            }
        } else {
            float mul_lo = e0[o_lo] * rsqrtf(e3[o_lo] + 1e-5f);
            float add_lo = e1[o_lo] - e2[o_lo] * mul_lo;
            float mul_hi = e0[o_hi] * rsqrtf(e3[o_hi] + 1e-5f);
            float add_hi = e1[o_hi] - e2[o_hi] * mul_hi;
            float* outb = OUT + (size_t)b * CC * NP;
#pragma unroll
            for (int nf = 0; nf < 8; nf++) {
                int pc = p0 + pb + nf * 8 + tg * 2;
                float2 v0, v1;
                v0.x = acc[mf][nf][0] * mul_lo + add_lo;
                v0.y = acc[mf][nf][1] * mul_lo + add_lo;
                v1.x = acc[mf][nf][2] * mul_hi + add_hi;
                v1.y = acc[mf][nf][3] * mul_hi + add_hi;
                *(float2*)&outb[(size_t)o_lo * NP + pc] = v0;
                *(float2*)&outb[(size_t)o_hi * NP + pc] = v1;
            }
        }
    }
#undef LOAD_CHUNK
}

// ---------------- kz: z = softmax_k( xf^T @ m ), reg-prefetch pipeline ------
__global__ __launch_bounds__(256, 2)
void kz_kernel(int use_gm)
{
    __shared__ __align__(16) u16 Xh[32 * 136], Xl[32 * 136]; // (c32, p128)
    __shared__ __align__(16) u16 Mh[32 * 72],  Ml[32 * 72];  // (c32, k64)

    const int p0 = blockIdx.x * 128;
    const int b  = blockIdx.y;
    const int tid = threadIdx.x;
    const int lane = tid & 31, wid = tid >> 5;
    const int pw = wid * 16;

    const u16* XH = g_xfh + (size_t)b * CC * NP;
    const u16* XL = g_xfl + (size_t)b * CC * NP;
    const u16* MH = use_gm ? (g_mh + (size_t)b * CC * KK) : g_muh;
    const u16* ML = use_gm ? (g_ml + (size_t)b * CC * KK) : g_mul;

    float acc[8][4];
#pragma unroll
    for (int nf = 0; nf < 8; nf++)
#pragma unroll
        for (int q = 0; q < 4; q++) acc[nf][q] = 0.f;

    const u32 sxh = smem_u32(Xh), sxl = smem_u32(Xl);
    const u32 smh = smem_u32(Mh), sml = smem_u32(Ml);

    // load coords
    const int xr0 = tid >> 4,           xg0 = (tid & 15) * 8;
    const int xr1 = (tid + 256) >> 4,   xg1 = (tid & 15) * 8;
    const int mr  = tid >> 3,           mg  = (tid & 7) * 8;

    uint4 pxh[2], pxl[2], pmh, pml;
#define KZ_PREFETCH(c0)                                                        \
    do {                                                                       \
        pxh[0] = *(const uint4*)(XH + (size_t)((c0) + xr0) * NP + p0 + xg0);   \
        pxh[1] = *(const uint4*)(XH + (size_t)((c0) + xr1) * NP + p0 + xg1);   \
        pxl[0] = *(const uint4*)(XL + (size_t)((c0) + xr0) * NP + p0 + xg0);   \
        pxl[1] = *(const uint4*)(XL + (size_t)((c0) + xr1) * NP + p0 + xg1);   \
        pmh    = *(const uint4*)(MH + (size_t)((c0) + mr) * KK + mg);          \
        pml    = *(const uint4*)(ML + (size_t)((c0) + mr) * KK + mg);          \
    } while (0)

    KZ_PREFETCH(0);

    for (int c0 = 0; c0 < CC; c0 += 32) {
        __syncthreads();
        *(uint4*)&Xh[xr0 * 136 + xg0] = pxh[0];
        *(uint4*)&Xh[xr1 * 136 + xg1] = pxh[1];
        *(uint4*)&Xl[xr0 * 136 + xg0] = pxl[0];
        *(uint4*)&Xl[xr1 * 136 + xg1] = pxl[1];
        *(uint4*)&Mh[mr * 72 + mg] = pmh;
        *(uint4*)&Ml[mr * 72 + mg] = pml;
        __syncthreads();
        if (c0 + 32 < CC) KZ_PREFETCH(c0 + 32);

#pragma unroll
        for (int ks = 0; ks < 2; ks++) {
            u32 ah[4], al[4];
            {
                u32 row = ks * 16 + (lane & 7) + ((lane >> 4) & 1) * 8;
                u32 col = pw + ((lane >> 3) & 1) * 8;
                u32 off = (row * 136 + col) << 1;
                ldsm4t(ah, sxh + off);
                ldsm4t(al, sxl + off);
            }
            u32 bh[4][4], bl[4][4];
            {
                u32 row = ks * 16 + (lane & 7) + ((lane >> 3) & 1) * 8;
                u32 col = ((lane >> 4) & 1) * 8;
#pragma unroll
                for (int pr = 0; pr < 4; pr++) {
                    u32 off = (row * 72 + col + pr * 16) << 1;
                    ldsm4t(bh[pr], smh + off);
                    ldsm4t(bl[pr], sml + off);
                }
            }
#pragma unroll
            for (int nf = 0; nf < 8; nf++) {
                const u32* bhp = &bh[nf >> 1][(nf & 1) * 2];
                const u32* blp = &bl[nf >> 1][(nf & 1) * 2];
                mma_bf16(acc[nf], ah, bhp);
                mma_bf16(acc[nf], ah, blp);
                mma_bf16(acc[nf], al, bhp);
            }
        }
    }
#undef KZ_PREFETCH

    const int gr = lane >> 2;
    float mx0 = -1e30f, mx1 = -1e30f;
#pragma unroll
    for (int nf = 0; nf < 8; nf++) {
        mx0 = fmaxf(mx0, fmaxf(acc[nf][0], acc[nf][1]));
        mx1 = fmaxf(mx1, fmaxf(acc[nf][2], acc[nf][3]));
    }
#pragma unroll
    for (int s = 1; s < 4; s <<= 1) {
        mx0 = fmaxf(mx0, __shfl_xor_sync(0xffffffffu, mx0, s));
        mx1 = fmaxf(mx1, __shfl_xor_sync(0xffffffffu, mx1, s));
    }
    float sm0 = 0.f, sm1 = 0.f;
#pragma unroll
    for (int nf = 0; nf < 8; nf++) {
        acc[nf][0] = expf(acc[nf][0] - mx0); sm0 += acc[nf][0];
        acc[nf][1] = expf(acc[nf][1] - mx0); sm0 += acc[nf][1];
        acc[nf][2] = expf(acc[nf][2] - mx1); sm1 += acc[nf][2];
        acc[nf][3] = expf(acc[nf][3] - mx1); sm1 += acc[nf][3];
    }
#pragma unroll
    for (int s = 1; s < 4; s <<= 1) {
        sm0 += __shfl_xor_sync(0xffffffffu, sm0, s);
        sm1 += __shfl_xor_sync(0xffffffffu, sm1, s);
    }
    float inv0 = 1.f / sm0, inv1 = 1.f / sm1;
    const int tg = lane & 3;
    size_t prow_lo = (size_t)(b * NP + p0 + pw + gr) * KK;
    size_t prow_hi = prow_lo + (size_t)8 * KK;
#pragma unroll
    for (int nf = 0; nf < 8; nf++) {
        int kc = nf * 8 + tg * 2;
        u32 h, l;
        split2(acc[nf][0] * inv0, acc[nf][1] * inv0, h, l);
        *(u32*)&g_zh[prow_lo + kc] = h;
        *(u32*)&g_zl[prow_lo + kc] = l;
        split2(acc[nf][2] * inv1, acc[nf][3] * inv1, h, l);
        *(u32*)&g_zh[prow_hi + kc] = h;
        *(u32*)&g_zl[prow_hi + kc] = l;
    }
}

// ---------------- km: mpart = xf @ z (split-K over p), reg-prefetch ---------
__global__ __launch_bounds__(256, 2)
void km_kernel()
{
    __shared__ __align__(16) u16 Ah[128 * 40], Al[128 * 40]; // (c128, p32)
    __shared__ __align__(16) u16 Zh[32 * 72],  Zl[32 * 72];  // (p32, k64)

    const int ct0 = blockIdx.x * 128;
    const int b   = blockIdx.y;
    const int s   = blockIdx.z;
    const int ps0 = s * (NP / NSPLIT);
    const int tid = threadIdx.x;
    const int lane = tid & 31, wid = tid >> 5;

    const u16* XH = g_xfh + (size_t)b * CC * NP;
    const u16* XL = g_xfl + (size_t)b * CC * NP;
    const u16* ZH = g_zh + (size_t)b * NP * KK;
    const u16* ZL = g_zl + (size_t)b * NP * KK;

    float acc[8][4];
#pragma unroll
    for (int nf = 0; nf < 8; nf++)
#pragma unroll
        for (int q = 0; q < 4; q++) acc[nf][q] = 0.f;

    const u32 sah = smem_u32(Ah), sal = smem_u32(Al);
    const u32 szh = smem_u32(Zh), szl = smem_u32(Zl);

    const int ar0 = tid >> 2,         ag0 = (tid & 3) * 8;
    const int ar1 = (tid + 256) >> 2, ag1 = (tid & 3) * 8;
    const int zr  = tid >> 3,         zg  = (tid & 7) * 8;

    uint4 pah[2], pal[2], pzh, pzl;
#define KM_PREFETCH(pc0)                                                       \
    do {                                                                       \
        pah[0] = *(const uint4*)(XH + (size_t)(ct0 + ar0) * NP + (pc0) + ag0); \
        pah[1] = *(const uint4*)(XH + (size_t)(ct0 + ar1) * NP + (pc0) + ag1); \
        pal[0] = *(const uint4*)(XL + (size_t)(ct0 + ar0) * NP + (pc0) + ag0); \
        pal[1] = *(const uint4*)(XL + (size_t)(ct0 + ar1) * NP + (pc0) + ag1); \
        pzh    = *(const uint4*)(ZH + (size_t)((pc0) + zr) * KK + zg);         \
        pzl    = *(const uint4*)(ZL + (size_t)((pc0) + zr) * KK + zg);         \
    } while (0)

    KM_PREFETCH(ps0);

    for (int pc0 = ps0; pc0 < ps0 + NP / NSPLIT; pc0 += 32) {
        __syncthreads();
        *(uint4*)&Ah[ar0 * 40 + ag0] = pah[0];
        *(uint4*)&Ah[ar1 * 40 + ag1] = pah[1];
        *(uint4*)&Al[ar0 * 40 + ag0] = pal[0];
        *(uint4*)&Al[ar1 * 40 + ag1] = pal[1];
        *(uint4*)&Zh[zr * 72 + zg] = pzh;
        *(uint4*)&Zl[zr * 72 + zg] = pzl;
        __syncthreads();
        if (pc0 + 32 < ps0 + NP / NSPLIT) KM_PREFETCH(pc0 + 32);

#pragma unroll
        for (int ks = 0; ks < 2; ks++) {
            u32 ah[4], al[4];
            {
                u32 off = (((wid * 16 + (lane & 15)) * 40 +
                            ks * 16 + (lane >> 4) * 8)) << 1;
                ldsm4(ah, sah + off);
                ldsm4(al, sal + off);
            }
            u32 bh[4][4], bl[4][4];
            {
                u32 row = ks * 16 + (lane & 7) + ((lane >> 3) & 1) * 8;
                u32 col = ((lane >> 4) & 1) * 8;
#pragma unroll
                for (int pr = 0; pr < 4; pr++) {
                    u32 off = (row * 72 + col + pr * 16) << 1;
                    ldsm4t(bh[pr], szh + off);
                    ldsm4t(bl[pr], szl + off);
                }
            }
#pragma unroll
            for (int nf = 0; nf < 8; nf++) {
                const u32* bhp = &bh[nf >> 1][(nf & 1) * 2];
                const u32* blp = &bl[nf >> 1][(nf & 1) * 2];
                mma_bf16(acc[nf], ah, bhp);
                mma_bf16(acc[nf], ah, blp);
                mma_bf16(acc[nf], al, bhp);
            }
        }
    }
#undef KM_PREFETCH

    const int gr = lane >> 2, tg = lane & 3;
    float* out = g_mpart + ((size_t)(s * BB + b) * CC + ct0 + wid * 16) * KK;
#pragma unroll
    for (int nf = 0; nf < 8; nf++) {
        int kc = nf * 8 + tg * 2;
        *(float2*)&out[(size_t)gr * KK + kc] =
            make_float2(acc[nf][0], acc[nf][1]);
        *(float2*)&out[(size_t)(gr + 8) * KK + kc] =
            make_float2(acc[nf][2], acc[nf][3]);
    }
}

// ---------------- norm phase 1 ------------------------------------------------
__global__ void knorm1()
{
    const int cs = blockIdx.x, b = blockIdx.y;
    __shared__ float red[256];
    const int tid = threadIdx.x;
    const size_t bc = ((size_t)b * CC + cs * 64) * KK;
    float ln = 0.f;
#pragma unroll
    for (int it = 0; it < 16; it++) {
        size_t off = bc + tid + it * 256;
        float v = 0.f;
#pragma unroll
        for (int s = 0; s < NSPLIT; s++)
            v += g_mpart[(size_t)s * (BB * CC * KK) + off];
        g_m[off] = v;
        ln += v * v;
    }
    red[tid] = ln;
    __syncthreads();
    if (tid < 64)
        g_norm2[(size_t)(cs * BB + b) * KK + tid] =
            red[tid] + red[tid + 64] + red[tid + 128] + red[tid + 192];
}

// ---------------- norm phase 2 ------------------------------------------------
__global__ void knorm2()
{
    const int cs = blockIdx.x, b = blockIdx.y;
    __shared__ float inv[64];
    const int tid = threadIdx.x;
    if (tid < 64) {
        float s = 0.f;
#pragma unroll
        for (int q = 0; q < 8; q++)
            s += g_norm2[(size_t)(q * BB + b) * KK + tid];
        inv[tid] = 1.f / (EPSF + sqrtf(s));
    }
    __syncthreads();
    const size_t bc = ((size_t)b * CC + cs * 64) * KK;
#pragma unroll
    for (int it = 0; it < 8; it++) {
        size_t off = bc + (tid + it * 256) * 2;
        float v0 = g_m[off] * inv[(2 * tid) & 63];
        float v1 = g_m[off + 1] * inv[(2 * tid + 1) & 63];
        u32 h, l;
        split2(v0, v1, h, l);
        *(u32*)&g_mh[off] = h;
        *(u32*)&g_ml[off] = l;
    }
}

// ---------------- krec: rec = relu(m @ z^T) -> fp16 hi/lo (c,p) --------------
__global__ __launch_bounds__(256, 2)
void krec_kernel()
{
    __shared__ __align__(16) u16 Ah[128 * 40], Al[128 * 40]; // (c128, k32)
    __shared__ __align__(16) u16 Bh[128 * 40], Bl[128 * 40]; // (p128, k32)

    const int p0  = blockIdx.x * 128;
    const int ct0 = blockIdx.y * 128;
    const int b   = blockIdx.z;
    const int tid = threadIdx.x;
    const int lane = tid & 31, wid = tid >> 5;
    const int wm = wid & 1, wn = wid >> 1;
    const int cb = wm * 64, pb = wn * 32;

    const u16* MH = g_mh + (size_t)b * CC * KK;
    const u16* ML = g_ml + (size_t)b * CC * KK;
    const u16* ZH = g_zh + (size_t)b * NP * KK;
    const u16* ZL = g_zl + (size_t)b * NP * KK;

    float acc[4][4][4];
#pragma unroll
    for (int mf = 0; mf < 4; mf++)
#pragma unroll
        for (int nf = 0; nf < 4; nf++)
#pragma unroll
            for (int q = 0; q < 4; q++) acc[mf][nf][q] = 0.f;

    const u32 sah = smem_u32(Ah), sal = smem_u32(Al);
    const u32 sbh = smem_u32(Bh), sbl = smem_u32(Bl);

    for (int kc0 = 0; kc0 < KK; kc0 += 32) {
#pragma unroll
        for (int it = 0; it < 2; it++) {
            int lin = tid + it * 256;
            int r = lin >> 2, g = lin & 3;
            *(uint4*)&Ah[r * 40 + g * 8] =
                *(const uint4*)(MH + (size_t)(ct0 + r) * KK + kc0 + g * 8);
            *(uint4*)&Al[r * 40 + g * 8] =
                *(const uint4*)(ML + (size_t)(ct0 + r) * KK + kc0 + g * 8);
        }
#pragma unroll
        for (int it = 0; it < 2; it++) {
            int lin = tid + it * 256;
            int r = lin >> 2, g = lin & 3;
            *(uint4*)&Bh[r * 40 + g * 8] =
                *(const uint4*)(ZH + (size_t)(p0 + r) * KK + kc0 + g * 8);
            *(uint4*)&Bl[r * 40 + g * 8] =
                *(const uint4*)(ZL + (size_t)(p0 + r) * KK + kc0 + g * 8);
        }
        __syncthreads();
#pragma unroll
        for (int ks = 0; ks < 2; ks++) {
            u32 ah[4][4], al[4][4];
            u32 a_off = (((cb + (lane & 15)) * 40 + ks * 16 + (lane >> 4) * 8)) << 1;
#pragma unroll
            for (int mf = 0; mf < 4; mf++) {
                ldsm4(ah[mf], sah + a_off + mf * (16 * 40 * 2));
                ldsm4(al[mf], sal + a_off + mf * (16 * 40 * 2));
            }
            u32 bh[2][4], bl[2][4];
            u32 brow = pb + ((lane >> 4) & 1) * 8 + (lane & 7);
            u32 bcol = ks * 16 + ((lane >> 3) & 1) * 8;
#pragma unroll
            for (int pr = 0; pr < 2; pr++) {
                u32 boff = ((brow + pr * 16) * 40 + bcol) << 1;
                ldsm4(bh[pr], sbh + boff);
                ldsm4(bl[pr], sbl + boff);
            }
#pragma unroll
            for (int mf = 0; mf < 4; mf++)
#pragma unroll
                for (int nf = 0; nf < 4; nf++) {
                    const u32* bhp = &bh[nf >> 1][(nf & 1) * 2];
                    const u32* blp = &bl[nf >> 1][(nf & 1) * 2];
                    mma_bf16(acc[mf][nf], ah[mf], bhp);
                    mma_bf16(acc[mf][nf], ah[mf], blp);
                    mma_bf16(acc[mf][nf], al[mf], bhp);
                }
        }
        __syncthreads();
    }

    const int g = lane >> 2, tg = lane & 3;
    u16* rh = g_rech + (size_t)b * CC * NP;
    u16* rl = g_recl + (size_t)b * CC * NP;
#pragma unroll
    for (int mf = 0; mf < 4; mf++) {
        int c_lo = ct0 + cb + mf * 16 + g;
        int c_hi = c_lo + 8;
#pragma unroll
        for (int nf = 0; nf < 4; nf++) {
            int pc = p0 + pb + nf * 8 + tg * 2;
            u32 h, l;
            split2h(fmaxf(acc[mf][nf][0], 0.f), fmaxf(acc[mf][nf][1], 0.f), h, l);
            *(u32*)&rh[(size_t)c_lo * NP + pc] = h;
            *(u32*)&rl[(size_t)c_lo * NP + pc] = l;
            split2h(fmaxf(acc[mf][nf][2], 0.f), fmaxf(acc[mf][nf][3], 0.f), h, l);
            *(u32*)&rh[(size_t)c_hi * NP + pc] = h;
            *(u32*)&rl[(size_t)c_hi * NP + pc] = l;
        }
    }
}

// ---------------- launch ----------------------------------------------------
extern "C" void kernel_launch(void* const* d_in, const int* in_sizes, int n_in,
                              void* d_out, int out_size)
{
    (void)in_sizes; (void)n_in; (void)out_size;
    const float* x     = (const float*)d_in[0];
    const float* w1    = (const float*)d_in[1];
    const float* b1    = (const float*)d_in[2];
    const float* mu    = (const float*)d_in[3];
    const float* w2    = (const float*)d_in[4];
    const float* gamma = (const float*)d_in[5];
    const float* beta  = (const float*)d_in[6];
    const float* mean  = (const float*)d_in[7];
    const float* var   = (const float*)d_in[8];
    float* out = (float*)d_out;

    cudaFuncSetAttribute(hconv<0>, cudaFuncAttributeMaxDynamicSharedMemorySize,
                         HCONV_SMEM);
    cudaFuncSetAttribute(hconv<1>, cudaFuncAttributeMaxDynamicSharedMemorySize,
                         HCONV_SMEM);

    kcvt_x<<<(int)(((size_t)BB * CC * NP) / 1024), 256>>>(x);
    kcvt_w<<<(CC * CC) / 512, 256>>>(w1, w2);
    kcvt_mu<<<(CC * KK) / 512, 256>>>(mu);

    hconv<0><<<dim3(NP / 128, CC / 128, BB), 128, HCONV_SMEM>>>(
        nullptr, b1, nullptr, nullptr, nullptr);

    for (int st = 0; st < 3; st++) {
        kz_kernel<<<dim3(NP / 128, BB), 256>>>(st > 0 ? 1 : 0);
        km_kernel<<<dim3(CC / 128, BB, NSPLIT), 256>>>();
        knorm1<<<dim3(8, BB), 256>>>();
        knorm2<<<dim3(8, BB), 256>>>();
    }

    krec_kernel<<<dim3(NP / 128, CC / 128, BB), 256>>>();

    hconv<1><<<dim3(NP / 128, CC / 128, BB), 128, HCONV_SMEM>>>(
        out, gamma, beta, mean, var);
}

// round 10
// speedup vs baseline: 2.7606x; 1.0085x over previous
#include <cuda_runtime.h>
#include <cuda_bf16.h>
#include <cuda_fp16.h>

#define CC 512
#define NP 4096
#define KK 64
#define BB 16
#define NSPLIT 4
#define EPSF 1e-6f

typedef unsigned long long u64;
typedef unsigned int u32;
typedef unsigned short u16;

// ---------------- scratch (static device globals) ---------------------------
__device__ u16 g_xh[(size_t)BB * CC * NP];   // x hi fp16 (b,c,p)
__device__ u16 g_xl[(size_t)BB * CC * NP];   // x lo fp16
__device__ u16 g_wf1[(size_t)CC * CC];       // w1 fp16 single
__device__ u16 g_wf2[(size_t)CC * CC];       // w2 fp16 single
__device__ u16 g_muh[(size_t)CC * KK], g_mul[(size_t)CC * KK];   // bf16
__device__ u16 g_xfh[(size_t)BB * CC * NP];  // conv1 out hi bf16 (b,c,p)
__device__ u16 g_xfl[(size_t)BB * CC * NP];
__device__ u16 g_zh[(size_t)BB * NP * KK];   // z hi bf16 (b,p,k)
__device__ u16 g_zl[(size_t)BB * NP * KK];
__device__ u16 g_mh[(size_t)BB * CC * KK];   // m hi bf16 (b,c,k)
__device__ u16 g_ml[(size_t)BB * CC * KK];
__device__ u16 g_rech[(size_t)BB * CC * NP]; // relu(rec) hi fp16 (b,c,p)
__device__ u16 g_recl[(size_t)BB * CC * NP]; // relu(rec) lo fp16
__device__ float g_mpart[(size_t)NSPLIT * BB * CC * KK];

// ---------------- helpers ----------------------------------------------------
__device__ __forceinline__ u32 smem_u32(const void* p) {
    u32 a;
    asm("{ .reg .u64 t; cvta.to.shared.u64 t, %1; cvt.u32.u64 %0, t; }"
        : "=r"(a) : "l"(p));
    return a;
}
__device__ __forceinline__ void ldsm4(u32* r, u32 addr) {
    asm volatile("ldmatrix.sync.aligned.m8n8.x4.shared.b16 {%0,%1,%2,%3}, [%4];"
                 : "=r"(r[0]), "=r"(r[1]), "=r"(r[2]), "=r"(r[3]) : "r"(addr));
}
__device__ __forceinline__ void ldsm4t(u32* r, u32 addr) {
    asm volatile("ldmatrix.sync.aligned.m8n8.x4.trans.shared.b16 {%0,%1,%2,%3}, [%4];"
                 : "=r"(r[0]), "=r"(r[1]), "=r"(r[2]), "=r"(r[3]) : "r"(addr));
}
__device__ __forceinline__ void mma_bf16(float* d, const u32* a, const u32* b) {
    asm volatile(
        "mma.sync.aligned.m16n8k16.row.col.f32.bf16.bf16.f32 "
        "{%0,%1,%2,%3}, {%4,%5,%6,%7}, {%8,%9}, {%0,%1,%2,%3};"
        : "+f"(d[0]), "+f"(d[1]), "+f"(d[2]), "+f"(d[3])
        : "r"(a[0]), "r"(a[1]), "r"(a[2]), "r"(a[3]), "r"(b[0]), "r"(b[1]));
}
__device__ __forceinline__ void mma_fp16(float* d, const u32* a, const u32* b) {
    asm volatile(
        "mma.sync.aligned.m16n8k16.row.col.f32.f16.f16.f32 "
        "{%0,%1,%2,%3}, {%4,%5,%6,%7}, {%8,%9}, {%0,%1,%2,%3};"
        : "+f"(d[0]), "+f"(d[1]), "+f"(d[2]), "+f"(d[3])
        : "r"(a[0]), "r"(a[1]), "r"(a[2]), "r"(a[3]), "r"(b[0]), "r"(b[1]));
}
__device__ __forceinline__ void split2(float v0, float v1, u32& hi, u32& lo) {
    __nv_bfloat16 h0 = __float2bfloat16_rn(v0);
    __nv_bfloat16 h1 = __float2bfloat16_rn(v1);
    __nv_bfloat16 l0 = __float2bfloat16_rn(v0 - __bfloat162float(h0));
    __nv_bfloat16 l1 = __float2bfloat16_rn(v1 - __bfloat162float(h1));
    hi = (u32)__bfloat16_as_ushort(h0) | ((u32)__bfloat16_as_ushort(h1) << 16);
    lo = (u32)__bfloat16_as_ushort(l0) | ((u32)__bfloat16_as_ushort(l1) << 16);
}
__device__ __forceinline__ void split2h(float v0, float v1, u32& hi, u32& lo) {
    __half h0 = __float2half_rn(v0);
    __half h1 = __float2half_rn(v1);
    __half l0 = __float2half_rn(v0 - __half2float(h0));
    __half l1 = __float2half_rn(v1 - __half2float(h1));
    hi = (u32)__half_as_ushort(h0) | ((u32)__half_as_ushort(h1) << 16);
    lo = (u32)__half_as_ushort(l0) | ((u32)__half_as_ushort(l1) << 16);
}
__device__ __forceinline__ void cpa16(u32 dst, const void* src) {
    asm volatile("cp.async.cg.shared.global [%0], [%1], 16;"
                 :: "r"(dst), "l"(src));
}
#define CPA_COMMIT() asm volatile("cp.async.commit_group;")
#define CPA_WAIT(n)  asm volatile("cp.async.wait_group %0;" :: "n"(n))

// ---------------- convert kernels -------------------------------------------
__global__ void kcvt_x(const float* __restrict__ x)
{
    size_t i4 = ((size_t)blockIdx.x * 256 + threadIdx.x) * 4;
    float4 v = *(const float4*)&x[i4];
    u32 h0, l0, h1, l1;
    split2h(v.x, v.y, h0, l0);
    split2h(v.z, v.w, h1, l1);
    *(uint2*)&g_xh[i4] = make_uint2(h0, h1);
    *(uint2*)&g_xl[i4] = make_uint2(l0, l1);
}
__global__ void kcvt_w(const float* __restrict__ w1, const float* __restrict__ w2)
{
    size_t i2 = ((size_t)blockIdx.x * 256 + threadIdx.x) * 2;
    {
        __half a = __float2half_rn(w1[i2]), b = __float2half_rn(w1[i2 + 1]);
        *(u32*)&g_wf1[i2] = (u32)__half_as_ushort(a) |
                            ((u32)__half_as_ushort(b) << 16);
    }
    {
        __half a = __float2half_rn(w2[i2]), b = __float2half_rn(w2[i2 + 1]);
        *(u32*)&g_wf2[i2] = (u32)__half_as_ushort(a) |
                            ((u32)__half_as_ushort(b) << 16);
    }
}
__global__ void kcvt_mu(const float* __restrict__ mu)
{
    size_t i2 = ((size_t)blockIdx.x * 256 + threadIdx.x) * 2;
    u32 h, l;
    split2(mu[i2], mu[i2 + 1], h, l);
    *(u32*)&g_muh[i2] = h; *(u32*)&g_mul[i2] = l;
}

// ---------------- conv GEMM v5: fp16 2-term, 4-stage cp.async ---------------
#define APITCH 40
#define BPITCH 136
#define AH_OFF 0
#define BH_OFF 10240
#define BL_OFF 18944
#define STAGE_B 27648
#define NSTAGE 4
#define NCH 16
#define HCONV_SMEM (STAGE_B * NSTAGE)

template <int EPI>
__global__ __launch_bounds__(128, 2)
void hconv(float* __restrict__ OUT,
           const float* __restrict__ e0, const float* __restrict__ e1,
           const float* __restrict__ e2, const float* __restrict__ e3)
{
    extern __shared__ __align__(16) char dsm[];
    const u32 sb = smem_u32(dsm);

    const int p0 = blockIdx.x * 128;
    const int o0 = blockIdx.y * 128;
    const int b  = blockIdx.z;
    const int tid = threadIdx.x;
    const int lane = tid & 31, wid = tid >> 5;
    const int ob = (wid & 1) * 64, pb = (wid >> 1) * 64;

    const u16* WH = (EPI == 0) ? g_wf1 : g_wf2;
    const u16* IH = ((EPI == 0) ? g_xh : g_rech) + (size_t)b * CC * NP;
    const u16* IL = ((EPI == 0) ? g_xl : g_recl) + (size_t)b * CC * NP;

    float acc[4][8][4];
#pragma unroll
    for (int mf = 0; mf < 4; mf++)
#pragma unroll
        for (int nf = 0; nf < 8; nf++)
#pragma unroll
            for (int q = 0; q < 4; q++) acc[mf][nf][q] = 0.f;

    const int arow = tid >> 2, au = (tid & 3) * 8;
    const int brow = tid >> 4, bu = (tid & 15) * 8;

#define LOAD_CHUNK(st, c0)                                                      \
    do {                                                                        \
        u32 base = sb + (st) * STAGE_B;                                         \
        _Pragma("unroll")                                                       \
        for (int i = 0; i < 4; i++) {                                           \
            int r = arow + i * 32;                                              \
            cpa16(base + AH_OFF + (r * APITCH + au) * 2,                        \
                  WH + (size_t)(o0 + r) * CC + (c0) + au);                      \
        }                                                                       \
        _Pragma("unroll")                                                       \
        for (int i = 0; i < 4; i++) {                                           \
            int r = brow + i * 8;                                               \
            cpa16(base + BH_OFF + (r * BPITCH + bu) * 2,                        \
                  IH + (size_t)((c0) + r) * NP + p0 + bu);                      \
            cpa16(base + BL_OFF + (r * BPITCH + bu) * 2,                        \
                  IL + (size_t)((c0) + r) * NP + p0 + bu);                      \
        }                                                                       \
        CPA_COMMIT();                                                           \
    } while (0)

    LOAD_CHUNK(0, 0);
    LOAD_CHUNK(1, 32);
    LOAD_CHUNK(2, 64);

    const u32 a_lane = ((ob + (lane & 15)) * APITCH + (lane >> 4) * 8) * 2;
    const u32 b_rbase = (lane & 7) + ((lane >> 3) & 1) * 8;
    const u32 b_col   = pb + ((lane >> 4) & 1) * 8;

    for (int ch = 0; ch < NCH; ch++) {
        if (ch < NCH - 2)      { CPA_WAIT(2); }
        else if (ch == NCH - 2){ CPA_WAIT(1); }
        else                   { CPA_WAIT(0); }
        __syncthreads();
        if (ch < NCH - 3) LOAD_CHUNK((ch + 3) % NSTAGE, (ch + 3) * 32);

        const u32 stb = sb + (ch % NSTAGE) * STAGE_B;
#pragma unroll
        for (int ks = 0; ks < 2; ks++) {
            u32 ah[4][4];
            const u32 abase = stb + a_lane + ks * 32;
#pragma unroll
            for (int mf = 0; mf < 4; mf++)
                ldsm4(ah[mf], abase + AH_OFF + mf * (16 * APITCH * 2));
            const u32 brow = ks * 16 + b_rbase;
            const u32 bbase = stb + (brow * BPITCH + b_col) * 2;
#pragma unroll
            for (int pr = 0; pr < 4; pr++) {
                u32 bh[4], bl[4];
                ldsm4t(bh, bbase + BH_OFF + pr * 32);
                ldsm4t(bl, bbase + BL_OFF + pr * 32);
#pragma unroll
                for (int mf = 0; mf < 4; mf++) {
#pragma unroll
                    for (int hn = 0; hn < 2; hn++) {
                        float* a = acc[mf][pr * 2 + hn];
                        mma_fp16(a, ah[mf], &bh[hn * 2]);
                        mma_fp16(a, ah[mf], &bl[hn * 2]);
                    }
                }
            }
        }
    }

    const int g = lane >> 2, tg = lane & 3;
#pragma unroll
    for (int mf = 0; mf < 4; mf++) {
        int o_lo = o0 + ob + mf * 16 + g;
        int o_hi = o_lo + 8;
        if (EPI == 0) {
            float add_lo = e0[o_lo], add_hi = e0[o_hi];
            u16* xfh = g_xfh + (size_t)b * CC * NP;
            u16* xfl = g_xfl + (size_t)b * CC * NP;
#pragma unroll
            for (int nf = 0; nf < 8; nf++) {
                int pc = p0 + pb + nf * 8 + tg * 2;
                u32 h, l;
                split2(acc[mf][nf][0] + add_lo, acc[mf][nf][1] + add_lo, h, l);
                *(u32*)&xfh[(size_t)o_lo * NP + pc] = h;
                *(u32*)&xfl[(size_t)o_lo * NP + pc] = l;
                split2(acc[mf][nf][2] + add_hi, acc[mf][nf][3] + add_hi, h, l);
                *(u32*)&xfh[(size_t)o_hi * NP + pc] = h;
                *(u32*)&xfl[(size_t)o_hi * NP + pc] = l;
            }
        } else {
            float mul_lo = e0[o_lo] * rsqrtf(e3[o_lo] + 1e-5f);
            float add_lo = e1[o_lo] - e2[o_lo] * mul_lo;
            float mul_hi = e0[o_hi] * rsqrtf(e3[o_hi] + 1e-5f);
            float add_hi = e1[o_hi] - e2[o_hi] * mul_hi;
            float* outb = OUT + (size_t)b * CC * NP;
#pragma unroll
            for (int nf = 0; nf < 8; nf++) {
                int pc = p0 + pb + nf * 8 + tg * 2;
                float2 v0, v1;
                v0.x = acc[mf][nf][0] * mul_lo + add_lo;
                v0.y = acc[mf][nf][1] * mul_lo + add_lo;
                v1.x = acc[mf][nf][2] * mul_hi + add_hi;
                v1.y = acc[mf][nf][3] * mul_hi + add_hi;
                *(float2*)&outb[(size_t)o_lo * NP + pc] = v0;
                *(float2*)&outb[(size_t)o_hi * NP + pc] = v1;
            }
        }
    }
#undef LOAD_CHUNK
}

// ---------------- kz: z = softmax_k( xf^T @ m ), reg-prefetch pipeline ------
__global__ __launch_bounds__(256, 2)
void kz_kernel(int use_gm)
{
    __shared__ __align__(16) u16 Xh[32 * 136], Xl[32 * 136]; // (c32, p128)
    __shared__ __align__(16) u16 Mh[32 * 72],  Ml[32 * 72];  // (c32, k64)

    const int p0 = blockIdx.x * 128;
    const int b  = blockIdx.y;
    const int tid = threadIdx.x;
    const int lane = tid & 31, wid = tid >> 5;
    const int pw = wid * 16;

    const u16* XH = g_xfh + (size_t)b * CC * NP;
    const u16* XL = g_xfl + (size_t)b * CC * NP;
    const u16* MH = use_gm ? (g_mh + (size_t)b * CC * KK) : g_muh;
    const u16* ML = use_gm ? (g_ml + (size_t)b * CC * KK) : g_mul;

    float acc[8][4];
#pragma unroll
    for (int nf = 0; nf < 8; nf++)
#pragma unroll
        for (int q = 0; q < 4; q++) acc[nf][q] = 0.f;

    const u32 sxh = smem_u32(Xh), sxl = smem_u32(Xl);
    const u32 smh = smem_u32(Mh), sml = smem_u32(Ml);

    const int xr0 = tid >> 4,           xg0 = (tid & 15) * 8;
    const int xr1 = (tid + 256) >> 4,   xg1 = (tid & 15) * 8;
    const int mr  = tid >> 3,           mg  = (tid & 7) * 8;

    uint4 pxh[2], pxl[2], pmh, pml;
#define KZ_PREFETCH(c0)                                                        \
    do {                                                                       \
        pxh[0] = *(const uint4*)(XH + (size_t)((c0) + xr0) * NP + p0 + xg0);   \
        pxh[1] = *(const uint4*)(XH + (size_t)((c0) + xr1) * NP + p0 + xg1);   \
        pxl[0] = *(const uint4*)(XL + (size_t)((c0) + xr0) * NP + p0 + xg0);   \
        pxl[1] = *(const uint4*)(XL + (size_t)((c0) + xr1) * NP + p0 + xg1);   \
        pmh    = *(const uint4*)(MH + (size_t)((c0) + mr) * KK + mg);          \
        pml    = *(const uint4*)(ML + (size_t)((c0) + mr) * KK + mg);          \
    } while (0)

    KZ_PREFETCH(0);

    for (int c0 = 0; c0 < CC; c0 += 32) {
        __syncthreads();
        *(uint4*)&Xh[xr0 * 136 + xg0] = pxh[0];
        *(uint4*)&Xh[xr1 * 136 + xg1] = pxh[1];
        *(uint4*)&Xl[xr0 * 136 + xg0] = pxl[0];
        *(uint4*)&Xl[xr1 * 136 + xg1] = pxl[1];
        *(uint4*)&Mh[mr * 72 + mg] = pmh;
        *(uint4*)&Ml[mr * 72 + mg] = pml;
        __syncthreads();
        if (c0 + 32 < CC) KZ_PREFETCH(c0 + 32);

#pragma unroll
        for (int ks = 0; ks < 2; ks++) {
            u32 ah[4], al[4];
            {
                u32 row = ks * 16 + (lane & 7) + ((lane >> 4) & 1) * 8;
                u32 col = pw + ((lane >> 3) & 1) * 8;
                u32 off = (row * 136 + col) << 1;
                ldsm4t(ah, sxh + off);
                ldsm4t(al, sxl + off);
            }
            u32 bh[4][4], bl[4][4];
            {
                u32 row = ks * 16 + (lane & 7) + ((lane >> 3) & 1) * 8;
                u32 col = ((lane >> 4) & 1) * 8;
#pragma unroll
                for (int pr = 0; pr < 4; pr++) {
                    u32 off = (row * 72 + col + pr * 16) << 1;
                    ldsm4t(bh[pr], smh + off);
                    ldsm4t(bl[pr], sml + off);
                }
            }
#pragma unroll
            for (int nf = 0; nf < 8; nf++) {
                const u32* bhp = &bh[nf >> 1][(nf & 1) * 2];
                const u32* blp = &bl[nf >> 1][(nf & 1) * 2];
                mma_bf16(acc[nf], ah, bhp);
                mma_bf16(acc[nf], ah, blp);
                mma_bf16(acc[nf], al, bhp);
            }
        }
    }
#undef KZ_PREFETCH

    const int gr = lane >> 2;
    float mx0 = -1e30f, mx1 = -1e30f;
#pragma unroll
    for (int nf = 0; nf < 8; nf++) {
        mx0 = fmaxf(mx0, fmaxf(acc[nf][0], acc[nf][1]));
        mx1 = fmaxf(mx1, fmaxf(acc[nf][2], acc[nf][3]));
    }
#pragma unroll
    for (int s = 1; s < 4; s <<= 1) {
        mx0 = fmaxf(mx0, __shfl_xor_sync(0xffffffffu, mx0, s));
        mx1 = fmaxf(mx1, __shfl_xor_sync(0xffffffffu, mx1, s));
    }
    float sm0 = 0.f, sm1 = 0.f;
#pragma unroll
    for (int nf = 0; nf < 8; nf++) {
        acc[nf][0] = expf(acc[nf][0] - mx0); sm0 += acc[nf][0];
        acc[nf][1] = expf(acc[nf][1] - mx0); sm0 += acc[nf][1];
        acc[nf][2] = expf(acc[nf][2] - mx1); sm1 += acc[nf][2];
        acc[nf][3] = expf(acc[nf][3] - mx1); sm1 += acc[nf][3];
    }
#pragma unroll
    for (int s = 1; s < 4; s <<= 1) {
        sm0 += __shfl_xor_sync(0xffffffffu, sm0, s);
        sm1 += __shfl_xor_sync(0xffffffffu, sm1, s);
    }
    float inv0 = 1.f / sm0, inv1 = 1.f / sm1;
    const int tg = lane & 3;
    size_t prow_lo = (size_t)(b * NP + p0 + pw + gr) * KK;
    size_t prow_hi = prow_lo + (size_t)8 * KK;
#pragma unroll
    for (int nf = 0; nf < 8; nf++) {
        int kc = nf * 8 + tg * 2;
        u32 h, l;
        split2(acc[nf][0] * inv0, acc[nf][1] * inv0, h, l);
        *(u32*)&g_zh[prow_lo + kc] = h;
        *(u32*)&g_zl[prow_lo + kc] = l;
        split2(acc[nf][2] * inv1, acc[nf][3] * inv1, h, l);
        *(u32*)&g_zh[prow_hi + kc] = h;
        *(u32*)&g_zl[prow_hi + kc] = l;
    }
}

// ---------------- km: mpart = xf @ z (split-K over p), reg-prefetch ---------
__global__ __launch_bounds__(256, 2)
void km_kernel()
{
    __shared__ __align__(16) u16 Ah[128 * 40], Al[128 * 40]; // (c128, p32)
    __shared__ __align__(16) u16 Zh[32 * 72],  Zl[32 * 72];  // (p32, k64)

    const int ct0 = blockIdx.x * 128;
    const int b   = blockIdx.y;
    const int s   = blockIdx.z;
    const int ps0 = s * (NP / NSPLIT);
    const int tid = threadIdx.x;
    const int lane = tid & 31, wid = tid >> 5;

    const u16* XH = g_xfh + (size_t)b * CC * NP;
    const u16* XL = g_xfl + (size_t)b * CC * NP;
    const u16* ZH = g_zh + (size_t)b * NP * KK;
    const u16* ZL = g_zl + (size_t)b * NP * KK;

    float acc[8][4];
#pragma unroll
    for (int nf = 0; nf < 8; nf++)
#pragma unroll
        for (int q = 0; q < 4; q++) acc[nf][q] = 0.f;

    const u32 sah = smem_u32(Ah), sal = smem_u32(Al);
    const u32 szh = smem_u32(Zh), szl = smem_u32(Zl);

    const int ar0 = tid >> 2,         ag0 = (tid & 3) * 8;
    const int ar1 = (tid + 256) >> 2, ag1 = (tid & 3) * 8;
    const int zr  = tid >> 3,         zg  = (tid & 7) * 8;

    uint4 pah[2], pal[2], pzh, pzl;
#define KM_PREFETCH(pc0)                                                       \
    do {                                                                       \
        pah[0] = *(const uint4*)(XH + (size_t)(ct0 + ar0) * NP + (pc0) + ag0); \
        pah[1] = *(const uint4*)(XH + (size_t)(ct0 + ar1) * NP + (pc0) + ag1); \
        pal[0] = *(const uint4*)(XL + (size_t)(ct0 + ar0) * NP + (pc0) + ag0); \
        pal[1] = *(const uint4*)(XL + (size_t)(ct0 + ar1) * NP + (pc0) + ag1); \
        pzh    = *(const uint4*)(ZH + (size_t)((pc0) + zr) * KK + zg);         \
        pzl    = *(const uint4*)(ZL + (size_t)((pc0) + zr) * KK + zg);         \
    } while (0)

    KM_PREFETCH(ps0);

    for (int pc0 = ps0; pc0 < ps0 + NP / NSPLIT; pc0 += 32) {
        __syncthreads();
        *(uint4*)&Ah[ar0 * 40 + ag0] = pah[0];
        *(uint4*)&Ah[ar1 * 40 + ag1] = pah[1];
        *(uint4*)&Al[ar0 * 40 + ag0] = pal[0];
        *(uint4*)&Al[ar1 * 40 + ag1] = pal[1];
        *(uint4*)&Zh[zr * 72 + zg] = pzh;
        *(uint4*)&Zl[zr * 72 + zg] = pzl;
        __syncthreads();
        if (pc0 + 32 < ps0 + NP / NSPLIT) KM_PREFETCH(pc0 + 32);

#pragma unroll
        for (int ks = 0; ks < 2; ks++) {
            u32 ah[4], al[4];
            {
                u32 off = (((wid * 16 + (lane & 15)) * 40 +
                            ks * 16 + (lane >> 4) * 8)) << 1;
                ldsm4(ah, sah + off);
                ldsm4(al, sal + off);
            }
            u32 bh[4][4], bl[4][4];
            {
                u32 row = ks * 16 + (lane & 7) + ((lane >> 3) & 1) * 8;
                u32 col = ((lane >> 4) & 1) * 8;
#pragma unroll
                for (int pr = 0; pr < 4; pr++) {
                    u32 off = (row * 72 + col + pr * 16) << 1;
                    ldsm4t(bh[pr], szh + off);
                    ldsm4t(bl[pr], szl + off);
                }
            }
#pragma unroll
            for (int nf = 0; nf < 8; nf++) {
                const u32* bhp = &bh[nf >> 1][(nf & 1) * 2];
                const u32* blp = &bl[nf >> 1][(nf & 1) * 2];
                mma_bf16(acc[nf], ah, bhp);
                mma_bf16(acc[nf], ah, blp);
                mma_bf16(acc[nf], al, bhp);
            }
        }
    }
#undef KM_PREFETCH

    const int gr = lane >> 2, tg = lane & 3;
    float* out = g_mpart + ((size_t)(s * BB + b) * CC + ct0 + wid * 16) * KK;
#pragma unroll
    for (int nf = 0; nf < 8; nf++) {
        int kc = nf * 8 + tg * 2;
        *(float2*)&out[(size_t)gr * KK + kc] =
            make_float2(acc[nf][0], acc[nf][1]);
        *(float2*)&out[(size_t)(gr + 8) * KK + kc] =
            make_float2(acc[nf][2], acc[nf][3]);
    }
}

// ---------------- fused norm: split-reduce + L2 norm + bf16 split -----------
// grid = (BB), 1024 threads. thread = (cg = tid>>6 in [0,16), k = tid&63).
// Each thread reduces 32 c-rows across NSPLIT partials in registers,
// contributes sum-of-squares, then scales and writes g_mh/g_ml directly.
__global__ __launch_bounds__(1024)
void knorm_fused()
{
    const int b = blockIdx.x;
    const int tid = threadIdx.x;
    const int k  = tid & 63;
    const int cg = tid >> 6;            // 0..15, each owns 32 c-rows

    __shared__ float red[16][64];
    __shared__ float sinv[64];

    const size_t base = (size_t)b * CC * KK;
    float v[32];
    float ss = 0.f;
#pragma unroll
    for (int i = 0; i < 32; i++) {
        size_t off = base + (size_t)(cg * 32 + i) * KK + k;
        float t = 0.f;
#pragma unroll
        for (int s = 0; s < NSPLIT; s++)
            t += g_mpart[(size_t)s * (BB * CC * KK) + off];
        v[i] = t;
        ss += t * t;
    }
    red[cg][k] = ss;
    __syncthreads();
    if (cg == 0) {
        float s = 0.f;
#pragma unroll
        for (int g2 = 0; g2 < 16; g2++) s += red[g2][k];
        sinv[k] = 1.f / (EPSF + sqrtf(s));
    }
    __syncthreads();
    const float inv = sinv[k];
    u16* mh = g_mh + base;
    u16* ml = g_ml + base;
#pragma unroll
    for (int i = 0; i < 32; i++) {
        float sv = v[i] * inv;
        __nv_bfloat16 h = __float2bfloat16_rn(sv);
        __nv_bfloat16 l = __float2bfloat16_rn(sv - __bfloat162float(h));
        size_t off = (size_t)(cg * 32 + i) * KK + k;
        mh[off] = __bfloat16_as_ushort(h);
        ml[off] = __bfloat16_as_ushort(l);
    }
}

// ---------------- krec: rec = relu(m @ z^T) -> fp16 hi/lo (c,p) --------------
__global__ __launch_bounds__(256, 2)
void krec_kernel()
{
    __shared__ __align__(16) u16 Ah[128 * 40], Al[128 * 40]; // (c128, k32)
    __shared__ __align__(16) u16 Bh[128 * 40], Bl[128 * 40]; // (p128, k32)

    const int p0  = blockIdx.x * 128;
    const int ct0 = blockIdx.y * 128;
    const int b   = blockIdx.z;
    const int tid = threadIdx.x;
    const int lane = tid & 31, wid = tid >> 5;
    const int wm = wid & 1, wn = wid >> 1;
    const int cb = wm * 64, pb = wn * 32;

    const u16* MH = g_mh + (size_t)b * CC * KK;
    const u16* ML = g_ml + (size_t)b * CC * KK;
    const u16* ZH = g_zh + (size_t)b * NP * KK;
    const u16* ZL = g_zl + (size_t)b * NP * KK;

    float acc[4][4][4];
#pragma unroll
    for (int mf = 0; mf < 4; mf++)
#pragma unroll
        for (int nf = 0; nf < 4; nf++)
#pragma unroll
            for (int q = 0; q < 4; q++) acc[mf][nf][q] = 0.f;

    const u32 sah = smem_u32(Ah), sal = smem_u32(Al);
    const u32 sbh = smem_u32(Bh), sbl = smem_u32(Bl);

    for (int kc0 = 0; kc0 < KK; kc0 += 32) {
#pragma unroll
        for (int it = 0; it < 2; it++) {
            int lin = tid + it * 256;
            int r = lin >> 2, g = lin & 3;
            *(uint4*)&Ah[r * 40 + g * 8] =
                *(const uint4*)(MH + (size_t)(ct0 + r) * KK + kc0 + g * 8);
            *(uint4*)&Al[r * 40 + g * 8] =
                *(const uint4*)(ML + (size_t)(ct0 + r) * KK + kc0 + g * 8);
        }
#pragma unroll
        for (int it = 0; it < 2; it++) {
            int lin = tid + it * 256;
            int r = lin >> 2, g = lin & 3;
            *(uint4*)&Bh[r * 40 + g * 8] =
                *(const uint4*)(ZH + (size_t)(p0 + r) * KK + kc0 + g * 8);
            *(uint4*)&Bl[r * 40 + g * 8] =
                *(const uint4*)(ZL + (size_t)(p0 + r) * KK + kc0 + g * 8);
        }
        __syncthreads();
#pragma unroll
        for (int ks = 0; ks < 2; ks++) {
            u32 ah[4][4], al[4][4];
            u32 a_off = (((cb + (lane & 15)) * 40 + ks * 16 + (lane >> 4) * 8)) << 1;
#pragma unroll
            for (int mf = 0; mf < 4; mf++) {
                ldsm4(ah[mf], sah + a_off + mf * (16 * 40 * 2));
                ldsm4(al[mf], sal + a_off + mf * (16 * 40 * 2));
            }
            u32 bh[2][4], bl[2][4];
            u32 brow = pb + ((lane >> 4) & 1) * 8 + (lane & 7);
            u32 bcol = ks * 16 + ((lane >> 3) & 1) * 8;
#pragma unroll
            for (int pr = 0; pr < 2; pr++) {
                u32 boff = ((brow + pr * 16) * 40 + bcol) << 1;
                ldsm4(bh[pr], sbh + boff);
                ldsm4(bl[pr], sbl + boff);
            }
#pragma unroll
            for (int mf = 0; mf < 4; mf++)
#pragma unroll
                for (int nf = 0; nf < 4; nf++) {
                    const u32* bhp = &bh[nf >> 1][(nf & 1) * 2];
                    const u32* blp = &bl[nf >> 1][(nf & 1) * 2];
                    mma_bf16(acc[mf][nf], ah[mf], bhp);
                    mma_bf16(acc[mf][nf], ah[mf], blp);
                    mma_bf16(acc[mf][nf], al[mf], bhp);
                }
        }
        __syncthreads();
    }

    const int g = lane >> 2, tg = lane & 3;
    u16* rh = g_rech + (size_t)b * CC * NP;
    u16* rl = g_recl + (size_t)b * CC * NP;
#pragma unroll
    for (int mf = 0; mf < 4; mf++) {
        int c_lo = ct0 + cb + mf * 16 + g;
        int c_hi = c_lo + 8;
#pragma unroll
        for (int nf = 0; nf < 4; nf++) {
            int pc = p0 + pb + nf * 8 + tg * 2;
            u32 h, l;
            split2h(fmaxf(acc[mf][nf][0], 0.f), fmaxf(acc[mf][nf][1], 0.f), h, l);
            *(u32*)&rh[(size_t)c_lo * NP + pc] = h;
            *(u32*)&rl[(size_t)c_lo * NP + pc] = l;
            split2h(fmaxf(acc[mf][nf][2], 0.f), fmaxf(acc[mf][nf][3], 0.f), h, l);
            *(u32*)&rh[(size_t)c_hi * NP + pc] = h;
            *(u32*)&rl[(size_t)c_hi * NP + pc] = l;
        }
    }
}

// ---------------- launch ----------------------------------------------------
extern "C" void kernel_launch(void* const* d_in, const int* in_sizes, int n_in,
                              void* d_out, int out_size)
{
    (void)in_sizes; (void)n_in; (void)out_size;
    const float* x     = (const float*)d_in[0];
    const float* w1    = (const float*)d_in[1];
    const float* b1    = (const float*)d_in[2];
    const float* mu    = (const float*)d_in[3];
    const float* w2    = (const float*)d_in[4];
    const float* gamma = (const float*)d_in[5];
    const float* beta  = (const float*)d_in[6];
    const float* mean  = (const float*)d_in[7];
    const float* var   = (const float*)d_in[8];
    float* out = (float*)d_out;

    cudaFuncSetAttribute(hconv<0>, cudaFuncAttributeMaxDynamicSharedMemorySize,
                         HCONV_SMEM);
    cudaFuncSetAttribute(hconv<1>, cudaFuncAttributeMaxDynamicSharedMemorySize,
                         HCONV_SMEM);

    kcvt_x<<<(int)(((size_t)BB * CC * NP) / 1024), 256>>>(x);
    kcvt_w<<<(CC * CC) / 512, 256>>>(w1, w2);
    kcvt_mu<<<(CC * KK) / 512, 256>>>(mu);

    hconv<0><<<dim3(NP / 128, CC / 128, BB), 128, HCONV_SMEM>>>(
        nullptr, b1, nullptr, nullptr, nullptr);

    for (int st = 0; st < 3; st++) {
        kz_kernel<<<dim3(NP / 128, BB), 256>>>(st > 0 ? 1 : 0);
        km_kernel<<<dim3(CC / 128, BB, NSPLIT), 256>>>();
        knorm_fused<<<BB, 1024>>>();
    }

    krec_kernel<<<dim3(NP / 128, CC / 128, BB), 256>>>();

    hconv<1><<<dim3(NP / 128, CC / 128, BB), 128, HCONV_SMEM>>>(
        out, gamma, beta, mean, var);
}

// round 11
// speedup vs baseline: 2.8185x; 1.0210x over previous
#include <cuda_runtime.h>
#include <cuda_bf16.h>
#include <cuda_fp16.h>

#define CC 512
#define NP 4096
#define KK 64
#define BB 16
#define NSPLIT 4
#define EPSF 1e-6f

typedef unsigned long long u64;
typedef unsigned int u32;
typedef unsigned short u16;

// ---------------- scratch (static device globals) ---------------------------
__device__ u16 g_xh[(size_t)BB * CC * NP];   // x hi fp16 (b,c,p)
__device__ u16 g_xl[(size_t)BB * CC * NP];   // x lo fp16
__device__ u16 g_wf1[(size_t)CC * CC];       // w1 fp16 single
__device__ u16 g_wf2[(size_t)CC * CC];       // w2 fp16 single
__device__ u16 g_muh[(size_t)CC * KK], g_mul[(size_t)CC * KK];   // bf16
__device__ u16 g_xfh[(size_t)BB * CC * NP];  // conv1 out hi bf16 (b,c,p)
__device__ u16 g_xfl[(size_t)BB * CC * NP];
__device__ u16 g_zh[(size_t)BB * NP * KK];   // z hi bf16 (b,p,k)
__device__ u16 g_zl[(size_t)BB * NP * KK];
__device__ u16 g_mh[(size_t)BB * CC * KK];   // m hi bf16 (b,c,k)
__device__ u16 g_ml[(size_t)BB * CC * KK];
__device__ u16 g_rech[(size_t)BB * CC * NP]; // relu(rec) hi fp16 (b,c,p)
__device__ u16 g_recl[(size_t)BB * CC * NP]; // relu(rec) lo fp16
__device__ float g_mpart[(size_t)NSPLIT * BB * CC * KK];

// ---------------- helpers ----------------------------------------------------
__device__ __forceinline__ u32 smem_u32(const void* p) {
    u32 a;
    asm("{ .reg .u64 t; cvta.to.shared.u64 t, %1; cvt.u32.u64 %0, t; }"
        : "=r"(a) : "l"(p));
    return a;
}
__device__ __forceinline__ void ldsm4(u32* r, u32 addr) {
    asm volatile("ldmatrix.sync.aligned.m8n8.x4.shared.b16 {%0,%1,%2,%3}, [%4];"
                 : "=r"(r[0]), "=r"(r[1]), "=r"(r[2]), "=r"(r[3]) : "r"(addr));
}
__device__ __forceinline__ void ldsm4t(u32* r, u32 addr) {
    asm volatile("ldmatrix.sync.aligned.m8n8.x4.trans.shared.b16 {%0,%1,%2,%3}, [%4];"
                 : "=r"(r[0]), "=r"(r[1]), "=r"(r[2]), "=r"(r[3]) : "r"(addr));
}
__device__ __forceinline__ void mma_bf16(float* d, const u32* a, const u32* b) {
    asm volatile(
        "mma.sync.aligned.m16n8k16.row.col.f32.bf16.bf16.f32 "
        "{%0,%1,%2,%3}, {%4,%5,%6,%7}, {%8,%9}, {%0,%1,%2,%3};"
        : "+f"(d[0]), "+f"(d[1]), "+f"(d[2]), "+f"(d[3])
        : "r"(a[0]), "r"(a[1]), "r"(a[2]), "r"(a[3]), "r"(b[0]), "r"(b[1]));
}
__device__ __forceinline__ void mma_fp16(float* d, const u32* a, const u32* b) {
    asm volatile(
        "mma.sync.aligned.m16n8k16.row.col.f32.f16.f16.f32 "
        "{%0,%1,%2,%3}, {%4,%5,%6,%7}, {%8,%9}, {%0,%1,%2,%3};"
        : "+f"(d[0]), "+f"(d[1]), "+f"(d[2]), "+f"(d[3])
        : "r"(a[0]), "r"(a[1]), "r"(a[2]), "r"(a[3]), "r"(b[0]), "r"(b[1]));
}
__device__ __forceinline__ void split2(float v0, float v1, u32& hi, u32& lo) {
    __nv_bfloat16 h0 = __float2bfloat16_rn(v0);
    __nv_bfloat16 h1 = __float2bfloat16_rn(v1);
    __nv_bfloat16 l0 = __float2bfloat16_rn(v0 - __bfloat162float(h0));
    __nv_bfloat16 l1 = __float2bfloat16_rn(v1 - __bfloat162float(h1));
    hi = (u32)__bfloat16_as_ushort(h0) | ((u32)__bfloat16_as_ushort(h1) << 16);
    lo = (u32)__bfloat16_as_ushort(l0) | ((u32)__bfloat16_as_ushort(l1) << 16);
}
__device__ __forceinline__ void split2h(float v0, float v1, u32& hi, u32& lo) {
    __half h0 = __float2half_rn(v0);
    __half h1 = __float2half_rn(v1);
    __half l0 = __float2half_rn(v0 - __half2float(h0));
    __half l1 = __float2half_rn(v1 - __half2float(h1));
    hi = (u32)__half_as_ushort(h0) | ((u32)__half_as_ushort(h1) << 16);
    lo = (u32)__half_as_ushort(l0) | ((u32)__half_as_ushort(l1) << 16);
}
__device__ __forceinline__ void cpa16(u32 dst, const void* src) {
    asm volatile("cp.async.cg.shared.global [%0], [%1], 16;"
                 :: "r"(dst), "l"(src));
}
#define CPA_COMMIT() asm volatile("cp.async.commit_group;")
#define CPA_WAIT(n)  asm volatile("cp.async.wait_group %0;" :: "n"(n))

// ---------------- fused convert kernel (x + w1/w2 + mu in one launch) -------
#define XBLOCKS 32768          // BB*CC*NP / 1024
#define WBLOCKS 512            // CC*CC / 512
#define MUBLOCKS 64            // CC*KK / 512
__global__ void kcvt_all(const float* __restrict__ x,
                         const float* __restrict__ w1,
                         const float* __restrict__ w2,
                         const float* __restrict__ mu)
{
    int bx = blockIdx.x;
    if (bx < XBLOCKS) {
        size_t i4 = ((size_t)bx * 256 + threadIdx.x) * 4;
        float4 v = *(const float4*)&x[i4];
        u32 h0, l0, h1, l1;
        split2h(v.x, v.y, h0, l0);
        split2h(v.z, v.w, h1, l1);
        *(uint2*)&g_xh[i4] = make_uint2(h0, h1);
        *(uint2*)&g_xl[i4] = make_uint2(l0, l1);
    } else if (bx < XBLOCKS + WBLOCKS) {
        size_t i2 = ((size_t)(bx - XBLOCKS) * 256 + threadIdx.x) * 2;
        {
            __half a = __float2half_rn(w1[i2]), b = __float2half_rn(w1[i2 + 1]);
            *(u32*)&g_wf1[i2] = (u32)__half_as_ushort(a) |
                                ((u32)__half_as_ushort(b) << 16);
        }
        {
            __half a = __float2half_rn(w2[i2]), b = __float2half_rn(w2[i2 + 1]);
            *(u32*)&g_wf2[i2] = (u32)__half_as_ushort(a) |
                                ((u32)__half_as_ushort(b) << 16);
        }
    } else {
        size_t i2 = ((size_t)(bx - XBLOCKS - WBLOCKS) * 256 + threadIdx.x) * 2;
        u32 h, l;
        split2(mu[i2], mu[i2 + 1], h, l);
        *(u32*)&g_muh[i2] = h; *(u32*)&g_mul[i2] = l;
    }
}

// ---------------- conv GEMM v5: fp16 2-term, 4-stage cp.async ---------------
#define APITCH 40
#define BPITCH 136
#define AH_OFF 0
#define BH_OFF 10240
#define BL_OFF 18944
#define STAGE_B 27648
#define NSTAGE 4
#define NCH 16
#define HCONV_SMEM (STAGE_B * NSTAGE)

template <int EPI>
__global__ __launch_bounds__(128, 2)
void hconv(float* __restrict__ OUT,
           const float* __restrict__ e0, const float* __restrict__ e1,
           const float* __restrict__ e2, const float* __restrict__ e3)
{
    extern __shared__ __align__(16) char dsm[];
    const u32 sb = smem_u32(dsm);

    const int p0 = blockIdx.x * 128;
    const int o0 = blockIdx.y * 128;
    const int b  = blockIdx.z;
    const int tid = threadIdx.x;
    const int lane = tid & 31, wid = tid >> 5;
    const int ob = (wid & 1) * 64, pb = (wid >> 1) * 64;

    const u16* WH = (EPI == 0) ? g_wf1 : g_wf2;
    const u16* IH = ((EPI == 0) ? g_xh : g_rech) + (size_t)b * CC * NP;
    const u16* IL = ((EPI == 0) ? g_xl : g_recl) + (size_t)b * CC * NP;

    float acc[4][8][4];
#pragma unroll
    for (int mf = 0; mf < 4; mf++)
#pragma unroll
        for (int nf = 0; nf < 8; nf++)
#pragma unroll
            for (int q = 0; q < 4; q++) acc[mf][nf][q] = 0.f;

    const int arow = tid >> 2, au = (tid & 3) * 8;
    const int brow = tid >> 4, bu = (tid & 15) * 8;

#define LOAD_CHUNK(st, c0)                                                      \
    do {                                                                        \
        u32 base = sb + (st) * STAGE_B;                                         \
        _Pragma("unroll")                                                       \
        for (int i = 0; i < 4; i++) {                                           \
            int r = arow + i * 32;                                              \
            cpa16(base + AH_OFF + (r * APITCH + au) * 2,                        \
                  WH + (size_t)(o0 + r) * CC + (c0) + au);                      \
        }                                                                       \
        _Pragma("unroll")                                                       \
        for (int i = 0; i < 4; i++) {                                           \
            int r = brow + i * 8;                                               \
            cpa16(base + BH_OFF + (r * BPITCH + bu) * 2,                        \
                  IH + (size_t)((c0) + r) * NP + p0 + bu);                      \
            cpa16(base + BL_OFF + (r * BPITCH + bu) * 2,                        \
                  IL + (size_t)((c0) + r) * NP + p0 + bu);                      \
        }                                                                       \
        CPA_COMMIT();                                                           \
    } while (0)

    LOAD_CHUNK(0, 0);
    LOAD_CHUNK(1, 32);
    LOAD_CHUNK(2, 64);

    const u32 a_lane = ((ob + (lane & 15)) * APITCH + (lane >> 4) * 8) * 2;
    const u32 b_rbase = (lane & 7) + ((lane >> 3) & 1) * 8;
    const u32 b_col   = pb + ((lane >> 4) & 1) * 8;

    for (int ch = 0; ch < NCH; ch++) {
        if (ch < NCH - 2)      { CPA_WAIT(2); }
        else if (ch == NCH - 2){ CPA_WAIT(1); }
        else                   { CPA_WAIT(0); }
        __syncthreads();
        if (ch < NCH - 3) LOAD_CHUNK((ch + 3) % NSTAGE, (ch + 3) * 32);

        const u32 stb = sb + (ch % NSTAGE) * STAGE_B;
#pragma unroll
        for (int ks = 0; ks < 2; ks++) {
            u32 ah[4][4];
            const u32 abase = stb + a_lane + ks * 32;
#pragma unroll
            for (int mf = 0; mf < 4; mf++)
                ldsm4(ah[mf], abase + AH_OFF + mf * (16 * APITCH * 2));
            const u32 brow = ks * 16 + b_rbase;
            const u32 bbase = stb + (brow * BPITCH + b_col) * 2;
#pragma unroll
            for (int pr = 0; pr < 4; pr++) {
                u32 bh[4], bl[4];
                ldsm4t(bh, bbase + BH_OFF + pr * 32);
                ldsm4t(bl, bbase + BL_OFF + pr * 32);
#pragma unroll
                for (int mf = 0; mf < 4; mf++) {
#pragma unroll
                    for (int hn = 0; hn < 2; hn++) {
                        float* a = acc[mf][pr * 2 + hn];
                        mma_fp16(a, ah[mf], &bh[hn * 2]);
                        mma_fp16(a, ah[mf], &bl[hn * 2]);
                    }
                }
            }
        }
    }

    const int g = lane >> 2, tg = lane & 3;
#pragma unroll
    for (int mf = 0; mf < 4; mf++) {
        int o_lo = o0 + ob + mf * 16 + g;
        int o_hi = o_lo + 8;
        if (EPI == 0) {
            float add_lo = e0[o_lo], add_hi = e0[o_hi];
            u16* xfh = g_xfh + (size_t)b * CC * NP;
            u16* xfl = g_xfl + (size_t)b * CC * NP;
#pragma unroll
            for (int nf = 0; nf < 8; nf++) {
                int pc = p0 + pb + nf * 8 + tg * 2;
                u32 h, l;
                split2(acc[mf][nf][0] + add_lo, acc[mf][nf][1] + add_lo, h, l);
                *(u32*)&xfh[(size_t)o_lo * NP + pc] = h;
                *(u32*)&xfl[(size_t)o_lo * NP + pc] = l;
                split2(acc[mf][nf][2] + add_hi, acc[mf][nf][3] + add_hi, h, l);
                *(u32*)&xfh[(size_t)o_hi * NP + pc] = h;
                *(u32*)&xfl[(size_t)o_hi * NP + pc] = l;
            }
        } else {
            float mul_lo = e0[o_lo] * rsqrtf(e3[o_lo] + 1e-5f);
            float add_lo = e1[o_lo] - e2[o_lo] * mul_lo;
            float mul_hi = e0[o_hi] * rsqrtf(e3[o_hi] + 1e-5f);
            float add_hi = e1[o_hi] - e2[o_hi] * mul_hi;
            float* outb = OUT + (size_t)b * CC * NP;
#pragma unroll
            for (int nf = 0; nf < 8; nf++) {
                int pc = p0 + pb + nf * 8 + tg * 2;
                float2 v0, v1;
                v0.x = acc[mf][nf][0] * mul_lo + add_lo;
                v0.y = acc[mf][nf][1] * mul_lo + add_lo;
                v1.x = acc[mf][nf][2] * mul_hi + add_hi;
                v1.y = acc[mf][nf][3] * mul_hi + add_hi;
                *(float2*)&outb[(size_t)o_lo * NP + pc] = v0;
                *(float2*)&outb[(size_t)o_hi * NP + pc] = v1;
            }
        }
    }
#undef LOAD_CHUNK
}

// ---------------- kz: z = softmax_k( xf^T @ m ), reg-prefetch pipeline ------
__global__ __launch_bounds__(256, 2)
void kz_kernel(int use_gm)
{
    __shared__ __align__(16) u16 Xh[32 * 136], Xl[32 * 136]; // (c32, p128)
    __shared__ __align__(16) u16 Mh[32 * 72],  Ml[32 * 72];  // (c32, k64)

    const int p0 = blockIdx.x * 128;
    const int b  = blockIdx.y;
    const int tid = threadIdx.x;
    const int lane = tid & 31, wid = tid >> 5;
    const int pw = wid * 16;

    const u16* XH = g_xfh + (size_t)b * CC * NP;
    const u16* XL = g_xfl + (size_t)b * CC * NP;
    const u16* MH = use_gm ? (g_mh + (size_t)b * CC * KK) : g_muh;
    const u16* ML = use_gm ? (g_ml + (size_t)b * CC * KK) : g_mul;

    float acc[8][4];
#pragma unroll
    for (int nf = 0; nf < 8; nf++)
#pragma unroll
        for (int q = 0; q < 4; q++) acc[nf][q] = 0.f;

    const u32 sxh = smem_u32(Xh), sxl = smem_u32(Xl);
    const u32 smh = smem_u32(Mh), sml = smem_u32(Ml);

    const int xr0 = tid >> 4,           xg0 = (tid & 15) * 8;
    const int xr1 = (tid + 256) >> 4,   xg1 = (tid & 15) * 8;
    const int mr  = tid >> 3,           mg  = (tid & 7) * 8;

    uint4 pxh[2], pxl[2], pmh, pml;
#define KZ_PREFETCH(c0)                                                        \
    do {                                                                       \
        pxh[0] = *(const uint4*)(XH + (size_t)((c0) + xr0) * NP + p0 + xg0);   \
        pxh[1] = *(const uint4*)(XH + (size_t)((c0) + xr1) * NP + p0 + xg1);   \
        pxl[0] = *(const uint4*)(XL + (size_t)((c0) + xr0) * NP + p0 + xg0);   \
        pxl[1] = *(const uint4*)(XL + (size_t)((c0) + xr1) * NP + p0 + xg1);   \
        pmh    = *(const uint4*)(MH + (size_t)((c0) + mr) * KK + mg);          \
        pml    = *(const uint4*)(ML + (size_t)((c0) + mr) * KK + mg);          \
    } while (0)

    KZ_PREFETCH(0);

    for (int c0 = 0; c0 < CC; c0 += 32) {
        __syncthreads();
        *(uint4*)&Xh[xr0 * 136 + xg0] = pxh[0];
        *(uint4*)&Xh[xr1 * 136 + xg1] = pxh[1];
        *(uint4*)&Xl[xr0 * 136 + xg0] = pxl[0];
        *(uint4*)&Xl[xr1 * 136 + xg1] = pxl[1];
        *(uint4*)&Mh[mr * 72 + mg] = pmh;
        *(uint4*)&Ml[mr * 72 + mg] = pml;
        __syncthreads();
        if (c0 + 32 < CC) KZ_PREFETCH(c0 + 32);

#pragma unroll
        for (int ks = 0; ks < 2; ks++) {
            u32 ah[4], al[4];
            {
                u32 row = ks * 16 + (lane & 7) + ((lane >> 4) & 1) * 8;
                u32 col = pw + ((lane >> 3) & 1) * 8;
                u32 off = (row * 136 + col) << 1;
                ldsm4t(ah, sxh + off);
                ldsm4t(al, sxl + off);
            }
            u32 bh[4][4], bl[4][4];
            {
                u32 row = ks * 16 + (lane & 7) + ((lane >> 3) & 1) * 8;
                u32 col = ((lane >> 4) & 1) * 8;
#pragma unroll
                for (int pr = 0; pr < 4; pr++) {
                    u32 off = (row * 72 + col + pr * 16) << 1;
                    ldsm4t(bh[pr], smh + off);
                    ldsm4t(bl[pr], sml + off);
                }
            }
#pragma unroll
            for (int nf = 0; nf < 8; nf++) {
                const u32* bhp = &bh[nf >> 1][(nf & 1) * 2];
                const u32* blp = &bl[nf >> 1][(nf & 1) * 2];
                mma_bf16(acc[nf], ah, bhp);
                mma_bf16(acc[nf], ah, blp);
                mma_bf16(acc[nf], al, bhp);
            }
        }
    }
#undef KZ_PREFETCH

    const int gr = lane >> 2;
    float mx0 = -1e30f, mx1 = -1e30f;
#pragma unroll
    for (int nf = 0; nf < 8; nf++) {
        mx0 = fmaxf(mx0, fmaxf(acc[nf][0], acc[nf][1]));
        mx1 = fmaxf(mx1, fmaxf(acc[nf][2], acc[nf][3]));
    }
#pragma unroll
    for (int s = 1; s < 4; s <<= 1) {
        mx0 = fmaxf(mx0, __shfl_xor_sync(0xffffffffu, mx0, s));
        mx1 = fmaxf(mx1, __shfl_xor_sync(0xffffffffu, mx1, s));
    }
    float sm0 = 0.f, sm1 = 0.f;
#pragma unroll
    for (int nf = 0; nf < 8; nf++) {
        acc[nf][0] = expf(acc[nf][0] - mx0); sm0 += acc[nf][0];
        acc[nf][1] = expf(acc[nf][1] - mx0); sm0 += acc[nf][1];
        acc[nf][2] = expf(acc[nf][2] - mx1); sm1 += acc[nf][2];
        acc[nf][3] = expf(acc[nf][3] - mx1); sm1 += acc[nf][3];
    }
#pragma unroll
    for (int s = 1; s < 4; s <<= 1) {
        sm0 += __shfl_xor_sync(0xffffffffu, sm0, s);
        sm1 += __shfl_xor_sync(0xffffffffu, sm1, s);
    }
    float inv0 = 1.f / sm0, inv1 = 1.f / sm1;
    const int tg = lane & 3;
    size_t prow_lo = (size_t)(b * NP + p0 + pw + gr) * KK;
    size_t prow_hi = prow_lo + (size_t)8 * KK;
#pragma unroll
    for (int nf = 0; nf < 8; nf++) {
        int kc = nf * 8 + tg * 2;
        u32 h, l;
        split2(acc[nf][0] * inv0, acc[nf][1] * inv0, h, l);
        *(u32*)&g_zh[prow_lo + kc] = h;
        *(u32*)&g_zl[prow_lo + kc] = l;
        split2(acc[nf][2] * inv1, acc[nf][3] * inv1, h, l);
        *(u32*)&g_zh[prow_hi + kc] = h;
        *(u32*)&g_zl[prow_hi + kc] = l;
    }
}

// ---------------- km: mpart = xf @ z (split-K over p), reg-prefetch ---------
__global__ __launch_bounds__(256, 2)
void km_kernel()
{
    __shared__ __align__(16) u16 Ah[128 * 40], Al[128 * 40]; // (c128, p32)
    __shared__ __align__(16) u16 Zh[32 * 72],  Zl[32 * 72];  // (p32, k64)

    const int ct0 = blockIdx.x * 128;
    const int b   = blockIdx.y;
    const int s   = blockIdx.z;
    const int ps0 = s * (NP / NSPLIT);
    const int tid = threadIdx.x;
    const int lane = tid & 31, wid = tid >> 5;

    const u16* XH = g_xfh + (size_t)b * CC * NP;
    const u16* XL = g_xfl + (size_t)b * CC * NP;
    const u16* ZH = g_zh + (size_t)b * NP * KK;
    const u16* ZL = g_zl + (size_t)b * NP * KK;

    float acc[8][4];
#pragma unroll
    for (int nf = 0; nf < 8; nf++)
#pragma unroll
        for (int q = 0; q < 4; q++) acc[nf][q] = 0.f;

    const u32 sah = smem_u32(Ah), sal = smem_u32(Al);
    const u32 szh = smem_u32(Zh), szl = smem_u32(Zl);

    const int ar0 = tid >> 2,         ag0 = (tid & 3) * 8;
    const int ar1 = (tid + 256) >> 2, ag1 = (tid & 3) * 8;
    const int zr  = tid >> 3,         zg  = (tid & 7) * 8;

    uint4 pah[2], pal[2], pzh, pzl;
#define KM_PREFETCH(pc0)                                                       \
    do {                                                                       \
        pah[0] = *(const uint4*)(XH + (size_t)(ct0 + ar0) * NP + (pc0) + ag0); \
        pah[1] = *(const uint4*)(XH + (size_t)(ct0 + ar1) * NP + (pc0) + ag1); \
        pal[0] = *(const uint4*)(XL + (size_t)(ct0 + ar0) * NP + (pc0) + ag0); \
        pal[1] = *(const uint4*)(XL + (size_t)(ct0 + ar1) * NP + (pc0) + ag1); \
        pzh    = *(const uint4*)(ZH + (size_t)((pc0) + zr) * KK + zg);         \
        pzl    = *(const uint4*)(ZL + (size_t)((pc0) + zr) * KK + zg);         \
    } while (0)

    KM_PREFETCH(ps0);

    for (int pc0 = ps0; pc0 < ps0 + NP / NSPLIT; pc0 += 32) {
        __syncthreads();
        *(uint4*)&Ah[ar0 * 40 + ag0] = pah[0];
        *(uint4*)&Ah[ar1 * 40 + ag1] = pah[1];
        *(uint4*)&Al[ar0 * 40 + ag0] = pal[0];
        *(uint4*)&Al[ar1 * 40 + ag1] = pal[1];
        *(uint4*)&Zh[zr * 72 + zg] = pzh;
        *(uint4*)&Zl[zr * 72 + zg] = pzl;
        __syncthreads();
        if (pc0 + 32 < ps0 + NP / NSPLIT) KM_PREFETCH(pc0 + 32);

#pragma unroll
        for (int ks = 0; ks < 2; ks++) {
            u32 ah[4], al[4];
            {
                u32 off = (((wid * 16 + (lane & 15)) * 40 +
                            ks * 16 + (lane >> 4) * 8)) << 1;
                ldsm4(ah, sah + off);
                ldsm4(al, sal + off);
            }
            u32 bh[4][4], bl[4][4];
            {
                u32 row = ks * 16 + (lane & 7) + ((lane >> 3) & 1) * 8;
                u32 col = ((lane >> 4) & 1) * 8;
#pragma unroll
                for (int pr = 0; pr < 4; pr++) {
                    u32 off = (row * 72 + col + pr * 16) << 1;
                    ldsm4t(bh[pr], szh + off);
                    ldsm4t(bl[pr], szl + off);
                }
            }
#pragma unroll
            for (int nf = 0; nf < 8; nf++) {
                const u32* bhp = &bh[nf >> 1][(nf & 1) * 2];
                const u32* blp = &bl[nf >> 1][(nf & 1) * 2];
                mma_bf16(acc[nf], ah, bhp);
                mma_bf16(acc[nf], ah, blp);
                mma_bf16(acc[nf], al, bhp);
            }
        }
    }
#undef KM_PREFETCH

    const int gr = lane >> 2, tg = lane & 3;
    float* out = g_mpart + ((size_t)(s * BB + b) * CC + ct0 + wid * 16) * KK;
#pragma unroll
    for (int nf = 0; nf < 8; nf++) {
        int kc = nf * 8 + tg * 2;
        *(float2*)&out[(size_t)gr * KK + kc] =
            make_float2(acc[nf][0], acc[nf][1]);
        *(float2*)&out[(size_t)(gr + 8) * KK + kc] =
            make_float2(acc[nf][2], acc[nf][3]);
    }
}

// ---------------- fused norm v2: grid (4, BB), 64 blocks --------------------
// block handles k-quarter: threads (cg = tid>>4 in [0,64), kl = tid&15).
// Each thread reduces 8 c-rows across splits in regs, tree-reduces norms,
// scales and writes g_mh/g_ml directly.
__global__ __launch_bounds__(1024)
void knorm_fused()
{
    const int b  = blockIdx.y;
    const int k0 = blockIdx.x * 16;
    const int tid = threadIdx.x;
    const int kl = tid & 15;
    const int cg = tid >> 4;            // 0..63, each owns 8 c-rows

    __shared__ float red[64][17];

    const size_t base = (size_t)b * CC * KK;
    const int k = k0 + kl;
    float v[8];
    float ss = 0.f;
#pragma unroll
    for (int i = 0; i < 8; i++) {
        size_t off = base + (size_t)(cg * 8 + i) * KK + k;
        float t = 0.f;
#pragma unroll
        for (int s = 0; s < NSPLIT; s++)
            t += g_mpart[(size_t)s * (BB * CC * KK) + off];
        v[i] = t;
        ss += t * t;
    }
    red[cg][kl] = ss;
    __syncthreads();
#pragma unroll
    for (int s = 32; s > 0; s >>= 1) {
        if (cg < s) red[cg][kl] += red[cg + s][kl];
        __syncthreads();
    }
    const float inv = 1.f / (EPSF + sqrtf(red[0][kl]));
    u16* mh = g_mh + base;
    u16* ml = g_ml + base;
#pragma unroll
    for (int i = 0; i < 8; i++) {
        float sv = v[i] * inv;
        __nv_bfloat16 h = __float2bfloat16_rn(sv);
        __nv_bfloat16 l = __float2bfloat16_rn(sv - __bfloat162float(h));
        size_t off = (size_t)(cg * 8 + i) * KK + k;
        mh[off] = __bfloat16_as_ushort(h);
        ml[off] = __bfloat16_as_ushort(l);
    }
}

// ---------------- krec: rec = relu(m @ z^T) -> fp16 hi/lo (c,p) --------------
__global__ __launch_bounds__(256, 2)
void krec_kernel()
{
    __shared__ __align__(16) u16 Ah[128 * 40], Al[128 * 40]; // (c128, k32)
    __shared__ __align__(16) u16 Bh[128 * 40], Bl[128 * 40]; // (p128, k32)

    const int p0  = blockIdx.x * 128;
    const int ct0 = blockIdx.y * 128;
    const int b   = blockIdx.z;
    const int tid = threadIdx.x;
    const int lane = tid & 31, wid = tid >> 5;
    const int wm = wid & 1, wn = wid >> 1;
    const int cb = wm * 64, pb = wn * 32;

    const u16* MH = g_mh + (size_t)b * CC * KK;
    const u16* ML = g_ml + (size_t)b * CC * KK;
    const u16* ZH = g_zh + (size_t)b * NP * KK;
    const u16* ZL = g_zl + (size_t)b * NP * KK;

    float acc[4][4][4];
#pragma unroll
    for (int mf = 0; mf < 4; mf++)
#pragma unroll
        for (int nf = 0; nf < 4; nf++)
#pragma unroll
            for (int q = 0; q < 4; q++) acc[mf][nf][q] = 0.f;

    const u32 sah = smem_u32(Ah), sal = smem_u32(Al);
    const u32 sbh = smem_u32(Bh), sbl = smem_u32(Bl);

    for (int kc0 = 0; kc0 < KK; kc0 += 32) {
#pragma unroll
        for (int it = 0; it < 2; it++) {
            int lin = tid + it * 256;
            int r = lin >> 2, g = lin & 3;
            *(uint4*)&Ah[r * 40 + g * 8] =
                *(const uint4*)(MH + (size_t)(ct0 + r) * KK + kc0 + g * 8);
            *(uint4*)&Al[r * 40 + g * 8] =
                *(const uint4*)(ML + (size_t)(ct0 + r) * KK + kc0 + g * 8);
        }
#pragma unroll
        for (int it = 0; it < 2; it++) {
            int lin = tid + it * 256;
            int r = lin >> 2, g = lin & 3;
            *(uint4*)&Bh[r * 40 + g * 8] =
                *(const uint4*)(ZH + (size_t)(p0 + r) * KK + kc0 + g * 8);
            *(uint4*)&Bl[r * 40 + g * 8] =
                *(const uint4*)(ZL + (size_t)(p0 + r) * KK + kc0 + g * 8);
        }
        __syncthreads();
#pragma unroll
        for (int ks = 0; ks < 2; ks++) {
            u32 ah[4][4], al[4][4];
            u32 a_off = (((cb + (lane & 15)) * 40 + ks * 16 + (lane >> 4) * 8)) << 1;
#pragma unroll
            for (int mf = 0; mf < 4; mf++) {
                ldsm4(ah[mf], sah + a_off + mf * (16 * 40 * 2));
                ldsm4(al[mf], sal + a_off + mf * (16 * 40 * 2));
            }
            u32 bh[2][4], bl[2][4];
            u32 brow = pb + ((lane >> 4) & 1) * 8 + (lane & 7);
            u32 bcol = ks * 16 + ((lane >> 3) & 1) * 8;
#pragma unroll
            for (int pr = 0; pr < 2; pr++) {
                u32 boff = ((brow + pr * 16) * 40 + bcol) << 1;
                ldsm4(bh[pr], sbh + boff);
                ldsm4(bl[pr], sbl + boff);
            }
#pragma unroll
            for (int mf = 0; mf < 4; mf++)
#pragma unroll
                for (int nf = 0; nf < 4; nf++) {
                    const u32* bhp = &bh[nf >> 1][(nf & 1) * 2];
                    const u32* blp = &bl[nf >> 1][(nf & 1) * 2];
                    mma_bf16(acc[mf][nf], ah[mf], bhp);
                    mma_bf16(acc[mf][nf], ah[mf], blp);
                    mma_bf16(acc[mf][nf], al[mf], bhp);
                }
        }
        __syncthreads();
    }

    const int g = lane >> 2, tg = lane & 3;
    u16* rh = g_rech + (size_t)b * CC * NP;
    u16* rl = g_recl + (size_t)b * CC * NP;
#pragma unroll
    for (int mf = 0; mf < 4; mf++) {
        int c_lo = ct0 + cb + mf * 16 + g;
        int c_hi = c_lo + 8;
#pragma unroll
        for (int nf = 0; nf < 4; nf++) {
            int pc = p0 + pb + nf * 8 + tg * 2;
            u32 h, l;
            split2h(fmaxf(acc[mf][nf][0], 0.f), fmaxf(acc[mf][nf][1], 0.f), h, l);
            *(u32*)&rh[(size_t)c_lo * NP + pc] = h;
            *(u32*)&rl[(size_t)c_lo * NP + pc] = l;
            split2h(fmaxf(acc[mf][nf][2], 0.f), fmaxf(acc[mf][nf][3], 0.f), h, l);
            *(u32*)&rh[(size_t)c_hi * NP + pc] = h;
            *(u32*)&rl[(size_t)c_hi * NP + pc] = l;
        }
    }
}

// ---------------- launch ----------------------------------------------------
extern "C" void kernel_launch(void* const* d_in, const int* in_sizes, int n_in,
                              void* d_out, int out_size)
{
    (void)in_sizes; (void)n_in; (void)out_size;
    const float* x     = (const float*)d_in[0];
    const float* w1    = (const float*)d_in[1];
    const float* b1    = (const float*)d_in[2];
    const float* mu    = (const float*)d_in[3];
    const float* w2    = (const float*)d_in[4];
    const float* gamma = (const float*)d_in[5];
    const float* beta  = (const float*)d_in[6];
    const float* mean  = (const float*)d_in[7];
    const float* var   = (const float*)d_in[8];
    float* out = (float*)d_out;

    cudaFuncSetAttribute(hconv<0>, cudaFuncAttributeMaxDynamicSharedMemorySize,
                         HCONV_SMEM);
    cudaFuncSetAttribute(hconv<1>, cudaFuncAttributeMaxDynamicSharedMemorySize,
                         HCONV_SMEM);

    kcvt_all<<<XBLOCKS + WBLOCKS + MUBLOCKS, 256>>>(x, w1, w2, mu);

    hconv<0><<<dim3(NP / 128, CC / 128, BB), 128, HCONV_SMEM>>>(
        nullptr, b1, nullptr, nullptr, nullptr);

    for (int st = 0; st < 3; st++) {
        kz_kernel<<<dim3(NP / 128, BB), 256>>>(st > 0 ? 1 : 0);
        km_kernel<<<dim3(CC / 128, BB, NSPLIT), 256>>>();
        knorm_fused<<<dim3(4, BB), 1024>>>();
    }

    krec_kernel<<<dim3(NP / 128, CC / 128, BB), 256>>>();

    hconv<1><<<dim3(NP / 128, CC / 128, BB), 128, HCONV_SMEM>>>(
        out, gamma, beta, mean, var);
}

// round 12
// speedup vs baseline: 2.9199x; 1.0360x over previous
#include <cuda_runtime.h>
#include <cuda_bf16.h>
#include <cuda_fp16.h>

#define CC 512
#define NP 4096
#define KK 64
#define BB 16
#define NSPLIT 4
#define EPSF 1e-6f

typedef unsigned long long u64;
typedef unsigned int u32;
typedef unsigned short u16;

// ---------------- scratch (static device globals) ---------------------------
__device__ u16 g_xh[(size_t)BB * CC * NP];   // x hi fp16 (b,c,p)
__device__ u16 g_xl[(size_t)BB * CC * NP];   // x lo fp16
__device__ u16 g_wf1[(size_t)CC * CC];       // w1 fp16 single
__device__ u16 g_wf2[(size_t)CC * CC];       // w2 fp16 single
__device__ u16 g_muh[(size_t)CC * KK], g_mul[(size_t)CC * KK];   // bf16
__device__ u16 g_xfh[(size_t)BB * CC * NP];  // conv1 out hi bf16 (b,c,p)
__device__ u16 g_xfl[(size_t)BB * CC * NP];
__device__ u16 g_zh[(size_t)BB * NP * KK];   // z hi bf16 (b,p,k)
__device__ u16 g_zl[(size_t)BB * NP * KK];
__device__ u16 g_mh[(size_t)BB * CC * KK];   // m hi bf16 (b,c,k)
__device__ u16 g_ml[(size_t)BB * CC * KK];
__device__ u16 g_rech[(size_t)BB * CC * NP]; // relu(rec) hi fp16 (b,c,p)
__device__ u16 g_recl[(size_t)BB * CC * NP]; // relu(rec) lo fp16
__device__ float g_mpart[(size_t)NSPLIT * BB * CC * KK];

// ---------------- helpers ----------------------------------------------------
__device__ __forceinline__ u32 smem_u32(const void* p) {
    u32 a;
    asm("{ .reg .u64 t; cvta.to.shared.u64 t, %1; cvt.u32.u64 %0, t; }"
        : "=r"(a) : "l"(p));
    return a;
}
__device__ __forceinline__ void ldsm4(u32* r, u32 addr) {
    asm volatile("ldmatrix.sync.aligned.m8n8.x4.shared.b16 {%0,%1,%2,%3}, [%4];"
                 : "=r"(r[0]), "=r"(r[1]), "=r"(r[2]), "=r"(r[3]) : "r"(addr));
}
__device__ __forceinline__ void ldsm4t(u32* r, u32 addr) {
    asm volatile("ldmatrix.sync.aligned.m8n8.x4.trans.shared.b16 {%0,%1,%2,%3}, [%4];"
                 : "=r"(r[0]), "=r"(r[1]), "=r"(r[2]), "=r"(r[3]) : "r"(addr));
}
__device__ __forceinline__ void mma_bf16(float* d, const u32* a, const u32* b) {
    asm volatile(
        "mma.sync.aligned.m16n8k16.row.col.f32.bf16.bf16.f32 "
        "{%0,%1,%2,%3}, {%4,%5,%6,%7}, {%8,%9}, {%0,%1,%2,%3};"
        : "+f"(d[0]), "+f"(d[1]), "+f"(d[2]), "+f"(d[3])
        : "r"(a[0]), "r"(a[1]), "r"(a[2]), "r"(a[3]), "r"(b[0]), "r"(b[1]));
}
__device__ __forceinline__ void mma_fp16(float* d, const u32* a, const u32* b) {
    asm volatile(
        "mma.sync.aligned.m16n8k16.row.col.f32.f16.f16.f32 "
        "{%0,%1,%2,%3}, {%4,%5,%6,%7}, {%8,%9}, {%0,%1,%2,%3};"
        : "+f"(d[0]), "+f"(d[1]), "+f"(d[2]), "+f"(d[3])
        : "r"(a[0]), "r"(a[1]), "r"(a[2]), "r"(a[3]), "r"(b[0]), "r"(b[1]));
}
__device__ __forceinline__ void split2(float v0, float v1, u32& hi, u32& lo) {
    __nv_bfloat16 h0 = __float2bfloat16_rn(v0);
    __nv_bfloat16 h1 = __float2bfloat16_rn(v1);
    __nv_bfloat16 l0 = __float2bfloat16_rn(v0 - __bfloat162float(h0));
    __nv_bfloat16 l1 = __float2bfloat16_rn(v1 - __bfloat162float(h1));
    hi = (u32)__bfloat16_as_ushort(h0) | ((u32)__bfloat16_as_ushort(h1) << 16);
    lo = (u32)__bfloat16_as_ushort(l0) | ((u32)__bfloat16_as_ushort(l1) << 16);
}
__device__ __forceinline__ void split2h(float v0, float v1, u32& hi, u32& lo) {
    __half h0 = __float2half_rn(v0);
    __half h1 = __float2half_rn(v1);
    __half l0 = __float2half_rn(v0 - __half2float(h0));
    __half l1 = __float2half_rn(v1 - __half2float(h1));
    hi = (u32)__half_as_ushort(h0) | ((u32)__half_as_ushort(h1) << 16);
    lo = (u32)__half_as_ushort(l0) | ((u32)__half_as_ushort(l1) << 16);
}
__device__ __forceinline__ void cpa16(u32 dst, const void* src) {
    asm volatile("cp.async.cg.shared.global [%0], [%1], 16;"
                 :: "r"(dst), "l"(src));
}
#define CPA_COMMIT() asm volatile("cp.async.commit_group;")
#define CPA_WAIT(n)  asm volatile("cp.async.wait_group %0;" :: "n"(n))

// ---------------- fused convert kernel (x + w1/w2 + mu in one launch) -------
#define XBLOCKS 32768          // BB*CC*NP / 1024
#define WBLOCKS 512            // CC*CC / 512
#define MUBLOCKS 64            // CC*KK / 512
__global__ void kcvt_all(const float* __restrict__ x,
                         const float* __restrict__ w1,
                         const float* __restrict__ w2,
                         const float* __restrict__ mu)
{
    int bx = blockIdx.x;
    if (bx < XBLOCKS) {
        size_t i4 = ((size_t)bx * 256 + threadIdx.x) * 4;
        float4 v = *(const float4*)&x[i4];
        u32 h0, l0, h1, l1;
        split2h(v.x, v.y, h0, l0);
        split2h(v.z, v.w, h1, l1);
        *(uint2*)&g_xh[i4] = make_uint2(h0, h1);
        *(uint2*)&g_xl[i4] = make_uint2(l0, l1);
    } else if (bx < XBLOCKS + WBLOCKS) {
        size_t i2 = ((size_t)(bx - XBLOCKS) * 256 + threadIdx.x) * 2;
        {
            __half a = __float2half_rn(w1[i2]), b = __float2half_rn(w1[i2 + 1]);
            *(u32*)&g_wf1[i2] = (u32)__half_as_ushort(a) |
                                ((u32)__half_as_ushort(b) << 16);
        }
        {
            __half a = __float2half_rn(w2[i2]), b = __float2half_rn(w2[i2 + 1]);
            *(u32*)&g_wf2[i2] = (u32)__half_as_ushort(a) |
                                ((u32)__half_as_ushort(b) << 16);
        }
    } else {
        size_t i2 = ((size_t)(bx - XBLOCKS - WBLOCKS) * 256 + threadIdx.x) * 2;
        u32 h, l;
        split2(mu[i2], mu[i2 + 1], h, l);
        *(u32*)&g_muh[i2] = h; *(u32*)&g_mul[i2] = l;
    }
}

// ---------------- conv GEMM v5: fp16 2-term, 4-stage cp.async ---------------
#define APITCH 40
#define BPITCH 136
#define AH_OFF 0
#define BH_OFF 10240
#define BL_OFF 18944
#define STAGE_B 27648
#define NSTAGE 4
#define NCH 16
#define HCONV_SMEM (STAGE_B * NSTAGE)

template <int EPI>
__global__ __launch_bounds__(128, 2)
void hconv(float* __restrict__ OUT,
           const float* __restrict__ e0, const float* __restrict__ e1,
           const float* __restrict__ e2, const float* __restrict__ e3)
{
    extern __shared__ __align__(16) char dsm[];
    const u32 sb = smem_u32(dsm);

    const int p0 = blockIdx.x * 128;
    const int o0 = blockIdx.y * 128;
    const int b  = blockIdx.z;
    const int tid = threadIdx.x;
    const int lane = tid & 31, wid = tid >> 5;
    const int ob = (wid & 1) * 64, pb = (wid >> 1) * 64;

    const u16* WH = (EPI == 0) ? g_wf1 : g_wf2;
    const u16* IH = ((EPI == 0) ? g_xh : g_rech) + (size_t)b * CC * NP;
    const u16* IL = ((EPI == 0) ? g_xl : g_recl) + (size_t)b * CC * NP;

    float acc[4][8][4];
#pragma unroll
    for (int mf = 0; mf < 4; mf++)
#pragma unroll
        for (int nf = 0; nf < 8; nf++)
#pragma unroll
            for (int q = 0; q < 4; q++) acc[mf][nf][q] = 0.f;

    const int arow = tid >> 2, au = (tid & 3) * 8;
    const int brow = tid >> 4, bu = (tid & 15) * 8;

#define LOAD_CHUNK(st, c0)                                                      \
    do {                                                                        \
        u32 base = sb + (st) * STAGE_B;                                         \
        _Pragma("unroll")                                                       \
        for (int i = 0; i < 4; i++) {                                           \
            int r = arow + i * 32;                                              \
            cpa16(base + AH_OFF + (r * APITCH + au) * 2,                        \
                  WH + (size_t)(o0 + r) * CC + (c0) + au);                      \
        }                                                                       \
        _Pragma("unroll")                                                       \
        for (int i = 0; i < 4; i++) {                                           \
            int r = brow + i * 8;                                               \
            cpa16(base + BH_OFF + (r * BPITCH + bu) * 2,                        \
                  IH + (size_t)((c0) + r) * NP + p0 + bu);                      \
            cpa16(base + BL_OFF + (r * BPITCH + bu) * 2,                        \
                  IL + (size_t)((c0) + r) * NP + p0 + bu);                      \
        }                                                                       \
        CPA_COMMIT();                                                           \
    } while (0)

    LOAD_CHUNK(0, 0);
    LOAD_CHUNK(1, 32);
    LOAD_CHUNK(2, 64);

    const u32 a_lane = ((ob + (lane & 15)) * APITCH + (lane >> 4) * 8) * 2;
    const u32 b_rbase = (lane & 7) + ((lane >> 3) & 1) * 8;
    const u32 b_col   = pb + ((lane >> 4) & 1) * 8;

    for (int ch = 0; ch < NCH; ch++) {
        if (ch < NCH - 2)      { CPA_WAIT(2); }
        else if (ch == NCH - 2){ CPA_WAIT(1); }
        else                   { CPA_WAIT(0); }
        __syncthreads();
        if (ch < NCH - 3) LOAD_CHUNK((ch + 3) % NSTAGE, (ch + 3) * 32);

        const u32 stb = sb + (ch % NSTAGE) * STAGE_B;
#pragma unroll
        for (int ks = 0; ks < 2; ks++) {
            u32 ah[4][4];
            const u32 abase = stb + a_lane + ks * 32;
#pragma unroll
            for (int mf = 0; mf < 4; mf++)
                ldsm4(ah[mf], abase + AH_OFF + mf * (16 * APITCH * 2));
            const u32 brow = ks * 16 + b_rbase;
            const u32 bbase = stb + (brow * BPITCH + b_col) * 2;
#pragma unroll
            for (int pr = 0; pr < 4; pr++) {
                u32 bh[4], bl[4];
                ldsm4t(bh, bbase + BH_OFF + pr * 32);
                ldsm4t(bl, bbase + BL_OFF + pr * 32);
#pragma unroll
                for (int mf = 0; mf < 4; mf++) {
#pragma unroll
                    for (int hn = 0; hn < 2; hn++) {
                        float* a = acc[mf][pr * 2 + hn];
                        mma_fp16(a, ah[mf], &bh[hn * 2]);
                        mma_fp16(a, ah[mf], &bl[hn * 2]);
                    }
                }
            }
        }
    }

    const int g = lane >> 2, tg = lane & 3;
#pragma unroll
    for (int mf = 0; mf < 4; mf++) {
        int o_lo = o0 + ob + mf * 16 + g;
        int o_hi = o_lo + 8;
        if (EPI == 0) {
            float add_lo = e0[o_lo], add_hi = e0[o_hi];
            u16* xfh = g_xfh + (size_t)b * CC * NP;
            u16* xfl = g_xfl + (size_t)b * CC * NP;
#pragma unroll
            for (int nf = 0; nf < 8; nf++) {
                int pc = p0 + pb + nf * 8 + tg * 2;
                u32 h, l;
                split2(acc[mf][nf][0] + add_lo, acc[mf][nf][1] + add_lo, h, l);
                *(u32*)&xfh[(size_t)o_lo * NP + pc] = h;
                *(u32*)&xfl[(size_t)o_lo * NP + pc] = l;
                split2(acc[mf][nf][2] + add_hi, acc[mf][nf][3] + add_hi, h, l);
                *(u32*)&xfh[(size_t)o_hi * NP + pc] = h;
                *(u32*)&xfl[(size_t)o_hi * NP + pc] = l;
            }
        } else {
            float mul_lo = e0[o_lo] * rsqrtf(e3[o_lo] + 1e-5f);
            float add_lo = e1[o_lo] - e2[o_lo] * mul_lo;
            float mul_hi = e0[o_hi] * rsqrtf(e3[o_hi] + 1e-5f);
            float add_hi = e1[o_hi] - e2[o_hi] * mul_hi;
            float* outb = OUT + (size_t)b * CC * NP;
#pragma unroll
            for (int nf = 0; nf < 8; nf++) {
                int pc = p0 + pb + nf * 8 + tg * 2;
                float2 v0, v1;
                v0.x = acc[mf][nf][0] * mul_lo + add_lo;
                v0.y = acc[mf][nf][1] * mul_lo + add_lo;
                v1.x = acc[mf][nf][2] * mul_hi + add_hi;
                v1.y = acc[mf][nf][3] * mul_hi + add_hi;
                *(float2*)&outb[(size_t)o_lo * NP + pc] = v0;
                *(float2*)&outb[(size_t)o_hi * NP + pc] = v1;
            }
        }
    }
#undef LOAD_CHUNK
}

// ---------------- kz v3: 4 p-warps x 2 k-warps, reg-prefetch ----------------
__global__ __launch_bounds__(256, 2)
void kz_kernel(int use_gm)
{
    __shared__ __align__(16) u16 Xh[32 * 136], Xl[32 * 136]; // (c32, p128)
    __shared__ __align__(16) u16 Mh[32 * 72],  Ml[32 * 72];  // (c32, k64)
    __shared__ float sred[2][128];

    const int p0 = blockIdx.x * 128;
    const int b  = blockIdx.y;
    const int tid = threadIdx.x;
    const int lane = tid & 31, wid = tid >> 5;
    const int pg = wid & 3, kw = wid >> 2;
    const int pwb = pg * 32;

    const u16* XH = g_xfh + (size_t)b * CC * NP;
    const u16* XL = g_xfl + (size_t)b * CC * NP;
    const u16* MH = use_gm ? (g_mh + (size_t)b * CC * KK) : g_muh;
    const u16* ML = use_gm ? (g_ml + (size_t)b * CC * KK) : g_mul;

    float acc[2][4][4];
#pragma unroll
    for (int mf = 0; mf < 2; mf++)
#pragma unroll
        for (int nf = 0; nf < 4; nf++)
#pragma unroll
            for (int q = 0; q < 4; q++) acc[mf][nf][q] = 0.f;

    const u32 sxh = smem_u32(Xh), sxl = smem_u32(Xl);
    const u32 smh = smem_u32(Mh), sml = smem_u32(Ml);

    const int xr0 = tid >> 4,           xg0 = (tid & 15) * 8;
    const int xr1 = (tid + 256) >> 4,   xg1 = (tid & 15) * 8;
    const int mr  = tid >> 3,           mg  = (tid & 7) * 8;

    uint4 pxh[2], pxl[2], pmh, pml;
#define KZ_PREFETCH(c0)                                                        \
    do {                                                                       \
        pxh[0] = *(const uint4*)(XH + (size_t)((c0) + xr0) * NP + p0 + xg0);   \
        pxh[1] = *(const uint4*)(XH + (size_t)((c0) + xr1) * NP + p0 + xg1);   \
        pxl[0] = *(const uint4*)(XL + (size_t)((c0) + xr0) * NP + p0 + xg0);   \
        pxl[1] = *(const uint4*)(XL + (size_t)((c0) + xr1) * NP + p0 + xg1);   \
        pmh    = *(const uint4*)(MH + (size_t)((c0) + mr) * KK + mg);          \
        pml    = *(const uint4*)(ML + (size_t)((c0) + mr) * KK + mg);          \
    } while (0)

    KZ_PREFETCH(0);

    for (int c0 = 0; c0 < CC; c0 += 32) {
        __syncthreads();
        *(uint4*)&Xh[xr0 * 136 + xg0] = pxh[0];
        *(uint4*)&Xh[xr1 * 136 + xg1] = pxh[1];
        *(uint4*)&Xl[xr0 * 136 + xg0] = pxl[0];
        *(uint4*)&Xl[xr1 * 136 + xg1] = pxl[1];
        *(uint4*)&Mh[mr * 72 + mg] = pmh;
        *(uint4*)&Ml[mr * 72 + mg] = pml;
        __syncthreads();
        if (c0 + 32 < CC) KZ_PREFETCH(c0 + 32);

#pragma unroll
        for (int ks = 0; ks < 2; ks++) {
            u32 ah[2][4], al[2][4];
#pragma unroll
            for (int mf = 0; mf < 2; mf++) {
                u32 row = ks * 16 + (lane & 7) + ((lane >> 4) & 1) * 8;
                u32 col = pwb + mf * 16 + ((lane >> 3) & 1) * 8;
                u32 off = (row * 136 + col) << 1;
                ldsm4t(ah[mf], sxh + off);
                ldsm4t(al[mf], sxl + off);
            }
            u32 bh[2][4], bl[2][4];
            {
                u32 row = ks * 16 + (lane & 7) + ((lane >> 3) & 1) * 8;
                u32 col = kw * 32 + ((lane >> 4) & 1) * 8;
#pragma unroll
                for (int pr = 0; pr < 2; pr++) {
                    u32 off = (row * 72 + col + pr * 16) << 1;
                    ldsm4t(bh[pr], smh + off);
                    ldsm4t(bl[pr], sml + off);
                }
            }
#pragma unroll
            for (int mf = 0; mf < 2; mf++)
#pragma unroll
                for (int nf = 0; nf < 4; nf++) {
                    const u32* bhp = &bh[nf >> 1][(nf & 1) * 2];
                    const u32* blp = &bl[nf >> 1][(nf & 1) * 2];
                    mma_bf16(acc[mf][nf], ah[mf], bhp);
                    mma_bf16(acc[mf][nf], ah[mf], blp);
                    mma_bf16(acc[mf][nf], al[mf], bhp);
                }
        }
    }
#undef KZ_PREFETCH

    // ---- softmax over k=64 split across 2 k-warps ----
    const int gr = lane >> 2, tg = lane & 3;
    // partial max per (mf, half)
    float pm[2][2];
#pragma unroll
    for (int mf = 0; mf < 2; mf++) {
        float m0 = -1e30f, m1 = -1e30f;
#pragma unroll
        for (int nf = 0; nf < 4; nf++) {
            m0 = fmaxf(m0, fmaxf(acc[mf][nf][0], acc[mf][nf][1]));
            m1 = fmaxf(m1, fmaxf(acc[mf][nf][2], acc[mf][nf][3]));
        }
#pragma unroll
        for (int s = 1; s < 4; s <<= 1) {
            m0 = fmaxf(m0, __shfl_xor_sync(0xffffffffu, m0, s));
            m1 = fmaxf(m1, __shfl_xor_sync(0xffffffffu, m1, s));
        }
        pm[mf][0] = m0; pm[mf][1] = m1;
    }
    // exchange maxima
    if (tg == 0) {
#pragma unroll
        for (int mf = 0; mf < 2; mf++) {
            sred[kw][pwb + mf * 16 + gr]     = pm[mf][0];
            sred[kw][pwb + mf * 16 + gr + 8] = pm[mf][1];
        }
    }
    __syncthreads();
    float fm[2][2];
#pragma unroll
    for (int mf = 0; mf < 2; mf++) {
        fm[mf][0] = fmaxf(pm[mf][0], sred[kw ^ 1][pwb + mf * 16 + gr]);
        fm[mf][1] = fmaxf(pm[mf][1], sred[kw ^ 1][pwb + mf * 16 + gr + 8]);
    }
    __syncthreads();
    // exp + partial sums
    float ps[2][2];
#pragma unroll
    for (int mf = 0; mf < 2; mf++) {
        float s0 = 0.f, s1 = 0.f;
#pragma unroll
        for (int nf = 0; nf < 4; nf++) {
            acc[mf][nf][0] = expf(acc[mf][nf][0] - fm[mf][0]); s0 += acc[mf][nf][0];
            acc[mf][nf][1] = expf(acc[mf][nf][1] - fm[mf][0]); s0 += acc[mf][nf][1];
            acc[mf][nf][2] = expf(acc[mf][nf][2] - fm[mf][1]); s1 += acc[mf][nf][2];
            acc[mf][nf][3] = expf(acc[mf][nf][3] - fm[mf][1]); s1 += acc[mf][nf][3];
        }
#pragma unroll
        for (int s = 1; s < 4; s <<= 1) {
            s0 += __shfl_xor_sync(0xffffffffu, s0, s);
            s1 += __shfl_xor_sync(0xffffffffu, s1, s);
        }
        ps[mf][0] = s0; ps[mf][1] = s1;
    }
    if (tg == 0) {
#pragma unroll
        for (int mf = 0; mf < 2; mf++) {
            sred[kw][pwb + mf * 16 + gr]     = ps[mf][0];
            sred[kw][pwb + mf * 16 + gr + 8] = ps[mf][1];
        }
    }
    __syncthreads();
#pragma unroll
    for (int mf = 0; mf < 2; mf++) {
        float inv0 = 1.f / (ps[mf][0] + sred[kw ^ 1][pwb + mf * 16 + gr]);
        float inv1 = 1.f / (ps[mf][1] + sred[kw ^ 1][pwb + mf * 16 + gr + 8]);
        size_t prow_lo = (size_t)(b * NP + p0 + pwb + mf * 16 + gr) * KK;
        size_t prow_hi = prow_lo + (size_t)8 * KK;
#pragma unroll
        for (int nf = 0; nf < 4; nf++) {
            int kc = kw * 32 + nf * 8 + tg * 2;
            u32 h, l;
            split2(acc[mf][nf][0] * inv0, acc[mf][nf][1] * inv0, h, l);
            *(u32*)&g_zh[prow_lo + kc] = h;
            *(u32*)&g_zl[prow_lo + kc] = l;
            split2(acc[mf][nf][2] * inv1, acc[mf][nf][3] * inv1, h, l);
            *(u32*)&g_zh[prow_hi + kc] = h;
            *(u32*)&g_zl[prow_hi + kc] = l;
        }
    }
}

// ---------------- km v3: 4 c-warps x 2 k-warps, reg-prefetch ----------------
__global__ __launch_bounds__(256, 2)
void km_kernel()
{
    __shared__ __align__(16) u16 Ah[128 * 40], Al[128 * 40]; // (c128, p32)
    __shared__ __align__(16) u16 Zh[32 * 72],  Zl[32 * 72];  // (p32, k64)

    const int ct0 = blockIdx.x * 128;
    const int b   = blockIdx.y;
    const int s   = blockIdx.z;
    const int ps0 = s * (NP / NSPLIT);
    const int tid = threadIdx.x;
    const int lane = tid & 31, wid = tid >> 5;
    const int cw = wid & 3, kw = wid >> 2;

    const u16* XH = g_xfh + (size_t)b * CC * NP;
    const u16* XL = g_xfl + (size_t)b * CC * NP;
    const u16* ZH = g_zh + (size_t)b * NP * KK;
    const u16* ZL = g_zl + (size_t)b * NP * KK;

    float acc[2][4][4];
#pragma unroll
    for (int mf = 0; mf < 2; mf++)
#pragma unroll
        for (int nf = 0; nf < 4; nf++)
#pragma unroll
            for (int q = 0; q < 4; q++) acc[mf][nf][q] = 0.f;

    const u32 sah = smem_u32(Ah), sal = smem_u32(Al);
    const u32 szh = smem_u32(Zh), szl = smem_u32(Zl);

    const int ar0 = tid >> 2,         ag0 = (tid & 3) * 8;
    const int ar1 = (tid + 256) >> 2, ag1 = (tid & 3) * 8;
    const int zr  = tid >> 3,         zg  = (tid & 7) * 8;

    uint4 pah[2], pal[2], pzh, pzl;
#define KM_PREFETCH(pc0)                                                       \
    do {                                                                       \
        pah[0] = *(const uint4*)(XH + (size_t)(ct0 + ar0) * NP + (pc0) + ag0); \
        pah[1] = *(const uint4*)(XH + (size_t)(ct0 + ar1) * NP + (pc0) + ag1); \
        pal[0] = *(const uint4*)(XL + (size_t)(ct0 + ar0) * NP + (pc0) + ag0); \
        pal[1] = *(const uint4*)(XL + (size_t)(ct0 + ar1) * NP + (pc0) + ag1); \
        pzh    = *(const uint4*)(ZH + (size_t)((pc0) + zr) * KK + zg);         \
        pzl    = *(const uint4*)(ZL + (size_t)((pc0) + zr) * KK + zg);         \
    } while (0)

    KM_PREFETCH(ps0);

    for (int pc0 = ps0; pc0 < ps0 + NP / NSPLIT; pc0 += 32) {
        __syncthreads();
        *(uint4*)&Ah[ar0 * 40 + ag0] = pah[0];
        *(uint4*)&Ah[ar1 * 40 + ag1] = pah[1];
        *(uint4*)&Al[ar0 * 40 + ag0] = pal[0];
        *(uint4*)&Al[ar1 * 40 + ag1] = pal[1];
        *(uint4*)&Zh[zr * 72 + zg] = pzh;
        *(uint4*)&Zl[zr * 72 + zg] = pzl;
        __syncthreads();
        if (pc0 + 32 < ps0 + NP / NSPLIT) KM_PREFETCH(pc0 + 32);

#pragma unroll
        for (int ks = 0; ks < 2; ks++) {
            u32 ah[2][4], al[2][4];
#pragma unroll
            for (int mf = 0; mf < 2; mf++) {
                u32 off = (((cw * 32 + mf * 16 + (lane & 15)) * 40 +
                            ks * 16 + (lane >> 4) * 8)) << 1;
                ldsm4(ah[mf], sah + off);
                ldsm4(al[mf], sal + off);
            }
            u32 bh[2][4], bl[2][4];
            {
                u32 row = ks * 16 + (lane & 7) + ((lane >> 3) & 1) * 8;
                u32 col = kw * 32 + ((lane >> 4) & 1) * 8;
#pragma unroll
                for (int pr = 0; pr < 2; pr++) {
                    u32 off = (row * 72 + col + pr * 16) << 1;
                    ldsm4t(bh[pr], szh + off);
                    ldsm4t(bl[pr], szl + off);
                }
            }
#pragma unroll
            for (int mf = 0; mf < 2; mf++)
#pragma unroll
                for (int nf = 0; nf < 4; nf++) {
                    const u32* bhp = &bh[nf >> 1][(nf & 1) * 2];
                    const u32* blp = &bl[nf >> 1][(nf & 1) * 2];
                    mma_bf16(acc[mf][nf], ah[mf], bhp);
                    mma_bf16(acc[mf][nf], ah[mf], blp);
                    mma_bf16(acc[mf][nf], al[mf], bhp);
                }
        }
    }
#undef KM_PREFETCH

    const int gr = lane >> 2, tg = lane & 3;
    float* out = g_mpart + ((size_t)(s * BB + b) * CC + ct0 + cw * 32) * KK;
#pragma unroll
    for (int mf = 0; mf < 2; mf++)
#pragma unroll
        for (int nf = 0; nf < 4; nf++) {
            int kc = kw * 32 + nf * 8 + tg * 2;
            int r0 = mf * 16 + gr;
            *(float2*)&out[(size_t)r0 * KK + kc] =
                make_float2(acc[mf][nf][0], acc[mf][nf][1]);
            *(float2*)&out[(size_t)(r0 + 8) * KK + kc] =
                make_float2(acc[mf][nf][2], acc[mf][nf][3]);
        }
}

// ---------------- fused norm v2: grid (4, BB), 64 blocks --------------------
__global__ __launch_bounds__(1024)
void knorm_fused()
{
    const int b  = blockIdx.y;
    const int k0 = blockIdx.x * 16;
    const int tid = threadIdx.x;
    const int kl = tid & 15;
    const int cg = tid >> 4;            // 0..63, each owns 8 c-rows

    __shared__ float red[64][17];

    const size_t base = (size_t)b * CC * KK;
    const int k = k0 + kl;
    float v[8];
    float ss = 0.f;
#pragma unroll
    for (int i = 0; i < 8; i++) {
        size_t off = base + (size_t)(cg * 8 + i) * KK + k;
        float t = 0.f;
#pragma unroll
        for (int s = 0; s < NSPLIT; s++)
            t += g_mpart[(size_t)s * (BB * CC * KK) + off];
        v[i] = t;
        ss += t * t;
    }
    red[cg][kl] = ss;
    __syncthreads();
#pragma unroll
    for (int s = 32; s > 0; s >>= 1) {
        if (cg < s) red[cg][kl] += red[cg + s][kl];
        __syncthreads();
    }
    const float inv = 1.f / (EPSF + sqrtf(red[0][kl]));
    u16* mh = g_mh + base;
    u16* ml = g_ml + base;
#pragma unroll
    for (int i = 0; i < 8; i++) {
        float sv = v[i] * inv;
        __nv_bfloat16 h = __float2bfloat16_rn(sv);
        __nv_bfloat16 l = __float2bfloat16_rn(sv - __bfloat162float(h));
        size_t off = (size_t)(cg * 8 + i) * KK + k;
        mh[off] = __bfloat16_as_ushort(h);
        ml[off] = __bfloat16_as_ushort(l);
    }
}

// ---------------- krec: rec = relu(m @ z^T) -> fp16 hi/lo (c,p) --------------
__global__ __launch_bounds__(256, 2)
void krec_kernel()
{
    __shared__ __align__(16) u16 Ah[128 * 40], Al[128 * 40]; // (c128, k32)
    __shared__ __align__(16) u16 Bh[128 * 40], Bl[128 * 40]; // (p128, k32)

    const int p0  = blockIdx.x * 128;
    const int ct0 = blockIdx.y * 128;
    const int b   = blockIdx.z;
    const int tid = threadIdx.x;
    const int lane = tid & 31, wid = tid >> 5;
    const int wm = wid & 1, wn = wid >> 1;
    const int cb = wm * 64, pb = wn * 32;

    const u16* MH = g_mh + (size_t)b * CC * KK;
    const u16* ML = g_ml + (size_t)b * CC * KK;
    const u16* ZH = g_zh + (size_t)b * NP * KK;
    const u16* ZL = g_zl + (size_t)b * NP * KK;

    float acc[4][4][4];
#pragma unroll
    for (int mf = 0; mf < 4; mf++)
#pragma unroll
        for (int nf = 0; nf < 4; nf++)
#pragma unroll
            for (int q = 0; q < 4; q++) acc[mf][nf][q] = 0.f;

    const u32 sah = smem_u32(Ah), sal = smem_u32(Al);
    const u32 sbh = smem_u32(Bh), sbl = smem_u32(Bl);

    for (int kc0 = 0; kc0 < KK; kc0 += 32) {
#pragma unroll
        for (int it = 0; it < 2; it++) {
            int lin = tid + it * 256;
            int r = lin >> 2, g = lin & 3;
            *(uint4*)&Ah[r * 40 + g * 8] =
                *(const uint4*)(MH + (size_t)(ct0 + r) * KK + kc0 + g * 8);
            *(uint4*)&Al[r * 40 + g * 8] =
                *(const uint4*)(ML + (size_t)(ct0 + r) * KK + kc0 + g * 8);
        }
#pragma unroll
        for (int it = 0; it < 2; it++) {
            int lin = tid + it * 256;
            int r = lin >> 2, g = lin & 3;
            *(uint4*)&Bh[r * 40 + g * 8] =
                *(const uint4*)(ZH + (size_t)(p0 + r) * KK + kc0 + g * 8);
            *(uint4*)&Bl[r * 40 + g * 8] =
                *(const uint4*)(ZL + (size_t)(p0 + r) * KK + kc0 + g * 8);
        }
        __syncthreads();
#pragma unroll
        for (int ks = 0; ks < 2; ks++) {
            u32 ah[4][4], al[4][4];
            u32 a_off = (((cb + (lane & 15)) * 40 + ks * 16 + (lane >> 4) * 8)) << 1;
#pragma unroll
            for (int mf = 0; mf < 4; mf++) {
                ldsm4(ah[mf], sah + a_off + mf * (16 * 40 * 2));
                ldsm4(al[mf], sal + a_off + mf * (16 * 40 * 2));
            }
            u32 bh[2][4], bl[2][4];
            u32 brow = pb + ((lane >> 4) & 1) * 8 + (lane & 7);
            u32 bcol = ks * 16 + ((lane >> 3) & 1) * 8;
#pragma unroll
            for (int pr = 0; pr < 2; pr++) {
                u32 boff = ((brow + pr * 16) * 40 + bcol) << 1;
                ldsm4(bh[pr], sbh + boff);
                ldsm4(bl[pr], sbl + boff);
            }
#pragma unroll
            for (int mf = 0; mf < 4; mf++)
#pragma unroll
                for (int nf = 0; nf < 4; nf++) {
                    const u32* bhp = &bh[nf >> 1][(nf & 1) * 2];
                    const u32* blp = &bl[nf >> 1][(nf & 1) * 2];
                    mma_bf16(acc[mf][nf], ah[mf], bhp);
                    mma_bf16(acc[mf][nf], ah[mf], blp);
                    mma_bf16(acc[mf][nf], al[mf], bhp);
                }
        }
        __syncthreads();
    }

    const int g = lane >> 2, tg = lane & 3;
    u16* rh = g_rech + (size_t)b * CC * NP;
    u16* rl = g_recl + (size_t)b * CC * NP;
#pragma unroll
    for (int mf = 0; mf < 4; mf++) {
        int c_lo = ct0 + cb + mf * 16 + g;
        int c_hi = c_lo + 8;
#pragma unroll
        for (int nf = 0; nf < 4; nf++) {
            int pc = p0 + pb + nf * 8 + tg * 2;
            u32 h, l;
            split2h(fmaxf(acc[mf][nf][0], 0.f), fmaxf(acc[mf][nf][1], 0.f), h, l);
            *(u32*)&rh[(size_t)c_lo * NP + pc] = h;
            *(u32*)&rl[(size_t)c_lo * NP + pc] = l;
            split2h(fmaxf(acc[mf][nf][2], 0.f), fmaxf(acc[mf][nf][3], 0.f), h, l);
            *(u32*)&rh[(size_t)c_hi * NP + pc] = h;
            *(u32*)&rl[(size_t)c_hi * NP + pc] = l;
        }
    }
}

// ---------------- launch ----------------------------------------------------
extern "C" void kernel_launch(void* const* d_in, const int* in_sizes, int n_in,
                              void* d_out, int out_size)
{
    (void)in_sizes; (void)n_in; (void)out_size;
    const float* x     = (const float*)d_in[0];
    const float* w1    = (const float*)d_in[1];
    const float* b1    = (const float*)d_in[2];
    const float* mu    = (const float*)d_in[3];
    const float* w2    = (const float*)d_in[4];
    const float* gamma = (const float*)d_in[5];
    const float* beta  = (const float*)d_in[6];
    const float* mean  = (const float*)d_in[7];
    const float* var   = (const float*)d_in[8];
    float* out = (float*)d_out;

    cudaFuncSetAttribute(hconv<0>, cudaFuncAttributeMaxDynamicSharedMemorySize,
                         HCONV_SMEM);
    cudaFuncSetAttribute(hconv<1>, cudaFuncAttributeMaxDynamicSharedMemorySize,
                         HCONV_SMEM);

    kcvt_all<<<XBLOCKS + WBLOCKS + MUBLOCKS, 256>>>(x, w1, w2, mu);

    hconv<0><<<dim3(NP / 128, CC / 128, BB), 128, HCONV_SMEM>>>(
        nullptr, b1, nullptr, nullptr, nullptr);

    for (int st = 0; st < 3; st++) {
        kz_kernel<<<dim3(NP / 128, BB), 256>>>(st > 0 ? 1 : 0);
        km_kernel<<<dim3(CC / 128, BB, NSPLIT), 256>>>();
        knorm_fused<<<dim3(4, BB), 1024>>>();
    }

    krec_kernel<<<dim3(NP / 128, CC / 128, BB), 256>>>();

    hconv<1><<<dim3(NP / 128, CC / 128, BB), 128, HCONV_SMEM>>>(
        out, gamma, beta, mean, var);
}

// round 13
// speedup vs baseline: 3.3119x; 1.1343x over previous
#include <cuda_runtime.h>
#include <cuda_bf16.h>
#include <cuda_fp16.h>

#define CC 512
#define NP 4096
#define KK 64
#define BB 16
#define NSPLIT 4
#define EPSF 1e-6f

typedef unsigned long long u64;
typedef unsigned int u32;
typedef unsigned short u16;

// ---------------- scratch (static device globals) ---------------------------
__device__ u16 g_xh[(size_t)BB * CC * NP];   // x hi fp16 (b,c,p)
__device__ u16 g_xl[(size_t)BB * CC * NP];   // x lo fp16
__device__ u16 g_wf1[(size_t)CC * CC];       // w1 fp16 single
__device__ u16 g_wf2[(size_t)CC * CC];       // w2 fp16 single
__device__ u16 g_muh[(size_t)CC * KK], g_mul[(size_t)CC * KK];   // bf16
__device__ u16 g_xfh[(size_t)BB * CC * NP];  // conv1 out hi bf16 (b,c,p)
__device__ u16 g_xfl[(size_t)BB * CC * NP];
__device__ u16 g_zh[(size_t)BB * NP * KK];   // z hi bf16 (b,p,k)
__device__ u16 g_zl[(size_t)BB * NP * KK];
__device__ u16 g_mh[(size_t)BB * CC * KK];   // m hi bf16 (b,c,k)
__device__ u16 g_ml[(size_t)BB * CC * KK];
__device__ u16 g_rech[(size_t)BB * CC * NP]; // relu(rec) fp16 single (b,c,p)
__device__ float g_mpart[(size_t)NSPLIT * BB * CC * KK];

// ---------------- helpers ----------------------------------------------------
__device__ __forceinline__ u32 smem_u32(const void* p) {
    u32 a;
    asm("{ .reg .u64 t; cvta.to.shared.u64 t, %1; cvt.u32.u64 %0, t; }"
        : "=r"(a) : "l"(p));
    return a;
}
__device__ __forceinline__ void ldsm4(u32* r, u32 addr) {
    asm volatile("ldmatrix.sync.aligned.m8n8.x4.shared.b16 {%0,%1,%2,%3}, [%4];"
                 : "=r"(r[0]), "=r"(r[1]), "=r"(r[2]), "=r"(r[3]) : "r"(addr));
}
__device__ __forceinline__ void ldsm4t(u32* r, u32 addr) {
    asm volatile("ldmatrix.sync.aligned.m8n8.x4.trans.shared.b16 {%0,%1,%2,%3}, [%4];"
                 : "=r"(r[0]), "=r"(r[1]), "=r"(r[2]), "=r"(r[3]) : "r"(addr));
}
__device__ __forceinline__ void mma_bf16(float* d, const u32* a, const u32* b) {
    asm volatile(
        "mma.sync.aligned.m16n8k16.row.col.f32.bf16.bf16.f32 "
        "{%0,%1,%2,%3}, {%4,%5,%6,%7}, {%8,%9}, {%0,%1,%2,%3};"
        : "+f"(d[0]), "+f"(d[1]), "+f"(d[2]), "+f"(d[3])
        : "r"(a[0]), "r"(a[1]), "r"(a[2]), "r"(a[3]), "r"(b[0]), "r"(b[1]));
}
__device__ __forceinline__ void mma_fp16(float* d, const u32* a, const u32* b) {
    asm volatile(
        "mma.sync.aligned.m16n8k16.row.col.f32.f16.f16.f32 "
        "{%0,%1,%2,%3}, {%4,%5,%6,%7}, {%8,%9}, {%0,%1,%2,%3};"
        : "+f"(d[0]), "+f"(d[1]), "+f"(d[2]), "+f"(d[3])
        : "r"(a[0]), "r"(a[1]), "r"(a[2]), "r"(a[3]), "r"(b[0]), "r"(b[1]));
}
__device__ __forceinline__ void split2(float v0, float v1, u32& hi, u32& lo) {
    __nv_bfloat16 h0 = __float2bfloat16_rn(v0);
    __nv_bfloat16 h1 = __float2bfloat16_rn(v1);
    __nv_bfloat16 l0 = __float2bfloat16_rn(v0 - __bfloat162float(h0));
    __nv_bfloat16 l1 = __float2bfloat16_rn(v1 - __bfloat162float(h1));
    hi = (u32)__bfloat16_as_ushort(h0) | ((u32)__bfloat16_as_ushort(h1) << 16);
    lo = (u32)__bfloat16_as_ushort(l0) | ((u32)__bfloat16_as_ushort(l1) << 16);
}
__device__ __forceinline__ void split2h(float v0, float v1, u32& hi, u32& lo) {
    __half h0 = __float2half_rn(v0);
    __half h1 = __float2half_rn(v1);
    __half l0 = __float2half_rn(v0 - __half2float(h0));
    __half l1 = __float2half_rn(v1 - __half2float(h1));
    hi = (u32)__half_as_ushort(h0) | ((u32)__half_as_ushort(h1) << 16);
    lo = (u32)__half_as_ushort(l0) | ((u32)__half_as_ushort(l1) << 16);
}
__device__ __forceinline__ u32 pack2h(float v0, float v1) {
    __half h0 = __float2half_rn(v0);
    __half h1 = __float2half_rn(v1);
    return (u32)__half_as_ushort(h0) | ((u32)__half_as_ushort(h1) << 16);
}
__device__ __forceinline__ void cpa16(u32 dst, const void* src) {
    asm volatile("cp.async.cg.shared.global [%0], [%1], 16;"
                 :: "r"(dst), "l"(src));
}
#define CPA_COMMIT() asm volatile("cp.async.commit_group;")
#define CPA_WAIT(n)  asm volatile("cp.async.wait_group %0;" :: "n"(n))

// ---------------- fused convert kernel (x + w1/w2 + mu in one launch) -------
#define XBLOCKS 32768          // BB*CC*NP / 1024
#define WBLOCKS 512            // CC*CC / 512
#define MUBLOCKS 64            // CC*KK / 512
__global__ void kcvt_all(const float* __restrict__ x,
                         const float* __restrict__ w1,
                         const float* __restrict__ w2,
                         const float* __restrict__ mu)
{
    int bx = blockIdx.x;
    if (bx < XBLOCKS) {
        size_t i4 = ((size_t)bx * 256 + threadIdx.x) * 4;
        float4 v = *(const float4*)&x[i4];
        u32 h0, l0, h1, l1;
        split2h(v.x, v.y, h0, l0);
        split2h(v.z, v.w, h1, l1);
        *(uint2*)&g_xh[i4] = make_uint2(h0, h1);
        *(uint2*)&g_xl[i4] = make_uint2(l0, l1);
    } else if (bx < XBLOCKS + WBLOCKS) {
        size_t i2 = ((size_t)(bx - XBLOCKS) * 256 + threadIdx.x) * 2;
        *(u32*)&g_wf1[i2] = pack2h(w1[i2], w1[i2 + 1]);
        *(u32*)&g_wf2[i2] = pack2h(w2[i2], w2[i2 + 1]);
    } else {
        size_t i2 = ((size_t)(bx - XBLOCKS - WBLOCKS) * 256 + threadIdx.x) * 2;
        u32 h, l;
        split2(mu[i2], mu[i2 + 1], h, l);
        *(u32*)&g_muh[i2] = h; *(u32*)&g_mul[i2] = l;
    }
}

// ---------------- conv GEMM v6: fp16, 4-stage cp.async ----------------------
// EPI=0: B = x hi/lo (2-term), bias -> g_xfh/g_xfl bf16 split
// EPI=1: B = rec single fp16 (1-term), BN -> OUT fp32
#define APITCH 40
#define BPITCH 136
#define AH_OFF 0
#define BH_OFF 10240
#define BL_OFF 18944
#define STAGE_B 27648
#define NSTAGE 4
#define NCH 16
#define HCONV_SMEM (STAGE_B * NSTAGE)

template <int EPI>
__global__ __launch_bounds__(128, 2)
void hconv(float* __restrict__ OUT,
           const float* __restrict__ e0, const float* __restrict__ e1,
           const float* __restrict__ e2, const float* __restrict__ e3)
{
    extern __shared__ __align__(16) char dsm[];
    const u32 sb = smem_u32(dsm);

    const int p0 = blockIdx.x * 128;
    const int o0 = blockIdx.y * 128;
    const int b  = blockIdx.z;
    const int tid = threadIdx.x;
    const int lane = tid & 31, wid = tid >> 5;
    const int ob = (wid & 1) * 64, pb = (wid >> 1) * 64;

    const u16* WH = (EPI == 0) ? g_wf1 : g_wf2;
    const u16* IH = ((EPI == 0) ? g_xh : g_rech) + (size_t)b * CC * NP;
    const u16* IL = g_xl + (size_t)b * CC * NP;   // only used when EPI == 0

    float acc[4][8][4];
#pragma unroll
    for (int mf = 0; mf < 4; mf++)
#pragma unroll
        for (int nf = 0; nf < 8; nf++)
#pragma unroll
            for (int q = 0; q < 4; q++) acc[mf][nf][q] = 0.f;

    const int arow = tid >> 2, au = (tid & 3) * 8;
    const int brow = tid >> 4, bu = (tid & 15) * 8;

#define LOAD_CHUNK(st, c0)                                                      \
    do {                                                                        \
        u32 base = sb + (st) * STAGE_B;                                         \
        _Pragma("unroll")                                                       \
        for (int i = 0; i < 4; i++) {                                           \
            int r = arow + i * 32;                                              \
            cpa16(base + AH_OFF + (r * APITCH + au) * 2,                        \
                  WH + (size_t)(o0 + r) * CC + (c0) + au);                      \
        }                                                                       \
        _Pragma("unroll")                                                       \
        for (int i = 0; i < 4; i++) {                                           \
            int r = brow + i * 8;                                               \
            cpa16(base + BH_OFF + (r * BPITCH + bu) * 2,                        \
                  IH + (size_t)((c0) + r) * NP + p0 + bu);                      \
            if (EPI == 0)                                                       \
                cpa16(base + BL_OFF + (r * BPITCH + bu) * 2,                    \
                      IL + (size_t)((c0) + r) * NP + p0 + bu);                  \
        }                                                                       \
        CPA_COMMIT();                                                           \
    } while (0)

    LOAD_CHUNK(0, 0);
    LOAD_CHUNK(1, 32);
    LOAD_CHUNK(2, 64);

    const u32 a_lane = ((ob + (lane & 15)) * APITCH + (lane >> 4) * 8) * 2;
    const u32 b_rbase = (lane & 7) + ((lane >> 3) & 1) * 8;
    const u32 b_col   = pb + ((lane >> 4) & 1) * 8;

    for (int ch = 0; ch < NCH; ch++) {
        if (ch < NCH - 2)      { CPA_WAIT(2); }
        else if (ch == NCH - 2){ CPA_WAIT(1); }
        else                   { CPA_WAIT(0); }
        __syncthreads();
        if (ch < NCH - 3) LOAD_CHUNK((ch + 3) % NSTAGE, (ch + 3) * 32);

        const u32 stb = sb + (ch % NSTAGE) * STAGE_B;
#pragma unroll
        for (int ks = 0; ks < 2; ks++) {
            u32 ah[4][4];
            const u32 abase = stb + a_lane + ks * 32;
#pragma unroll
            for (int mf = 0; mf < 4; mf++)
                ldsm4(ah[mf], abase + AH_OFF + mf * (16 * APITCH * 2));
            const u32 brow = ks * 16 + b_rbase;
            const u32 bbase = stb + (brow * BPITCH + b_col) * 2;
#pragma unroll
            for (int pr = 0; pr < 4; pr++) {
                u32 bh[4], bl[4];
                ldsm4t(bh, bbase + BH_OFF + pr * 32);
                if (EPI == 0) ldsm4t(bl, bbase + BL_OFF + pr * 32);
#pragma unroll
                for (int mf = 0; mf < 4; mf++) {
#pragma unroll
                    for (int hn = 0; hn < 2; hn++) {
                        float* a = acc[mf][pr * 2 + hn];
                        mma_fp16(a, ah[mf], &bh[hn * 2]);
                        if (EPI == 0) mma_fp16(a, ah[mf], &bl[hn * 2]);
                    }
                }
            }
        }
    }

    const int g = lane >> 2, tg = lane & 3;
#pragma unroll
    for (int mf = 0; mf < 4; mf++) {
        int o_lo = o0 + ob + mf * 16 + g;
        int o_hi = o_lo + 8;
        if (EPI == 0) {
            float add_lo = e0[o_lo], add_hi = e0[o_hi];
            u16* xfh = g_xfh + (size_t)b * CC * NP;
            u16* xfl = g_xfl + (size_t)b * CC * NP;
#pragma unroll
            for (int nf = 0; nf < 8; nf++) {
                int pc = p0 + pb + nf * 8 + tg * 2;
                u32 h, l;
                split2(acc[mf][nf][0] + add_lo, acc[mf][nf][1] + add_lo, h, l);
                *(u32*)&xfh[(size_t)o_lo * NP + pc] = h;
                *(u32*)&xfl[(size_t)o_lo * NP + pc] = l;
                split2(acc[mf][nf][2] + add_hi, acc[mf][nf][3] + add_hi, h, l);
                *(u32*)&xfh[(size_t)o_hi * NP + pc] = h;
                *(u32*)&xfl[(size_t)o_hi * NP + pc] = l;
            }
        } else {
            float mul_lo = e0[o_lo] * rsqrtf(e3[o_lo] + 1e-5f);
            float add_lo = e1[o_lo] - e2[o_lo] * mul_lo;
            float mul_hi = e0[o_hi] * rsqrtf(e3[o_hi] + 1e-5f);
            float add_hi = e1[o_hi] - e2[o_hi] * mul_hi;
            float* outb = OUT + (size_t)b * CC * NP;
#pragma unroll
            for (int nf = 0; nf < 8; nf++) {
                int pc = p0 + pb + nf * 8 + tg * 2;
                float2 v0, v1;
                v0.x = acc[mf][nf][0] * mul_lo + add_lo;
                v0.y = acc[mf][nf][1] * mul_lo + add_lo;
                v1.x = acc[mf][nf][2] * mul_hi + add_hi;
                v1.y = acc[mf][nf][3] * mul_hi + add_hi;
                *(float2*)&outb[(size_t)o_lo * NP + pc] = v0;
                *(float2*)&outb[(size_t)o_hi * NP + pc] = v1;
            }
        }
    }
#undef LOAD_CHUNK
}

// ---------------- kz v3: 4 p-warps x 2 k-warps, reg-prefetch ----------------
__global__ __launch_bounds__(256, 2)
void kz_kernel(int use_gm)
{
    __shared__ __align__(16) u16 Xh[32 * 136], Xl[32 * 136]; // (c32, p128)
    __shared__ __align__(16) u16 Mh[32 * 72],  Ml[32 * 72];  // (c32, k64)
    __shared__ float sred[2][128];

    const int p0 = blockIdx.x * 128;
    const int b  = blockIdx.y;
    const int tid = threadIdx.x;
    const int lane = tid & 31, wid = tid >> 5;
    const int pg = wid & 3, kw = wid >> 2;
    const int pwb = pg * 32;

    const u16* XH = g_xfh + (size_t)b * CC * NP;
    const u16* XL = g_xfl + (size_t)b * CC * NP;
    const u16* MH = use_gm ? (g_mh + (size_t)b * CC * KK) : g_muh;
    const u16* ML = use_gm ? (g_ml + (size_t)b * CC * KK) : g_mul;

    float acc[2][4][4];
#pragma unroll
    for (int mf = 0; mf < 2; mf++)
#pragma unroll
        for (int nf = 0; nf < 4; nf++)
#pragma unroll
            for (int q = 0; q < 4; q++) acc[mf][nf][q] = 0.f;

    const u32 sxh = smem_u32(Xh), sxl = smem_u32(Xl);
    const u32 smh = smem_u32(Mh), sml = smem_u32(Ml);

    const int xr0 = tid >> 4,           xg0 = (tid & 15) * 8;
    const int xr1 = (tid + 256) >> 4,   xg1 = (tid & 15) * 8;
    const int mr  = tid >> 3,           mg  = (tid & 7) * 8;

    uint4 pxh[2], pxl[2], pmh, pml;
#define KZ_PREFETCH(c0)                                                        \
    do {                                                                       \
        pxh[0] = *(const uint4*)(XH + (size_t)((c0) + xr0) * NP + p0 + xg0);   \
        pxh[1] = *(const uint4*)(XH + (size_t)((c0) + xr1) * NP + p0 + xg1);   \
        pxl[0] = *(const uint4*)(XL + (size_t)((c0) + xr0) * NP + p0 + xg0);   \
        pxl[1] = *(const uint4*)(XL + (size_t)((c0) + xr1) * NP + p0 + xg1);   \
        pmh    = *(const uint4*)(MH + (size_t)((c0) + mr) * KK + mg);          \
        pml    = *(const uint4*)(ML + (size_t)((c0) + mr) * KK + mg);          \
    } while (0)

    KZ_PREFETCH(0);

    for (int c0 = 0; c0 < CC; c0 += 32) {
        __syncthreads();
        *(uint4*)&Xh[xr0 * 136 + xg0] = pxh[0];
        *(uint4*)&Xh[xr1 * 136 + xg1] = pxh[1];
        *(uint4*)&Xl[xr0 * 136 + xg0] = pxl[0];
        *(uint4*)&Xl[xr1 * 136 + xg1] = pxl[1];
        *(uint4*)&Mh[mr * 72 + mg] = pmh;
        *(uint4*)&Ml[mr * 72 + mg] = pml;
        __syncthreads();
        if (c0 + 32 < CC) KZ_PREFETCH(c0 + 32);

#pragma unroll
        for (int ks = 0; ks < 2; ks++) {
            u32 ah[2][4], al[2][4];
#pragma unroll
            for (int mf = 0; mf < 2; mf++) {
                u32 row = ks * 16 + (lane & 7) + ((lane >> 4) & 1) * 8;
                u32 col = pwb + mf * 16 + ((lane >> 3) & 1) * 8;
                u32 off = (row * 136 + col) << 1;
                ldsm4t(ah[mf], sxh + off);
                ldsm4t(al[mf], sxl + off);
            }
            u32 bh[2][4], bl[2][4];
            {
                u32 row = ks * 16 + (lane & 7) + ((lane >> 3) & 1) * 8;
                u32 col = kw * 32 + ((lane >> 4) & 1) * 8;
#pragma unroll
                for (int pr = 0; pr < 2; pr++) {
                    u32 off = (row * 72 + col + pr * 16) << 1;
                    ldsm4t(bh[pr], smh + off);
                    ldsm4t(bl[pr], sml + off);
                }
            }
#pragma unroll
            for (int mf = 0; mf < 2; mf++)
#pragma unroll
                for (int nf = 0; nf < 4; nf++) {
                    const u32* bhp = &bh[nf >> 1][(nf & 1) * 2];
                    const u32* blp = &bl[nf >> 1][(nf & 1) * 2];
                    mma_bf16(acc[mf][nf], ah[mf], bhp);
                    mma_bf16(acc[mf][nf], ah[mf], blp);
                    mma_bf16(acc[mf][nf], al[mf], bhp);
                }
        }
    }
#undef KZ_PREFETCH

    // ---- softmax over k=64 split across 2 k-warps ----
    const int gr = lane >> 2, tg = lane & 3;
    float pm[2][2];
#pragma unroll
    for (int mf = 0; mf < 2; mf++) {
        float m0 = -1e30f, m1 = -1e30f;
#pragma unroll
        for (int nf = 0; nf < 4; nf++) {
            m0 = fmaxf(m0, fmaxf(acc[mf][nf][0], acc[mf][nf][1]));
            m1 = fmaxf(m1, fmaxf(acc[mf][nf][2], acc[mf][nf][3]));
        }
#pragma unroll
        for (int s = 1; s < 4; s <<= 1) {
            m0 = fmaxf(m0, __shfl_xor_sync(0xffffffffu, m0, s));
            m1 = fmaxf(m1, __shfl_xor_sync(0xffffffffu, m1, s));
        }
        pm[mf][0] = m0; pm[mf][1] = m1;
    }
    if (tg == 0) {
#pragma unroll
        for (int mf = 0; mf < 2; mf++) {
            sred[kw][pwb + mf * 16 + gr]     = pm[mf][0];
            sred[kw][pwb + mf * 16 + gr + 8] = pm[mf][1];
        }
    }
    __syncthreads();
    float fm[2][2];
#pragma unroll
    for (int mf = 0; mf < 2; mf++) {
        fm[mf][0] = fmaxf(pm[mf][0], sred[kw ^ 1][pwb + mf * 16 + gr]);
        fm[mf][1] = fmaxf(pm[mf][1], sred[kw ^ 1][pwb + mf * 16 + gr + 8]);
    }
    __syncthreads();
    float ps[2][2];
#pragma unroll
    for (int mf = 0; mf < 2; mf++) {
        float s0 = 0.f, s1 = 0.f;
#pragma unroll
        for (int nf = 0; nf < 4; nf++) {
            acc[mf][nf][0] = expf(acc[mf][nf][0] - fm[mf][0]); s0 += acc[mf][nf][0];
            acc[mf][nf][1] = expf(acc[mf][nf][1] - fm[mf][0]); s0 += acc[mf][nf][1];
            acc[mf][nf][2] = expf(acc[mf][nf][2] - fm[mf][1]); s1 += acc[mf][nf][2];
            acc[mf][nf][3] = expf(acc[mf][nf][3] - fm[mf][1]); s1 += acc[mf][nf][3];
        }
#pragma unroll
        for (int s = 1; s < 4; s <<= 1) {
            s0 += __shfl_xor_sync(0xffffffffu, s0, s);
            s1 += __shfl_xor_sync(0xffffffffu, s1, s);
        }
        ps[mf][0] = s0; ps[mf][1] = s1;
    }
    if (tg == 0) {
#pragma unroll
        for (int mf = 0; mf < 2; mf++) {
            sred[kw][pwb + mf * 16 + gr]     = ps[mf][0];
            sred[kw][pwb + mf * 16 + gr + 8] = ps[mf][1];
        }
    }
    __syncthreads();
#pragma unroll
    for (int mf = 0; mf < 2; mf++) {
        float inv0 = 1.f / (ps[mf][0] + sred[kw ^ 1][pwb + mf * 16 + gr]);
        float inv1 = 1.f / (ps[mf][1] + sred[kw ^ 1][pwb + mf * 16 + gr + 8]);
        size_t prow_lo = (size_t)(b * NP + p0 + pwb + mf * 16 + gr) * KK;
        size_t prow_hi = prow_lo + (size_t)8 * KK;
#pragma unroll
        for (int nf = 0; nf < 4; nf++) {
            int kc = kw * 32 + nf * 8 + tg * 2;
            u32 h, l;
            split2(acc[mf][nf][0] * inv0, acc[mf][nf][1] * inv0, h, l);
            *(u32*)&g_zh[prow_lo + kc] = h;
            *(u32*)&g_zl[prow_lo + kc] = l;
            split2(acc[mf][nf][2] * inv1, acc[mf][nf][3] * inv1, h, l);
            *(u32*)&g_zh[prow_hi + kc] = h;
            *(u32*)&g_zl[prow_hi + kc] = l;
        }
    }
}

// ---------------- km v3: 4 c-warps x 2 k-warps, reg-prefetch ----------------
__global__ __launch_bounds__(256, 2)
void km_kernel()
{
    __shared__ __align__(16) u16 Ah[128 * 40], Al[128 * 40]; // (c128, p32)
    __shared__ __align__(16) u16 Zh[32 * 72],  Zl[32 * 72];  // (p32, k64)

    const int ct0 = blockIdx.x * 128;
    const int b   = blockIdx.y;
    const int s   = blockIdx.z;
    const int ps0 = s * (NP / NSPLIT);
    const int tid = threadIdx.x;
    const int lane = tid & 31, wid = tid >> 5;
    const int cw = wid & 3, kw = wid >> 2;

    const u16* XH = g_xfh + (size_t)b * CC * NP;
    const u16* XL = g_xfl + (size_t)b * CC * NP;
    const u16* ZH = g_zh + (size_t)b * NP * KK;
    const u16* ZL = g_zl + (size_t)b * NP * KK;

    float acc[2][4][4];
#pragma unroll
    for (int mf = 0; mf < 2; mf++)
#pragma unroll
        for (int nf = 0; nf < 4; nf++)
#pragma unroll
            for (int q = 0; q < 4; q++) acc[mf][nf][q] = 0.f;

    const u32 sah = smem_u32(Ah), sal = smem_u32(Al);
    const u32 szh = smem_u32(Zh), szl = smem_u32(Zl);

    const int ar0 = tid >> 2,         ag0 = (tid & 3) * 8;
    const int ar1 = (tid + 256) >> 2, ag1 = (tid & 3) * 8;
    const int zr  = tid >> 3,         zg  = (tid & 7) * 8;

    uint4 pah[2], pal[2], pzh, pzl;
#define KM_PREFETCH(pc0)                                                       \
    do {                                                                       \
        pah[0] = *(const uint4*)(XH + (size_t)(ct0 + ar0) * NP + (pc0) + ag0); \
        pah[1] = *(const uint4*)(XH + (size_t)(ct0 + ar1) * NP + (pc0) + ag1); \
        pal[0] = *(const uint4*)(XL + (size_t)(ct0 + ar0) * NP + (pc0) + ag0); \
        pal[1] = *(const uint4*)(XL + (size_t)(ct0 + ar1) * NP + (pc0) + ag1); \
        pzh    = *(const uint4*)(ZH + (size_t)((pc0) + zr) * KK + zg);         \
        pzl    = *(const uint4*)(ZL + (size_t)((pc0) + zr) * KK + zg);         \
    } while (0)

    KM_PREFETCH(ps0);

    for (int pc0 = ps0; pc0 < ps0 + NP / NSPLIT; pc0 += 32) {
        __syncthreads();
        *(uint4*)&Ah[ar0 * 40 + ag0] = pah[0];
        *(uint4*)&Ah[ar1 * 40 + ag1] = pah[1];
        *(uint4*)&Al[ar0 * 40 + ag0] = pal[0];
        *(uint4*)&Al[ar1 * 40 + ag1] = pal[1];
        *(uint4*)&Zh[zr * 72 + zg] = pzh;
        *(uint4*)&Zl[zr * 72 + zg] = pzl;
        __syncthreads();
        if (pc0 + 32 < ps0 + NP / NSPLIT) KM_PREFETCH(pc0 + 32);

#pragma unroll
        for (int ks = 0; ks < 2; ks++) {
            u32 ah[2][4], al[2][4];
#pragma unroll
            for (int mf = 0; mf < 2; mf++) {
                u32 off = (((cw * 32 + mf * 16 + (lane & 15)) * 40 +
                            ks * 16 + (lane >> 4) * 8)) << 1;
                ldsm4(ah[mf], sah + off);
                ldsm4(al[mf], sal + off);
            }
            u32 bh[2][4], bl[2][4];
            {
                u32 row = ks * 16 + (lane & 7) + ((lane >> 3) & 1) * 8;
                u32 col = kw * 32 + ((lane >> 4) & 1) * 8;
#pragma unroll
                for (int pr = 0; pr < 2; pr++) {
                    u32 off = (row * 72 + col + pr * 16) << 1;
                    ldsm4t(bh[pr], szh + off);
                    ldsm4t(bl[pr], szl + off);
                }
            }
#pragma unroll
            for (int mf = 0; mf < 2; mf++)
#pragma unroll
                for (int nf = 0; nf < 4; nf++) {
                    const u32* bhp = &bh[nf >> 1][(nf & 1) * 2];
                    const u32* blp = &bl[nf >> 1][(nf & 1) * 2];
                    mma_bf16(acc[mf][nf], ah[mf], bhp);
                    mma_bf16(acc[mf][nf], ah[mf], blp);
                    mma_bf16(acc[mf][nf], al[mf], bhp);
                }
        }
    }
#undef KM_PREFETCH

    const int gr = lane >> 2, tg = lane & 3;
    float* out = g_mpart + ((size_t)(s * BB + b) * CC + ct0 + cw * 32) * KK;
#pragma unroll
    for (int mf = 0; mf < 2; mf++)
#pragma unroll
        for (int nf = 0; nf < 4; nf++) {
            int kc = kw * 32 + nf * 8 + tg * 2;
            int r0 = mf * 16 + gr;
            *(float2*)&out[(size_t)r0 * KK + kc] =
                make_float2(acc[mf][nf][0], acc[mf][nf][1]);
            *(float2*)&out[(size_t)(r0 + 8) * KK + kc] =
                make_float2(acc[mf][nf][2], acc[mf][nf][3]);
        }
}

// ---------------- fused norm v2: grid (4, BB), 64 blocks --------------------
__global__ __launch_bounds__(1024)
void knorm_fused()
{
    const int b  = blockIdx.y;
    const int k0 = blockIdx.x * 16;
    const int tid = threadIdx.x;
    const int kl = tid & 15;
    const int cg = tid >> 4;            // 0..63, each owns 8 c-rows

    __shared__ float red[64][17];

    const size_t base = (size_t)b * CC * KK;
    const int k = k0 + kl;
    float v[8];
    float ss = 0.f;
#pragma unroll
    for (int i = 0; i < 8; i++) {
        size_t off = base + (size_t)(cg * 8 + i) * KK + k;
        float t = 0.f;
#pragma unroll
        for (int s = 0; s < NSPLIT; s++)
            t += g_mpart[(size_t)s * (BB * CC * KK) + off];
        v[i] = t;
        ss += t * t;
    }
    red[cg][kl] = ss;
    __syncthreads();
#pragma unroll
    for (int s = 32; s > 0; s >>= 1) {
        if (cg < s) red[cg][kl] += red[cg + s][kl];
        __syncthreads();
    }
    const float inv = 1.f / (EPSF + sqrtf(red[0][kl]));
    u16* mh = g_mh + base;
    u16* ml = g_ml + base;
#pragma unroll
    for (int i = 0; i < 8; i++) {
        float sv = v[i] * inv;
        __nv_bfloat16 h = __float2bfloat16_rn(sv);
        __nv_bfloat16 l = __float2bfloat16_rn(sv - __bfloat162float(h));
        size_t off = (size_t)(cg * 8 + i) * KK + k;
        mh[off] = __bfloat16_as_ushort(h);
        ml[off] = __bfloat16_as_ushort(l);
    }
}

// ---------------- krec: rec = relu(m @ z^T) -> fp16 single (c,p) -------------
__global__ __launch_bounds__(256, 2)
void krec_kernel()
{
    __shared__ __align__(16) u16 Ah[128 * 40], Al[128 * 40]; // (c128, k32)
    __shared__ __align__(16) u16 Bh[128 * 40], Bl[128 * 40]; // (p128, k32)

    const int p0  = blockIdx.x * 128;
    const int ct0 = blockIdx.y * 128;
    const int b   = blockIdx.z;
    const int tid = threadIdx.x;
    const int lane = tid & 31, wid = tid >> 5;
    const int wm = wid & 1, wn = wid >> 1;
    const int cb = wm * 64, pb = wn * 32;

    const u16* MH = g_mh + (size_t)b * CC * KK;
    const u16* ML = g_ml + (size_t)b * CC * KK;
    const u16* ZH = g_zh + (size_t)b * NP * KK;
    const u16* ZL = g_zl + (size_t)b * NP * KK;

    float acc[4][4][4];
#pragma unroll
    for (int mf = 0; mf < 4; mf++)
#pragma unroll
        for (int nf = 0; nf < 4; nf++)
#pragma unroll
            for (int q = 0; q < 4; q++) acc[mf][nf][q] = 0.f;

    const u32 sah = smem_u32(Ah), sal = smem_u32(Al);
    const u32 sbh = smem_u32(Bh), sbl = smem_u32(Bl);

    for (int kc0 = 0; kc0 < KK; kc0 += 32) {
#pragma unroll
        for (int it = 0; it < 2; it++) {
            int lin = tid + it * 256;
            int r = lin >> 2, g = lin & 3;
            *(uint4*)&Ah[r * 40 + g * 8] =
                *(const uint4*)(MH + (size_t)(ct0 + r) * KK + kc0 + g * 8);
            *(uint4*)&Al[r * 40 + g * 8] =
                *(const uint4*)(ML + (size_t)(ct0 + r) * KK + kc0 + g * 8);
        }
#pragma unroll
        for (int it = 0; it < 2; it++) {
            int lin = tid + it * 256;
            int r = lin >> 2, g = lin & 3;
            *(uint4*)&Bh[r * 40 + g * 8] =
                *(const uint4*)(ZH + (size_t)(p0 + r) * KK + kc0 + g * 8);
            *(uint4*)&Bl[r * 40 + g * 8] =
                *(const uint4*)(ZL + (size_t)(p0 + r) * KK + kc0 + g * 8);
        }
        __syncthreads();
#pragma unroll
        for (int ks = 0; ks < 2; ks++) {
            u32 ah[4][4], al[4][4];
            u32 a_off = (((cb + (lane & 15)) * 40 + ks * 16 + (lane >> 4) * 8)) << 1;
#pragma unroll
            for (int mf = 0; mf < 4; mf++) {
                ldsm4(ah[mf], sah + a_off + mf * (16 * 40 * 2));
                ldsm4(al[mf], sal + a_off + mf * (16 * 40 * 2));
            }
            u32 bh[2][4], bl[2][4];
            u32 brow = pb + ((lane >> 4) & 1) * 8 + (lane & 7);
            u32 bcol = ks * 16 + ((lane >> 3) & 1) * 8;
#pragma unroll
            for (int pr = 0; pr < 2; pr++) {
                u32 boff = ((brow + pr * 16) * 40 + bcol) << 1;
                ldsm4(bh[pr], sbh + boff);
                ldsm4(bl[pr], sbl + boff);
            }
#pragma unroll
            for (int mf = 0; mf < 4; mf++)
#pragma unroll
                for (int nf = 0; nf < 4; nf++) {
                    const u32* bhp = &bh[nf >> 1][(nf & 1) * 2];
                    const u32* blp = &bl[nf >> 1][(nf & 1) * 2];
                    mma_bf16(acc[mf][nf], ah[mf], bhp);
                    mma_bf16(acc[mf][nf], ah[mf], blp);
                    mma_bf16(acc[mf][nf], al[mf], bhp);
                }
        }
        __syncthreads();
    }

    const int g = lane >> 2, tg = lane & 3;
    u16* rh = g_rech + (size_t)b * CC * NP;
#pragma unroll
    for (int mf = 0; mf < 4; mf++) {
        int c_lo = ct0 + cb + mf * 16 + g;
        int c_hi = c_lo + 8;
#pragma unroll
        for (int nf = 0; nf < 4; nf++) {
            int pc = p0 + pb + nf * 8 + tg * 2;
            *(u32*)&rh[(size_t)c_lo * NP + pc] =
                pack2h(fmaxf(acc[mf][nf][0], 0.f), fmaxf(acc[mf][nf][1], 0.f));
            *(u32*)&rh[(size_t)c_hi * NP + pc] =
                pack2h(fmaxf(acc[mf][nf][2], 0.f), fmaxf(acc[mf][nf][3], 0.f));
        }
    }
}

// ---------------- launch ----------------------------------------------------
extern "C" void kernel_launch(void* const* d_in, const int* in_sizes, int n_in,
                              void* d_out, int out_size)
{
    (void)in_sizes; (void)n_in; (void)out_size;
    const float* x     = (const float*)d_in[0];
    const float* w1    = (const float*)d_in[1];
    const float* b1    = (const float*)d_in[2];
    const float* mu    = (const float*)d_in[3];
    const float* w2    = (const float*)d_in[4];
    const float* gamma = (const float*)d_in[5];
    const float* beta  = (const float*)d_in[6];
    const float* mean  = (const float*)d_in[7];
    const float* var   = (const float*)d_in[8];
    float* out = (float*)d_out;

    cudaFuncSetAttribute(hconv<0>, cudaFuncAttributeMaxDynamicSharedMemorySize,
                         HCONV_SMEM);
    cudaFuncSetAttribute(hconv<1>, cudaFuncAttributeMaxDynamicSharedMemorySize,
                         HCONV_SMEM);

    kcvt_all<<<XBLOCKS + WBLOCKS + MUBLOCKS, 256>>>(x, w1, w2, mu);

    hconv<0><<<dim3(NP / 128, CC / 128, BB), 128, HCONV_SMEM>>>(
        nullptr, b1, nullptr, nullptr, nullptr);

    for (int st = 0; st < 3; st++) {
        kz_kernel<<<dim3(NP / 128, BB), 256>>>(st > 0 ? 1 : 0);
        km_kernel<<<dim3(CC / 128, BB, NSPLIT), 256>>>();
        knorm_fused<<<dim3(4, BB), 1024>>>();
    }

    krec_kernel<<<dim3(NP / 128, CC / 128, BB), 256>>>();

    hconv<1><<<dim3(NP / 128, CC / 128, BB), 128, HCONV_SMEM>>>(
        out, gamma, beta, mean, var);
}